// round 6
// baseline (speedup 1.0000x reference)
#include <cuda_runtime.h>
#include <cstddef>

// Problem constants
#define B_   2
#define S_   2048
#define D_   1024
#define H_   16
#define HD_  64
#define M_   (B_*S_)   // 4096 rows for all projection GEMMs

// Scratch (no allocation allowed -> device globals). 16 MB each.
__device__ float g_q[B_*S_*D_];
__device__ float g_k[B_*S_*D_];
__device__ float g_v[B_*S_*D_];
__device__ float g_ctx[B_*S_*D_];

// ---------------------------------------------------------------------------
// GEMM:  Y[M,N] = X[M,K] @ W[N,K]^T + bias[N]      (M=4096, N=K=1024)
// 128x128 block tile, BK=8, 256 threads, 8x8 per-thread register tile.
// ---------------------------------------------------------------------------
__global__ void __launch_bounds__(256, 2)
gemm_nt_bias(const float* __restrict__ X, const float* __restrict__ W,
             const float* __restrict__ bias, float* __restrict__ Y) {
    __shared__ float As[8][128];
    __shared__ float Bs[8][128];

    const int tid = threadIdx.x;
    const int tx  = tid & 15;      // 0..15 -> N direction
    const int ty  = tid >> 4;      // 0..15 -> M direction
    const int bm  = blockIdx.y * 128;
    const int bn  = blockIdx.x * 128;

    // loader mapping: each thread fetches one float4 of A and one of B per k-step
    const int lr = tid >> 1;          // 0..127 (tile row)
    const int lk = (tid & 1) * 4;     // 0 or 4 (k offset)

    const float* Xp = X + (size_t)(bm + lr) * D_ + lk;
    const float* Wp = W + (size_t)(bn + lr) * D_ + lk;

    float acc[8][8];
#pragma unroll
    for (int i = 0; i < 8; i++)
#pragma unroll
        for (int j = 0; j < 8; j++) acc[i][j] = 0.f;

    for (int k0 = 0; k0 < D_; k0 += 8) {
        float4 av = *(const float4*)(Xp + k0);
        float4 bv = *(const float4*)(Wp + k0);
        As[lk+0][lr] = av.x; As[lk+1][lr] = av.y;
        As[lk+2][lr] = av.z; As[lk+3][lr] = av.w;
        Bs[lk+0][lr] = bv.x; Bs[lk+1][lr] = bv.y;
        Bs[lk+2][lr] = bv.z; Bs[lk+3][lr] = bv.w;
        __syncthreads();

#pragma unroll
        for (int k = 0; k < 8; k++) {
            float a[8], b[8];
            *(float4*)&a[0] = *(const float4*)&As[k][ty*8];
            *(float4*)&a[4] = *(const float4*)&As[k][ty*8 + 4];
            *(float4*)&b[0] = *(const float4*)&Bs[k][tx*8];
            *(float4*)&b[4] = *(const float4*)&Bs[k][tx*8 + 4];
#pragma unroll
            for (int i = 0; i < 8; i++)
#pragma unroll
                for (int j = 0; j < 8; j++)
                    acc[i][j] = fmaf(a[i], b[j], acc[i][j]);
        }
        __syncthreads();
    }

    float bj[8];
#pragma unroll
    for (int j = 0; j < 8; j++) bj[j] = bias[bn + tx*8 + j];

#pragma unroll
    for (int i = 0; i < 8; i++) {
        float* yp = Y + (size_t)(bm + ty*8 + i) * D_ + bn + tx*8;
        float4 v0 = make_float4(acc[i][0]+bj[0], acc[i][1]+bj[1],
                                acc[i][2]+bj[2], acc[i][3]+bj[3]);
        float4 v1 = make_float4(acc[i][4]+bj[4], acc[i][5]+bj[5],
                                acc[i][6]+bj[6], acc[i][7]+bj[7]);
        *(float4*)(yp)     = v0;
        *(float4*)(yp + 4) = v1;
    }
}

// ---------------------------------------------------------------------------
// Fused attention (secure_softmax needs no max): one streaming pass.
//   ctx_row = (sum_k sig(s_k) * v_k) / (sum_k sig(s_k) + 1e-8)
// Tile: 64 q-rows x 64 keys, HD=64. 256 threads (16x16), 4x4 per thread.
// grid = (S/64, B*H)
// ---------------------------------------------------------------------------
#define LD_ 68   // smem row stride (floats): 16B-aligned, conflict-free pattern

__global__ void __launch_bounds__(256, 2)
attn_kernel(const float* __restrict__ Q, const float* __restrict__ K,
            const float* __restrict__ V, const float* __restrict__ mask,
            float* __restrict__ CTX) {
    extern __shared__ float sm_[];
    float* Qs = sm_;             // 64*68
    float* Ks = sm_ + 4352;      // 64*68
    float* Vs = sm_ + 8704;      // 64*68
    float* Ps = sm_ + 13056;     // 64*68
    float* Ms = sm_ + 17408;     // 64
    float* Ds = sm_ + 17472;     // 64*17

    const int tid = threadIdx.x;
    const int tx  = tid & 15;
    const int ty  = tid >> 4;
    const int bh  = blockIdx.y;          // 0..31
    const int b   = bh >> 4;
    const int h   = bh & 15;
    const int q0  = blockIdx.x * 64;

    const float* qb = Q + (size_t)b * S_ * D_ + h * HD_;
    const float* kb = K + (size_t)b * S_ * D_ + h * HD_;
    const float* vb = V + (size_t)b * S_ * D_ + h * HD_;

    // Load Q tile [64 x 64] (rows of 64 floats = 16 float4, fully coalesced)
#pragma unroll
    for (int r = 0; r < 4; r++) {
        int idx = tid + r * 256;
        int row = idx >> 4;
        int c4  = (idx & 15) * 4;
        *(float4*)&Qs[row*LD_ + c4] =
            *(const float4*)(qb + (size_t)(q0 + row) * D_ + c4);
    }

    float acc[4][4];
    float dpart[4] = {0.f, 0.f, 0.f, 0.f};
#pragma unroll
    for (int i = 0; i < 4; i++)
#pragma unroll
        for (int j = 0; j < 4; j++) acc[i][j] = 0.f;

    for (int kt = 0; kt < 32; kt++) {
        __syncthreads();   // previous Ps/Vs reads done before overwrite
        const int kr0 = kt * 64;
#pragma unroll
        for (int r = 0; r < 4; r++) {
            int idx = tid + r * 256;
            int row = idx >> 4;
            int c4  = (idx & 15) * 4;
            size_t go = (size_t)(kr0 + row) * D_ + c4;
            *(float4*)&Ks[row*LD_ + c4] = *(const float4*)(kb + go);
            *(float4*)&Vs[row*LD_ + c4] = *(const float4*)(vb + go);
        }
        if (tid < 64) Ms[tid] = mask[b * S_ + kr0 + tid];
        __syncthreads();

        // Stage A: S = Q K^T  (thread owns q rows ty+16i, key cols tx+16j)
        float s[4][4];
#pragma unroll
        for (int i = 0; i < 4; i++)
#pragma unroll
            for (int j = 0; j < 4; j++) s[i][j] = 0.f;

#pragma unroll 4
        for (int d = 0; d < HD_; d += 4) {
            float4 qv[4], kv[4];
#pragma unroll
            for (int i = 0; i < 4; i++)
                qv[i] = *(const float4*)&Qs[(ty + 16*i)*LD_ + d];
#pragma unroll
            for (int j = 0; j < 4; j++)
                kv[j] = *(const float4*)&Ks[(tx + 16*j)*LD_ + d];
#pragma unroll
            for (int i = 0; i < 4; i++)
#pragma unroll
                for (int j = 0; j < 4; j++) {
                    s[i][j] = fmaf(qv[i].x, kv[j].x, s[i][j]);
                    s[i][j] = fmaf(qv[i].y, kv[j].y, s[i][j]);
                    s[i][j] = fmaf(qv[i].z, kv[j].z, s[i][j]);
                    s[i][j] = fmaf(qv[i].w, kv[j].w, s[i][j]);
                }
        }

        // secure_softmax numerator (mask -> clip -> poly -> clip), row-sum tally
#pragma unroll
        for (int j = 0; j < 4; j++) {
            float mterm = (1.0f - Ms[tx + 16*j]) * -10000.0f;
#pragma unroll
            for (int i = 0; i < 4; i++) {
                float c = s[i][j] * 0.125f + mterm;   // / sqrt(64)
                c = fminf(3.0f, fmaxf(-3.0f, c));
                float sig = 0.5f + 0.25f*c - 0.01f*c*c*c;
                sig = fminf(0.99f, fmaxf(0.01f, sig));
                Ps[(ty + 16*i)*LD_ + tx + 16*j] = sig;
                dpart[i] += sig;
            }
        }
        __syncthreads();

        // Stage B: acc += P @ V  (thread owns hd cols tx+16j)
#pragma unroll 4
        for (int k4 = 0; k4 < 64; k4 += 4) {
            float4 p[4];
#pragma unroll
            for (int i = 0; i < 4; i++)
                p[i] = *(const float4*)&Ps[(ty + 16*i)*LD_ + k4];
#pragma unroll
            for (int kk = 0; kk < 4; kk++) {
                float vj[4];
#pragma unroll
                for (int j = 0; j < 4; j++)
                    vj[j] = Vs[(k4 + kk)*LD_ + tx + 16*j];
#pragma unroll
                for (int i = 0; i < 4; i++) {
                    float pv = ((const float*)&p[i])[kk];
#pragma unroll
                    for (int j = 0; j < 4; j++)
                        acc[i][j] = fmaf(pv, vj[j], acc[i][j]);
                }
            }
        }
    }

    // Reduce row denominators across the 16 tx threads
    __syncthreads();
#pragma unroll
    for (int i = 0; i < 4; i++) Ds[(ty + 16*i)*17 + tx] = dpart[i];
    __syncthreads();

#pragma unroll
    for (int i = 0; i < 4; i++) {
        float dsum = 0.f;
#pragma unroll
        for (int t = 0; t < 16; t++) dsum += Ds[(ty + 16*i)*17 + t];
        float inv = 1.0f / (dsum + 1e-8f);
        int row = q0 + ty + 16*i;
        float* cp = CTX + ((size_t)b * S_ + row) * D_ + h * HD_;
#pragma unroll
        for (int j = 0; j < 4; j++)
            cp[tx + 16*j] = acc[i][j] * inv;
    }
}

// ---------------------------------------------------------------------------
// Host launcher. Inputs (metadata order):
//  0 hidden_states [B,S,D] f32    1 attention_mask [B,S] f32
//  2 Wq [D,D]  3 bq [D]  4 Wk  5 bk  6 Wv  7 bv  8 Wo  9 bo
// Output: [B,S,D] f32
// ---------------------------------------------------------------------------
extern "C" void kernel_launch(void* const* d_in, const int* in_sizes, int n_in,
                              void* d_out, int out_size) {
    const float* hs = (const float*)d_in[0];
    const float* am = (const float*)d_in[1];
    const float* Wq = (const float*)d_in[2];
    const float* bq = (const float*)d_in[3];
    const float* Wk = (const float*)d_in[4];
    const float* bk = (const float*)d_in[5];
    const float* Wv = (const float*)d_in[6];
    const float* bv = (const float*)d_in[7];
    const float* Wo = (const float*)d_in[8];
    const float* bo = (const float*)d_in[9];
    float* out = (float*)d_out;

    float *q, *k, *v, *ctx;
    cudaGetSymbolAddress((void**)&q,   g_q);
    cudaGetSymbolAddress((void**)&k,   g_k);
    cudaGetSymbolAddress((void**)&v,   g_v);
    cudaGetSymbolAddress((void**)&ctx, g_ctx);

    const int ATTN_SMEM = (17472 + 64*17) * (int)sizeof(float);  // 74240 B
    static bool attr_set = false;
    if (!attr_set) {
        cudaFuncSetAttribute(attn_kernel,
                             cudaFuncAttributeMaxDynamicSharedMemorySize,
                             ATTN_SMEM);
        attr_set = true;
    }

    dim3 gthr(256);
    dim3 ggrid(D_/128, M_/128);   // (8, 32)

    gemm_nt_bias<<<ggrid, gthr>>>(hs, Wq, bq, q);
    gemm_nt_bias<<<ggrid, gthr>>>(hs, Wk, bk, k);
    gemm_nt_bias<<<ggrid, gthr>>>(hs, Wv, bv, v);

    dim3 agrid(S_/64, B_*H_);     // (32, 32)
    attn_kernel<<<agrid, 256, ATTN_SMEM>>>(q, k, v, am, ctx);

    gemm_nt_bias<<<ggrid, gthr>>>(ctx, Wo, bo, out);
}

// round 9
// speedup vs baseline: 1.4705x; 1.4705x over previous
#include <cuda_runtime.h>
#include <cuda_bf16.h>
#include <cstdint>
#include <cstddef>

// Problem constants
#define B_   2
#define S_   2048
#define D_   1024
#define H_   16
#define HD_  64
#define M_   (B_*S_)   // 4096 rows for all projection GEMMs

// Scratch (no allocation allowed -> device globals)
__device__ float g_q[M_*D_];
__device__ float g_k[M_*D_];
__device__ float g_v[M_*D_];
__device__ float g_ctx[M_*D_];
// bf16 split planes
__device__ __nv_bfloat16 g_x_hi[M_*D_];
__device__ __nv_bfloat16 g_x_lo[M_*D_];
__device__ __nv_bfloat16 g_c_hi[M_*D_];
__device__ __nv_bfloat16 g_c_lo[M_*D_];
__device__ __nv_bfloat16 g_w_hi[4*D_*D_];
__device__ __nv_bfloat16 g_w_lo[4*D_*D_];

// ===========================================================================
// Helpers (all baseline PTX for compute_103: ldmatrix, mma.sync, cp.async)
// ===========================================================================
__device__ __forceinline__ uint32_t smem_u32(const void* p) {
    uint32_t r;
    asm("{ .reg .u64 t; cvta.to.shared.u64 t, %1; cvt.u32.u64 %0, t; }"
        : "=r"(r) : "l"(p));
    return r;
}

__device__ __forceinline__ void cpa16(uint32_t dst, const void* src) {
    asm volatile("cp.async.cg.shared.global [%0], [%1], 16;"
                 :: "r"(dst), "l"(__cvta_generic_to_global(src)) : "memory");
}

#define CP_COMMIT() asm volatile("cp.async.commit_group;" ::: "memory")

#define LDSM4(d0,d1,d2,d3,a) \
    asm volatile("ldmatrix.sync.aligned.m8n8.x4.shared.b16 {%0,%1,%2,%3}, [%4];" \
        : "=r"(d0),"=r"(d1),"=r"(d2),"=r"(d3) : "r"(a))

#define MMA16816(c,a,b0,b1) \
    asm volatile("mma.sync.aligned.m16n8k16.row.col.f32.bf16.bf16.f32 " \
        "{%0,%1,%2,%3},{%4,%5,%6,%7},{%8,%9},{%0,%1,%2,%3};" \
        : "+f"((c)[0]),"+f"((c)[1]),"+f"((c)[2]),"+f"((c)[3]) \
        : "r"((a)[0]),"r"((a)[1]),"r"((a)[2]),"r"((a)[3]),"r"(b0),"r"(b1))

// ===========================================================================
// split_bf16: f32 -> (hi, lo) bf16 planes.  lo = bf16(x - f32(hi))
// ===========================================================================
__global__ void split_bf16(const float4* __restrict__ x,
                           __nv_bfloat162* __restrict__ hi,
                           __nv_bfloat162* __restrict__ lo, int n4) {
    int i = blockIdx.x * blockDim.x + threadIdx.x;
    if (i >= n4) return;
    float4 v = x[i];
    __nv_bfloat16 h0 = __float2bfloat16_rn(v.x);
    __nv_bfloat16 h1 = __float2bfloat16_rn(v.y);
    __nv_bfloat16 h2 = __float2bfloat16_rn(v.z);
    __nv_bfloat16 h3 = __float2bfloat16_rn(v.w);
    __nv_bfloat162 ph0; ph0.x = h0; ph0.y = h1;
    __nv_bfloat162 ph1; ph1.x = h2; ph1.y = h3;
    hi[2*i]   = ph0;
    hi[2*i+1] = ph1;
    __nv_bfloat162 pl0, pl1;
    pl0.x = __float2bfloat16_rn(v.x - __bfloat162float(h0));
    pl0.y = __float2bfloat16_rn(v.y - __bfloat162float(h1));
    pl1.x = __float2bfloat16_rn(v.z - __bfloat162float(h2));
    pl1.y = __float2bfloat16_rn(v.w - __bfloat162float(h3));
    lo[2*i]   = pl0;
    lo[2*i+1] = pl1;
}

// ===========================================================================
// gemm_bf16x3:  Y[M,N] = (Ah+Al)[M,K] @ (Bh+Bl)[N,K]^T + bias  (split-3)
// CTA tile 128x128, BK=32 bf16, 256 thr = 8 warps (2m x 4n), warp tile 64x32.
// Double-buffered cp.async; XOR-swizzled smem; ldmatrix.x4; m16n8k16 HMMA.
// SMEM: 2 stages x 4 planes x 8KB = 64 KB.
// ===========================================================================
#define GSTAGE 32768
#define GSMEM  (2*GSTAGE)

__global__ void __launch_bounds__(256)
gemm_bf16x3(const __nv_bfloat16* __restrict__ Ah, const __nv_bfloat16* __restrict__ Al,
            const __nv_bfloat16* __restrict__ Bh, const __nv_bfloat16* __restrict__ Bl,
            const float* __restrict__ bias, float* __restrict__ Y) {
    extern __shared__ char sm[];
    const uint32_t sb = smem_u32(sm);
    const int tid  = threadIdx.x;
    const int lane = tid & 31;
    const int wid  = tid >> 5;
    const int wm   = (wid & 1) * 64;
    const int wn   = (wid >> 1) * 32;
    const int bm   = blockIdx.y * 128;
    const int bn   = blockIdx.x * 128;

    float acc[4][4][4];
#pragma unroll
    for (int i = 0; i < 4; i++)
#pragma unroll
        for (int j = 0; j < 4; j++)
#pragma unroll
            for (int q = 0; q < 4; q++) acc[i][j][q] = 0.f;

    // prefetch one BK=32 chunk (all 4 planes) into stage stg
    auto prefetch = [&](int c, int stg) {
        uint32_t sbase = sb + stg * GSTAGE;
#pragma unroll
        for (int q = 0; q < 2; q++) {
            int u   = tid + q * 256;          // 0..511
            int row = u >> 2;                 // 0..127
            int seg = u & 3;                  // 16B segment within 64B row
            uint32_t d = row * 64 + ((seg * 16) ^ (((row >> 1) & 3) << 4));
            size_t oA = (size_t)(bm + row) * D_ + c * 32 + seg * 8;
            size_t oB = (size_t)(bn + row) * D_ + c * 32 + seg * 8;
            cpa16(sbase +         d, Ah + oA);
            cpa16(sbase +  8192 + d, Al + oA);
            cpa16(sbase + 16384 + d, Bh + oB);
            cpa16(sbase + 24576 + d, Bl + oB);
        }
        CP_COMMIT();
    };

    prefetch(0, 0);

    for (int c = 0; c < 32; c++) {
        if (c < 31) {
            prefetch(c + 1, (c + 1) & 1);
            asm volatile("cp.async.wait_group 1;" ::: "memory");
        } else {
            asm volatile("cp.async.wait_group 0;" ::: "memory");
        }
        __syncthreads();

        const uint32_t st = sb + (c & 1) * GSTAGE;
        const int r    = lane & 15;
        const int hseg = lane >> 4;

#pragma unroll
        for (int ks = 0; ks < 2; ks++) {
            const uint32_t kb = ks * 32 + hseg * 16;
            uint32_t ah[4][4], al[4][4], bh[4][2], bl[4][2];
#pragma unroll
            for (int i = 0; i < 4; i++) {
                int row = wm + i * 16 + r;
                uint32_t ad = st + row * 64 + (kb ^ (((row >> 1) & 3) << 4));
                LDSM4(ah[i][0], ah[i][1], ah[i][2], ah[i][3], ad);
                LDSM4(al[i][0], al[i][1], al[i][2], al[i][3], ad + 8192);
            }
#pragma unroll
            for (int jp = 0; jp < 2; jp++) {
                int row = wn + jp * 16 + r;
                uint32_t bd = st + 16384 + row * 64 + (kb ^ (((row >> 1) & 3) << 4));
                // x4 destinations = {frag j: b0, frag j+1: b0, frag j: b1, frag j+1: b1}
                LDSM4(bh[2*jp][0], bh[2*jp+1][0], bh[2*jp][1], bh[2*jp+1][1], bd);
                LDSM4(bl[2*jp][0], bl[2*jp+1][0], bl[2*jp][1], bl[2*jp+1][1], bd + 8192);
            }
#pragma unroll
            for (int i = 0; i < 4; i++)
#pragma unroll
                for (int j = 0; j < 4; j++) {
                    MMA16816(acc[i][j], ah[i], bh[j][0], bh[j][1]);
                    MMA16816(acc[i][j], ah[i], bl[j][0], bl[j][1]);
                    MMA16816(acc[i][j], al[i], bh[j][0], bh[j][1]);
                }
        }
        __syncthreads();
    }

    // Epilogue: per PTX m16n8k16 D layout: c0,c1 -> (mrow, ncol), c2,c3 -> (mrow+8, ncol)
    const int mrow = lane >> 2;
    const int ncol = (lane & 3) * 2;
#pragma unroll
    for (int i = 0; i < 4; i++) {
#pragma unroll
        for (int j = 0; j < 4; j++) {
            int m = bm + wm + i * 16 + mrow;
            int n = bn + wn + j * 8 + ncol;
            float2 bv = *(const float2*)(bias + n);
            float2 o;
            o.x = acc[i][j][0] + bv.x;
            o.y = acc[i][j][1] + bv.y;
            *(float2*)(Y + (size_t)m * D_ + n) = o;
            o.x = acc[i][j][2] + bv.x;
            o.y = acc[i][j][3] + bv.y;
            *(float2*)(Y + (size_t)(m + 8) * D_ + n) = o;
        }
    }
}

// ---------------------------------------------------------------------------
// Fused attention (secure_softmax needs no max): one streaming pass.
// [unchanged from R5 — proven correct, 920us]
// ---------------------------------------------------------------------------
#define LD_ 68

__global__ void __launch_bounds__(256, 2)
attn_kernel(const float* __restrict__ Q, const float* __restrict__ K,
            const float* __restrict__ V, const float* __restrict__ mask,
            float* __restrict__ CTX) {
    extern __shared__ float sm_[];
    float* Qs = sm_;             // 64*68
    float* Ks = sm_ + 4352;      // 64*68
    float* Vs = sm_ + 8704;      // 64*68
    float* Ps = sm_ + 13056;     // 64*68
    float* Ms = sm_ + 17408;     // 64
    float* Ds = sm_ + 17472;     // 64*17

    const int tid = threadIdx.x;
    const int tx  = tid & 15;
    const int ty  = tid >> 4;
    const int bh  = blockIdx.y;
    const int b   = bh >> 4;
    const int h   = bh & 15;
    const int q0  = blockIdx.x * 64;

    const float* qb = Q + (size_t)b * S_ * D_ + h * HD_;
    const float* kb = K + (size_t)b * S_ * D_ + h * HD_;
    const float* vb = V + (size_t)b * S_ * D_ + h * HD_;

#pragma unroll
    for (int r = 0; r < 4; r++) {
        int idx = tid + r * 256;
        int row = idx >> 4;
        int c4  = (idx & 15) * 4;
        *(float4*)&Qs[row*LD_ + c4] =
            *(const float4*)(qb + (size_t)(q0 + row) * D_ + c4);
    }

    float acc[4][4];
    float dpart[4] = {0.f, 0.f, 0.f, 0.f};
#pragma unroll
    for (int i = 0; i < 4; i++)
#pragma unroll
        for (int j = 0; j < 4; j++) acc[i][j] = 0.f;

    for (int kt = 0; kt < 32; kt++) {
        __syncthreads();
        const int kr0 = kt * 64;
#pragma unroll
        for (int r = 0; r < 4; r++) {
            int idx = tid + r * 256;
            int row = idx >> 4;
            int c4  = (idx & 15) * 4;
            size_t go = (size_t)(kr0 + row) * D_ + c4;
            *(float4*)&Ks[row*LD_ + c4] = *(const float4*)(kb + go);
            *(float4*)&Vs[row*LD_ + c4] = *(const float4*)(vb + go);
        }
        if (tid < 64) Ms[tid] = mask[b * S_ + kr0 + tid];
        __syncthreads();

        float s[4][4];
#pragma unroll
        for (int i = 0; i < 4; i++)
#pragma unroll
            for (int j = 0; j < 4; j++) s[i][j] = 0.f;

#pragma unroll 4
        for (int d = 0; d < HD_; d += 4) {
            float4 qv[4], kv[4];
#pragma unroll
            for (int i = 0; i < 4; i++)
                qv[i] = *(const float4*)&Qs[(ty + 16*i)*LD_ + d];
#pragma unroll
            for (int j = 0; j < 4; j++)
                kv[j] = *(const float4*)&Ks[(tx + 16*j)*LD_ + d];
#pragma unroll
            for (int i = 0; i < 4; i++)
#pragma unroll
                for (int j = 0; j < 4; j++) {
                    s[i][j] = fmaf(qv[i].x, kv[j].x, s[i][j]);
                    s[i][j] = fmaf(qv[i].y, kv[j].y, s[i][j]);
                    s[i][j] = fmaf(qv[i].z, kv[j].z, s[i][j]);
                    s[i][j] = fmaf(qv[i].w, kv[j].w, s[i][j]);
                }
        }

#pragma unroll
        for (int j = 0; j < 4; j++) {
            float mterm = (1.0f - Ms[tx + 16*j]) * -10000.0f;
#pragma unroll
            for (int i = 0; i < 4; i++) {
                float c = s[i][j] * 0.125f + mterm;
                c = fminf(3.0f, fmaxf(-3.0f, c));
                float sig = 0.5f + 0.25f*c - 0.01f*c*c*c;
                sig = fminf(0.99f, fmaxf(0.01f, sig));
                Ps[(ty + 16*i)*LD_ + tx + 16*j] = sig;
                dpart[i] += sig;
            }
        }
        __syncthreads();

#pragma unroll 4
        for (int k4 = 0; k4 < 64; k4 += 4) {
            float4 p[4];
#pragma unroll
            for (int i = 0; i < 4; i++)
                p[i] = *(const float4*)&Ps[(ty + 16*i)*LD_ + k4];
#pragma unroll
            for (int kk = 0; kk < 4; kk++) {
                float vj[4];
#pragma unroll
                for (int j = 0; j < 4; j++)
                    vj[j] = Vs[(k4 + kk)*LD_ + tx + 16*j];
#pragma unroll
                for (int i = 0; i < 4; i++) {
                    float pv = ((const float*)&p[i])[kk];
#pragma unroll
                    for (int j = 0; j < 4; j++)
                        acc[i][j] = fmaf(pv, vj[j], acc[i][j]);
                }
            }
        }
    }

    __syncthreads();
#pragma unroll
    for (int i = 0; i < 4; i++) Ds[(ty + 16*i)*17 + tx] = dpart[i];
    __syncthreads();

#pragma unroll
    for (int i = 0; i < 4; i++) {
        float dsum = 0.f;
#pragma unroll
        for (int t = 0; t < 16; t++) dsum += Ds[(ty + 16*i)*17 + t];
        float inv = 1.0f / (dsum + 1e-8f);
        int row = q0 + ty + 16*i;
        float* cp = CTX + ((size_t)b * S_ + row) * D_ + h * HD_;
#pragma unroll
        for (int j = 0; j < 4; j++)
            cp[tx + 16*j] = acc[i][j] * inv;
    }
}

// ---------------------------------------------------------------------------
// Host launcher. Inputs (metadata order):
//  0 hidden_states [B,S,D] f32    1 attention_mask [B,S] f32
//  2 Wq [D,D]  3 bq [D]  4 Wk  5 bk  6 Wv  7 bv  8 Wo  9 bo
// ---------------------------------------------------------------------------
extern "C" void kernel_launch(void* const* d_in, const int* in_sizes, int n_in,
                              void* d_out, int out_size) {
    const float* hs = (const float*)d_in[0];
    const float* am = (const float*)d_in[1];
    const float* Wq = (const float*)d_in[2];
    const float* bq = (const float*)d_in[3];
    const float* Wk = (const float*)d_in[4];
    const float* bk = (const float*)d_in[5];
    const float* Wv = (const float*)d_in[6];
    const float* bv = (const float*)d_in[7];
    const float* Wo = (const float*)d_in[8];
    const float* bo = (const float*)d_in[9];
    float* out = (float*)d_out;

    float *q, *k, *v, *ctx;
    __nv_bfloat16 *xh, *xl, *ch, *cl, *wh, *wl;
    cudaGetSymbolAddress((void**)&q,   g_q);
    cudaGetSymbolAddress((void**)&k,   g_k);
    cudaGetSymbolAddress((void**)&v,   g_v);
    cudaGetSymbolAddress((void**)&ctx, g_ctx);
    cudaGetSymbolAddress((void**)&xh,  g_x_hi);
    cudaGetSymbolAddress((void**)&xl,  g_x_lo);
    cudaGetSymbolAddress((void**)&ch,  g_c_hi);
    cudaGetSymbolAddress((void**)&cl,  g_c_lo);
    cudaGetSymbolAddress((void**)&wh,  g_w_hi);
    cudaGetSymbolAddress((void**)&wl,  g_w_lo);

    const int ATTN_SMEM = (17472 + 64*17) * (int)sizeof(float);  // 74240 B
    static bool attr_set = false;
    if (!attr_set) {
        cudaFuncSetAttribute(attn_kernel,
                             cudaFuncAttributeMaxDynamicSharedMemorySize,
                             ATTN_SMEM);
        cudaFuncSetAttribute(gemm_bf16x3,
                             cudaFuncAttributeMaxDynamicSharedMemorySize,
                             GSMEM);
        attr_set = true;
    }

    const int D2 = D_ * D_;
    const int n4_x = M_ * D_ / 4;    // 1048576
    const int n4_w = D2 / 4;         // 262144

    // Split inputs into bf16 hi/lo planes
    split_bf16<<<n4_x/256, 256>>>((const float4*)hs,
                                  (__nv_bfloat162*)xh, (__nv_bfloat162*)xl, n4_x);
    split_bf16<<<n4_w/256, 256>>>((const float4*)Wq,
                                  (__nv_bfloat162*)(wh),        (__nv_bfloat162*)(wl),        n4_w);
    split_bf16<<<n4_w/256, 256>>>((const float4*)Wk,
                                  (__nv_bfloat162*)(wh + D2),   (__nv_bfloat162*)(wl + D2),   n4_w);
    split_bf16<<<n4_w/256, 256>>>((const float4*)Wv,
                                  (__nv_bfloat162*)(wh + 2*D2), (__nv_bfloat162*)(wl + 2*D2), n4_w);
    split_bf16<<<n4_w/256, 256>>>((const float4*)Wo,
                                  (__nv_bfloat162*)(wh + 3*D2), (__nv_bfloat162*)(wl + 3*D2), n4_w);

    dim3 ggrid(D_/128, M_/128);   // (8, 32)
    gemm_bf16x3<<<ggrid, 256, GSMEM>>>(xh, xl, wh,        wl,        bq, q);
    gemm_bf16x3<<<ggrid, 256, GSMEM>>>(xh, xl, wh + D2,   wl + D2,   bk, k);
    gemm_bf16x3<<<ggrid, 256, GSMEM>>>(xh, xl, wh + 2*D2, wl + 2*D2, bv, v);

    dim3 agrid(S_/64, B_*H_);     // (32, 32)
    attn_kernel<<<agrid, 256, ATTN_SMEM>>>(q, k, v, am, ctx);

    split_bf16<<<n4_x/256, 256>>>((const float4*)ctx,
                                  (__nv_bfloat162*)ch, (__nv_bfloat162*)cl, n4_x);
    gemm_bf16x3<<<ggrid, 256, GSMEM>>>(ch, cl, wh + 3*D2, wl + 3*D2, bo, out);
}

// round 10
// speedup vs baseline: 2.6767x; 1.8202x over previous
#include <cuda_runtime.h>
#include <cuda_bf16.h>
#include <cstdint>
#include <cstddef>

// Problem constants
#define B_   2
#define S_   2048
#define D_   1024
#define H_   16
#define HD_  64
#define M_   (B_*S_)

// Scratch (no allocation allowed -> device globals)
__device__ __nv_bfloat16 g_x_hi[M_*D_];
__device__ __nv_bfloat16 g_x_lo[M_*D_];
__device__ __nv_bfloat16 g_w_hi[4*D_*D_];
__device__ __nv_bfloat16 g_w_lo[4*D_*D_];
__device__ __nv_bfloat16 g_qh[M_*D_];
__device__ __nv_bfloat16 g_ql[M_*D_];
__device__ __nv_bfloat16 g_kh[M_*D_];
__device__ __nv_bfloat16 g_kl[M_*D_];
__device__ float         g_v [M_*D_];
__device__ __nv_bfloat16 g_vth[M_*D_];   // V^T per (b,h): [b,h,hd,S]
__device__ __nv_bfloat16 g_vtl[M_*D_];
__device__ __nv_bfloat16 g_ch[M_*D_];
__device__ __nv_bfloat16 g_cl[M_*D_];

// ===========================================================================
// Helpers (baseline PTX for compute_103: ldmatrix, mma.sync, cp.async)
// ===========================================================================
__device__ __forceinline__ uint32_t smem_u32(const void* p) {
    uint32_t r;
    asm("{ .reg .u64 t; cvta.to.shared.u64 t, %1; cvt.u32.u64 %0, t; }"
        : "=r"(r) : "l"(p));
    return r;
}

__device__ __forceinline__ void cpa16(uint32_t dst, const void* src) {
    asm volatile("cp.async.cg.shared.global [%0], [%1], 16;"
                 :: "r"(dst), "l"(__cvta_generic_to_global(src)) : "memory");
}

#define CP_COMMIT() asm volatile("cp.async.commit_group;" ::: "memory")

#define LDSM4(d0,d1,d2,d3,a) \
    asm volatile("ldmatrix.sync.aligned.m8n8.x4.shared.b16 {%0,%1,%2,%3}, [%4];" \
        : "=r"(d0),"=r"(d1),"=r"(d2),"=r"(d3) : "r"(a))

#define MMA16816(c,a,b0,b1) \
    asm volatile("mma.sync.aligned.m16n8k16.row.col.f32.bf16.bf16.f32 " \
        "{%0,%1,%2,%3},{%4,%5,%6,%7},{%8,%9},{%0,%1,%2,%3};" \
        : "+f"((c)[0]),"+f"((c)[1]),"+f"((c)[2]),"+f"((c)[3]) \
        : "r"((a)[0]),"r"((a)[1]),"r"((a)[2]),"r"((a)[3]),"r"(b0),"r"(b1))

// pack two f32 -> bf16x2 reg (lo in low 16 bits)
__device__ __forceinline__ uint32_t packbf(float lo, float hi) {
    uint32_t r;
    asm("cvt.rn.bf16x2.f32 %0, %1, %2;" : "=r"(r) : "f"(hi), "f"(lo));
    return r;
}

// split f32 -> (hi bf16, residual f32)
__device__ __forceinline__ void splitf(float x, __nv_bfloat16& h, float& r) {
    h = __float2bfloat16_rn(x);
    r = x - __bfloat162float(h);
}

// ===========================================================================
// split_bf16: f32 -> (hi, lo) bf16 planes
// ===========================================================================
__global__ void split_bf16(const float4* __restrict__ x,
                           __nv_bfloat162* __restrict__ hi,
                           __nv_bfloat162* __restrict__ lo, int n4) {
    int i = blockIdx.x * blockDim.x + threadIdx.x;
    if (i >= n4) return;
    float4 v = x[i];
    __nv_bfloat16 h0, h1, h2, h3;
    float r0, r1, r2, r3;
    splitf(v.x, h0, r0); splitf(v.y, h1, r1);
    splitf(v.z, h2, r2); splitf(v.w, h3, r3);
    __nv_bfloat162 p0; p0.x = h0; p0.y = h1;
    __nv_bfloat162 p1; p1.x = h2; p1.y = h3;
    hi[2*i] = p0; hi[2*i+1] = p1;
    __nv_bfloat162 q0, q1;
    q0.x = __float2bfloat16_rn(r0); q0.y = __float2bfloat16_rn(r1);
    q1.x = __float2bfloat16_rn(r2); q1.y = __float2bfloat16_rn(r3);
    lo[2*i] = q0; lo[2*i+1] = q1;
}

// ===========================================================================
// vtrans: g_v f32 [b,s,h*64+d] -> vth/vtl bf16 [b,h,d,S] (per-head transpose)
// ===========================================================================
__global__ void vtrans(const float* __restrict__ v,
                       __nv_bfloat16* __restrict__ vth,
                       __nv_bfloat16* __restrict__ vtl) {
    __shared__ float tile[64][65];
    const int tid = threadIdx.x;
    const int s0  = blockIdx.x * 64;
    const int bh  = blockIdx.y;
    const int b   = bh >> 4, h = bh & 15;
    const float* vb = v + (size_t)b * S_ * D_ + h * HD_;
#pragma unroll
    for (int u = tid; u < 4096; u += 256) {
        int row = u >> 6, col = u & 63;
        tile[col][row] = vb[(size_t)(s0 + row) * D_ + col];
    }
    __syncthreads();
    __nv_bfloat16* oh = vth + (size_t)bh * HD_ * S_ + s0;
    __nv_bfloat16* ol = vtl + (size_t)bh * HD_ * S_ + s0;
#pragma unroll
    for (int u = tid; u < 4096; u += 256) {
        int d = u >> 6, sc = u & 63;
        float x = tile[d][sc];
        __nv_bfloat16 hh; float rr;
        splitf(x, hh, rr);
        oh[(size_t)d * S_ + sc] = hh;
        ol[(size_t)d * S_ + sc] = __float2bfloat16_rn(rr);
    }
}

// ===========================================================================
// gemm_bf16x3:  Y = (Ah+Al)[M,K] @ (Bh+Bl)[N,K]^T + bias   (split-3 HMMA)
// Output: f32 Y, or bf16 hi/lo planes (Yh/Yl) when Yh != nullptr.
// [mainloop identical to R8 — validated]
// ===========================================================================
#define GSTAGE 32768
#define GSMEM  (2*GSTAGE)

__global__ void __launch_bounds__(256)
gemm_bf16x3(const __nv_bfloat16* __restrict__ Ah, const __nv_bfloat16* __restrict__ Al,
            const __nv_bfloat16* __restrict__ Bh, const __nv_bfloat16* __restrict__ Bl,
            const float* __restrict__ bias, float* __restrict__ Y,
            __nv_bfloat16* __restrict__ Yh, __nv_bfloat16* __restrict__ Yl) {
    extern __shared__ char sm[];
    const uint32_t sb = smem_u32(sm);
    const int tid  = threadIdx.x;
    const int lane = tid & 31;
    const int wid  = tid >> 5;
    const int wm   = (wid & 1) * 64;
    const int wn   = (wid >> 1) * 32;
    const int bm   = blockIdx.y * 128;
    const int bn   = blockIdx.x * 128;

    float acc[4][4][4];
#pragma unroll
    for (int i = 0; i < 4; i++)
#pragma unroll
        for (int j = 0; j < 4; j++)
#pragma unroll
            for (int q = 0; q < 4; q++) acc[i][j][q] = 0.f;

    auto prefetch = [&](int c, int stg) {
        uint32_t sbase = sb + stg * GSTAGE;
#pragma unroll
        for (int q = 0; q < 2; q++) {
            int u   = tid + q * 256;
            int row = u >> 2;
            int seg = u & 3;
            uint32_t d = row * 64 + ((seg * 16) ^ (((row >> 1) & 3) << 4));
            size_t oA = (size_t)(bm + row) * D_ + c * 32 + seg * 8;
            size_t oB = (size_t)(bn + row) * D_ + c * 32 + seg * 8;
            cpa16(sbase +         d, Ah + oA);
            cpa16(sbase +  8192 + d, Al + oA);
            cpa16(sbase + 16384 + d, Bh + oB);
            cpa16(sbase + 24576 + d, Bl + oB);
        }
        CP_COMMIT();
    };

    prefetch(0, 0);

    for (int c = 0; c < 32; c++) {
        if (c < 31) {
            prefetch(c + 1, (c + 1) & 1);
            asm volatile("cp.async.wait_group 1;" ::: "memory");
        } else {
            asm volatile("cp.async.wait_group 0;" ::: "memory");
        }
        __syncthreads();

        const uint32_t st = sb + (c & 1) * GSTAGE;
        const int r    = lane & 15;
        const int hseg = lane >> 4;

#pragma unroll
        for (int ks = 0; ks < 2; ks++) {
            const uint32_t kb = ks * 32 + hseg * 16;
            uint32_t ah[4][4], al[4][4], bh[4][2], bl[4][2];
#pragma unroll
            for (int i = 0; i < 4; i++) {
                int row = wm + i * 16 + r;
                uint32_t ad = st + row * 64 + (kb ^ (((row >> 1) & 3) << 4));
                LDSM4(ah[i][0], ah[i][1], ah[i][2], ah[i][3], ad);
                LDSM4(al[i][0], al[i][1], al[i][2], al[i][3], ad + 8192);
            }
#pragma unroll
            for (int jp = 0; jp < 2; jp++) {
                int row = wn + jp * 16 + r;
                uint32_t bd = st + 16384 + row * 64 + (kb ^ (((row >> 1) & 3) << 4));
                LDSM4(bh[2*jp][0], bh[2*jp+1][0], bh[2*jp][1], bh[2*jp+1][1], bd);
                LDSM4(bl[2*jp][0], bl[2*jp+1][0], bl[2*jp][1], bl[2*jp+1][1], bd + 8192);
            }
#pragma unroll
            for (int i = 0; i < 4; i++)
#pragma unroll
                for (int j = 0; j < 4; j++) {
                    MMA16816(acc[i][j], ah[i], bh[j][0], bh[j][1]);
                    MMA16816(acc[i][j], ah[i], bl[j][0], bl[j][1]);
                    MMA16816(acc[i][j], al[i], bh[j][0], bh[j][1]);
                }
        }
        __syncthreads();
    }

    const int mrow = lane >> 2;
    const int ncol = (lane & 3) * 2;
#pragma unroll
    for (int i = 0; i < 4; i++) {
#pragma unroll
        for (int j = 0; j < 4; j++) {
            int m = bm + wm + i * 16 + mrow;
            int n = bn + wn + j * 8 + ncol;
            float2 bv = *(const float2*)(bias + n);
            float y0 = acc[i][j][0] + bv.x;
            float y1 = acc[i][j][1] + bv.y;
            float y2 = acc[i][j][2] + bv.x;
            float y3 = acc[i][j][3] + bv.y;
            if (Yh) {
                __nv_bfloat16 h0,h1,h2,h3; float r0,r1,r2,r3;
                splitf(y0,h0,r0); splitf(y1,h1,r1);
                splitf(y2,h2,r2); splitf(y3,h3,r3);
                __nv_bfloat162 p; p.x=h0; p.y=h1;
                *(__nv_bfloat162*)(Yh + (size_t)m*D_ + n) = p;
                p.x=h2; p.y=h3;
                *(__nv_bfloat162*)(Yh + (size_t)(m+8)*D_ + n) = p;
                *(uint32_t*)(Yl + (size_t)m*D_ + n)     = packbf(r0, r1);
                *(uint32_t*)(Yl + (size_t)(m+8)*D_ + n) = packbf(r2, r3);
            } else {
                float2 o;
                o.x = y0; o.y = y1;
                *(float2*)(Y + (size_t)m * D_ + n) = o;
                o.x = y2; o.y = y3;
                *(float2*)(Y + (size_t)(m + 8) * D_ + n) = o;
            }
        }
    }
}

// ===========================================================================
// attn_mma: FlashAttention-style secure-softmax attention, split-3 HMMA.
// CTA: 128 q-rows (8 warps x 16), loop 32 key-tiles of 64. HD=64.
//   stage A: S = Q K^T   (qh*kh + qh*kl + ql*kh)
//   softmax poly on fragments -> P split into bf16 hi/lo A-fragments
//   stage B: ctx += P V   (ph*vh + ph*vl + pl*vh), V pre-transposed
// SMEM: Q hi/lo 32KB + 2 stages x (K hi/lo + VT hi/lo + mask) = 98816 B.
// Swizzle for 128B rows: seg' = seg ^ (row&7), 16B segs.
// ===========================================================================
#define ASTG  33024
#define AQ    32768
#define ASMEM (AQ + 2*ASTG)   // 98816

__global__ void __launch_bounds__(256)
attn_mma(const __nv_bfloat16* __restrict__ qh_, const __nv_bfloat16* __restrict__ ql_,
         const __nv_bfloat16* __restrict__ kh_, const __nv_bfloat16* __restrict__ kl_,
         const __nv_bfloat16* __restrict__ vth_, const __nv_bfloat16* __restrict__ vtl_,
         const float* __restrict__ mask,
         __nv_bfloat16* __restrict__ ch_, __nv_bfloat16* __restrict__ cl_) {
    extern __shared__ char sm[];
    const uint32_t sb = smem_u32(sm);
    const int tid  = threadIdx.x;
    const int lane = tid & 31;
    const int wid  = tid >> 5;
    const int t    = lane & 3;
    const int bh   = blockIdx.y;
    const int b    = bh >> 4, h = bh & 15;
    const int q0   = blockIdx.x * 128;

    const __nv_bfloat16* qhb = qh_ + ((size_t)b * S_ + q0) * D_ + h * HD_;
    const __nv_bfloat16* qlb = ql_ + ((size_t)b * S_ + q0) * D_ + h * HD_;
    const __nv_bfloat16* khb = kh_ + (size_t)b * S_ * D_ + h * HD_;
    const __nv_bfloat16* klb = kl_ + (size_t)b * S_ * D_ + h * HD_;
    const __nv_bfloat16* vhb = vth_ + (size_t)bh * HD_ * S_;
    const __nv_bfloat16* vlb = vtl_ + (size_t)bh * HD_ * S_;

    // Load Q tile (128 rows x 64 bf16, hi+lo), swizzled
#pragma unroll
    for (int u = tid; u < 1024; u += 256) {
        int row = u >> 3, seg = u & 7;
        uint32_t d = row * 128 + (((seg ^ (row & 7))) << 4);
        cpa16(sb +         d, qhb + (size_t)row * D_ + seg * 8);
        cpa16(sb + 16384 + d, qlb + (size_t)row * D_ + seg * 8);
    }

    auto prefetch = [&](int kt, int stg) {
        uint32_t sbase = sb + AQ + stg * ASTG;
        int kr0 = kt * 64;
#pragma unroll
        for (int q = 0; q < 2; q++) {
            int u = tid + q * 256;            // 0..511
            int row = u >> 3, seg = u & 7;
            uint32_t d = row * 128 + ((seg ^ (row & 7)) << 4);
            size_t ko = (size_t)(kr0 + row) * D_ + seg * 8;
            cpa16(sbase +         d, khb + ko);
            cpa16(sbase +  8192 + d, klb + ko);
            size_t vo = (size_t)row * S_ + kr0 + seg * 8;
            cpa16(sbase + 16384 + d, vhb + vo);
            cpa16(sbase + 24576 + d, vlb + vo);
        }
        if (tid < 16)
            cpa16(sbase + 32768 + tid * 16, mask + (size_t)b * S_ + kr0 + tid * 4);
    };

    prefetch(0, 0);
    CP_COMMIT();     // group: Q + stage0

    float ctx[8][4];
#pragma unroll
    for (int j = 0; j < 8; j++)
#pragma unroll
        for (int q = 0; q < 4; q++) ctx[j][q] = 0.f;
    float dsum0 = 0.f, dsum1 = 0.f;

    const int r    = lane & 15;
    const int hseg = lane >> 4;
    const int rowA = wid * 16 + r;

    for (int kt = 0; kt < 32; kt++) {
        if (kt < 31) {
            prefetch(kt + 1, (kt + 1) & 1);
            CP_COMMIT();
            asm volatile("cp.async.wait_group 1;" ::: "memory");
        } else {
            asm volatile("cp.async.wait_group 0;" ::: "memory");
        }
        __syncthreads();

        const uint32_t st = sb + AQ + (kt & 1) * ASTG;
        const float* Ms = (const float*)(sm + AQ + (kt & 1) * ASTG + 32768);

        // ---- Stage A: S = Q K^T (split-3) ----
        float s[8][4];
#pragma unroll
        for (int j = 0; j < 8; j++)
#pragma unroll
            for (int q = 0; q < 4; q++) s[j][q] = 0.f;

#pragma unroll
        for (int ks = 0; ks < 4; ks++) {
            const int segA = ks * 2 + hseg;
            uint32_t qa = sb + rowA * 128 + ((segA ^ (rowA & 7)) << 4);
            uint32_t qA[4], qL[4];
            LDSM4(qA[0], qA[1], qA[2], qA[3], qa);
            LDSM4(qL[0], qL[1], qL[2], qL[3], qa + 16384);
            uint32_t kh[8][2], kl[8][2];
#pragma unroll
            for (int jp = 0; jp < 4; jp++) {
                int row = jp * 16 + r;
                uint32_t kd = st + row * 128 + ((segA ^ (row & 7)) << 4);
                LDSM4(kh[2*jp][0], kh[2*jp+1][0], kh[2*jp][1], kh[2*jp+1][1], kd);
                LDSM4(kl[2*jp][0], kl[2*jp+1][0], kl[2*jp][1], kl[2*jp+1][1], kd + 8192);
            }
#pragma unroll
            for (int j = 0; j < 8; j++) {
                MMA16816(s[j], qA, kh[j][0], kh[j][1]);
                MMA16816(s[j], qA, kl[j][0], kl[j][1]);
                MMA16816(s[j], qL, kh[j][0], kh[j][1]);
            }
        }

        // ---- softmax poly + build P fragments (hi/lo) ----
        uint32_t pah[4][4], pal[4][4];
#pragma unroll
        for (int j = 0; j < 8; j++) {
            float2 mv = *(const float2*)(Ms + j * 8 + t * 2);
            float mt0 = (1.0f - mv.x) * -10000.0f;
            float mt1 = (1.0f - mv.y) * -10000.0f;
            float e[4];
#pragma unroll
            for (int q = 0; q < 4; q++) {
                float c = s[j][q] * 0.125f + ((q & 1) ? mt1 : mt0);
                c = fminf(3.0f, fmaxf(-3.0f, c));
                float sg = 0.5f + c * (0.25f - 0.01f * c * c);
                e[q] = fminf(0.99f, fmaxf(0.01f, sg));
            }
            dsum0 += e[0] + e[1];
            dsum1 += e[2] + e[3];
            __nv_bfloat16 h0,h1,h2,h3; float r0,r1,r2,r3;
            splitf(e[0],h0,r0); splitf(e[1],h1,r1);
            splitf(e[2],h2,r2); splitf(e[3],h3,r3);
            __nv_bfloat162 p01; p01.x = h0; p01.y = h1;
            __nv_bfloat162 p23; p23.x = h2; p23.y = h3;
            int kk = j >> 1, half = (j & 1) * 2;
            pah[kk][half + 0] = *(uint32_t*)&p01;   // (g,   2t..)
            pah[kk][half + 1] = *(uint32_t*)&p23;   // (g+8, 2t..)
            pal[kk][half + 0] = packbf(r0, r1);
            pal[kk][half + 1] = packbf(r2, r3);
        }
        // re-order halves: a-frag order is {j0 rows, j0 rows+8, j1 rows, j1 rows+8}
        // pah[kk] currently = {j=2kk:(g),(g+8), j=2kk+1:(g),(g+8)} == {a0,a1,a2,a3} ✓

        // ---- Stage B: ctx += P V (split-3) ----
#pragma unroll
        for (int kk = 0; kk < 4; kk++) {
            const int segB = kk * 2 + hseg;
            uint32_t vh[8][2], vl[8][2];
#pragma unroll
            for (int jp = 0; jp < 4; jp++) {
                int row = jp * 16 + r;
                uint32_t vd = st + 16384 + row * 128 + ((segB ^ (row & 7)) << 4);
                LDSM4(vh[2*jp][0], vh[2*jp+1][0], vh[2*jp][1], vh[2*jp+1][1], vd);
                LDSM4(vl[2*jp][0], vl[2*jp+1][0], vl[2*jp][1], vl[2*jp+1][1], vd + 8192);
            }
#pragma unroll
            for (int j = 0; j < 8; j++) {
                MMA16816(ctx[j], pah[kk], vh[j][0], vh[j][1]);
                MMA16816(ctx[j], pah[kk], vl[j][0], vl[j][1]);
                MMA16816(ctx[j], pal[kk], vh[j][0], vh[j][1]);
            }
        }
        __syncthreads();
    }

    // ---- reduce denominators across lane quads (same row) ----
    dsum0 += __shfl_xor_sync(0xffffffffu, dsum0, 1);
    dsum0 += __shfl_xor_sync(0xffffffffu, dsum0, 2);
    dsum1 += __shfl_xor_sync(0xffffffffu, dsum1, 1);
    dsum1 += __shfl_xor_sync(0xffffffffu, dsum1, 2);
    float inv0 = 1.0f / (dsum0 + 1e-8f);
    float inv1 = 1.0f / (dsum1 + 1e-8f);

    const int g = lane >> 2;
    const int row0 = q0 + wid * 16 + g;
    const int row1 = row0 + 8;
#pragma unroll
    for (int j = 0; j < 8; j++) {
        int col = h * HD_ + j * 8 + t * 2;
        float y0 = ctx[j][0] * inv0, y1 = ctx[j][1] * inv0;
        float y2 = ctx[j][2] * inv1, y3 = ctx[j][3] * inv1;
        __nv_bfloat16 h0,h1,h2,h3; float r0,r1,r2,r3;
        splitf(y0,h0,r0); splitf(y1,h1,r1);
        splitf(y2,h2,r2); splitf(y3,h3,r3);
        size_t i0 = ((size_t)b * S_ + row0) * D_ + col;
        size_t i1 = ((size_t)b * S_ + row1) * D_ + col;
        __nv_bfloat162 p; p.x=h0; p.y=h1;
        *(__nv_bfloat162*)(ch_ + i0) = p;
        p.x=h2; p.y=h3;
        *(__nv_bfloat162*)(ch_ + i1) = p;
        *(uint32_t*)(cl_ + i0) = packbf(r0, r1);
        *(uint32_t*)(cl_ + i1) = packbf(r2, r3);
    }
}

// ---------------------------------------------------------------------------
// Host launcher.
// ---------------------------------------------------------------------------
extern "C" void kernel_launch(void* const* d_in, const int* in_sizes, int n_in,
                              void* d_out, int out_size) {
    const float* hs = (const float*)d_in[0];
    const float* am = (const float*)d_in[1];
    const float* Wq = (const float*)d_in[2];
    const float* bq = (const float*)d_in[3];
    const float* Wk = (const float*)d_in[4];
    const float* bk = (const float*)d_in[5];
    const float* Wv = (const float*)d_in[6];
    const float* bv = (const float*)d_in[7];
    const float* Wo = (const float*)d_in[8];
    const float* bo = (const float*)d_in[9];
    float* out = (float*)d_out;

    __nv_bfloat16 *xh, *xl, *wh, *wl, *qh, *ql, *kh, *kl, *vth, *vtl, *ch, *cl;
    float* v;
    cudaGetSymbolAddress((void**)&xh,  g_x_hi);
    cudaGetSymbolAddress((void**)&xl,  g_x_lo);
    cudaGetSymbolAddress((void**)&wh,  g_w_hi);
    cudaGetSymbolAddress((void**)&wl,  g_w_lo);
    cudaGetSymbolAddress((void**)&qh,  g_qh);
    cudaGetSymbolAddress((void**)&ql,  g_ql);
    cudaGetSymbolAddress((void**)&kh,  g_kh);
    cudaGetSymbolAddress((void**)&kl,  g_kl);
    cudaGetSymbolAddress((void**)&v,   g_v);
    cudaGetSymbolAddress((void**)&vth, g_vth);
    cudaGetSymbolAddress((void**)&vtl, g_vtl);
    cudaGetSymbolAddress((void**)&ch,  g_ch);
    cudaGetSymbolAddress((void**)&cl,  g_cl);

    static bool attr_set = false;
    if (!attr_set) {
        cudaFuncSetAttribute(gemm_bf16x3,
                             cudaFuncAttributeMaxDynamicSharedMemorySize, GSMEM);
        cudaFuncSetAttribute(attn_mma,
                             cudaFuncAttributeMaxDynamicSharedMemorySize, ASMEM);
        attr_set = true;
    }

    const int D2 = D_ * D_;
    const int n4_x = M_ * D_ / 4;
    const int n4_w = D2 / 4;

    split_bf16<<<n4_x/256, 256>>>((const float4*)hs,
                                  (__nv_bfloat162*)xh, (__nv_bfloat162*)xl, n4_x);
    split_bf16<<<n4_w/256, 256>>>((const float4*)Wq,
                                  (__nv_bfloat162*)(wh),        (__nv_bfloat162*)(wl),        n4_w);
    split_bf16<<<n4_w/256, 256>>>((const float4*)Wk,
                                  (__nv_bfloat162*)(wh + D2),   (__nv_bfloat162*)(wl + D2),   n4_w);
    split_bf16<<<n4_w/256, 256>>>((const float4*)Wv,
                                  (__nv_bfloat162*)(wh + 2*D2), (__nv_bfloat162*)(wl + 2*D2), n4_w);
    split_bf16<<<n4_w/256, 256>>>((const float4*)Wo,
                                  (__nv_bfloat162*)(wh + 3*D2), (__nv_bfloat162*)(wl + 3*D2), n4_w);

    dim3 ggrid(D_/128, M_/128);   // (8, 32)
    gemm_bf16x3<<<ggrid, 256, GSMEM>>>(xh, xl, wh,        wl,        bq, nullptr, qh, ql);
    gemm_bf16x3<<<ggrid, 256, GSMEM>>>(xh, xl, wh + D2,   wl + D2,   bk, nullptr, kh, kl);
    gemm_bf16x3<<<ggrid, 256, GSMEM>>>(xh, xl, wh + 2*D2, wl + 2*D2, bv, v, nullptr, nullptr);

    vtrans<<<dim3(S_/64, B_*H_), 256>>>(v, vth, vtl);

    dim3 agrid(S_/128, B_*H_);    // (16, 32)
    attn_mma<<<agrid, 256, ASMEM>>>(qh, ql, kh, kl, vth, vtl, am, ch, cl);

    gemm_bf16x3<<<ggrid, 256, GSMEM>>>(ch, cl, wh + 3*D2, wl + 3*D2, bo, out, nullptr, nullptr);
}

// round 12
// speedup vs baseline: 3.6536x; 1.3650x over previous
#include <cuda_runtime.h>
#include <cuda_bf16.h>
#include <cuda_fp16.h>
#include <cstdint>
#include <cstddef>

// Problem constants
#define B_   2
#define S_   2048
#define D_   1024
#define H_   16
#define HD_  64
#define M_   (B_*S_)

// Scratch (no allocation allowed -> device globals)
__device__ __nv_bfloat16 g_x_hi[M_*D_];
__device__ __nv_bfloat16 g_x_lo[M_*D_];
__device__ __nv_bfloat16 g_w_hi[4*D_*D_];
__device__ __nv_bfloat16 g_w_lo[4*D_*D_];
__device__ __half        g_qf[M_*D_];
__device__ __half        g_kf[M_*D_];
__device__ float         g_v [M_*D_];
__device__ __half        g_vtf[M_*D_];   // V^T per (b,h): [b,h,hd,S]
__device__ __nv_bfloat16 g_ch[M_*D_];
__device__ __nv_bfloat16 g_cl[M_*D_];

// ===========================================================================
// Helpers (baseline PTX for compute_103: ldmatrix, mma.sync, cp.async)
// ===========================================================================
__device__ __forceinline__ uint32_t smem_u32(const void* p) {
    uint32_t r;
    asm("{ .reg .u64 t; cvta.to.shared.u64 t, %1; cvt.u32.u64 %0, t; }"
        : "=r"(r) : "l"(p));
    return r;
}

__device__ __forceinline__ void cpa16(uint32_t dst, const void* src) {
    asm volatile("cp.async.cg.shared.global [%0], [%1], 16;"
                 :: "r"(dst), "l"(__cvta_generic_to_global(src)) : "memory");
}

#define CP_COMMIT() asm volatile("cp.async.commit_group;" ::: "memory")

#define LDSM4(d0,d1,d2,d3,a) \
    asm volatile("ldmatrix.sync.aligned.m8n8.x4.shared.b16 {%0,%1,%2,%3}, [%4];" \
        : "=r"(d0),"=r"(d1),"=r"(d2),"=r"(d3) : "r"(a))

#define MMA16816(c,a,b0,b1) \
    asm volatile("mma.sync.aligned.m16n8k16.row.col.f32.bf16.bf16.f32 " \
        "{%0,%1,%2,%3},{%4,%5,%6,%7},{%8,%9},{%0,%1,%2,%3};" \
        : "+f"((c)[0]),"+f"((c)[1]),"+f"((c)[2]),"+f"((c)[3]) \
        : "r"((a)[0]),"r"((a)[1]),"r"((a)[2]),"r"((a)[3]),"r"(b0),"r"(b1))

#define MMAH16816(c,a,b0,b1) \
    asm volatile("mma.sync.aligned.m16n8k16.row.col.f32.f16.f16.f32 " \
        "{%0,%1,%2,%3},{%4,%5,%6,%7},{%8,%9},{%0,%1,%2,%3};" \
        : "+f"((c)[0]),"+f"((c)[1]),"+f"((c)[2]),"+f"((c)[3]) \
        : "r"((a)[0]),"r"((a)[1]),"r"((a)[2]),"r"((a)[3]),"r"(b0),"r"(b1))

// pack two f32 -> bf16x2 reg (first arg in low 16 bits)
__device__ __forceinline__ uint32_t packbf(float lo, float hi) {
    uint32_t r;
    asm("cvt.rn.bf16x2.f32 %0, %1, %2;" : "=r"(r) : "f"(hi), "f"(lo));
    return r;
}
// pack two f32 -> f16x2 reg (first arg in low 16 bits)
__device__ __forceinline__ uint32_t packh(float lo, float hi) {
    uint32_t r;
    asm("cvt.rn.f16x2.f32 %0, %1, %2;" : "=r"(r) : "f"(hi), "f"(lo));
    return r;
}

// split f32 -> (hi bf16, residual f32)
__device__ __forceinline__ void splitf(float x, __nv_bfloat16& h, float& r) {
    h = __float2bfloat16_rn(x);
    r = x - __bfloat162float(h);
}

// ===========================================================================
// split_bf16: f32 -> (hi, lo) bf16 planes
// ===========================================================================
__global__ void split_bf16(const float4* __restrict__ x,
                           __nv_bfloat162* __restrict__ hi,
                           __nv_bfloat162* __restrict__ lo, int n4) {
    int i = blockIdx.x * blockDim.x + threadIdx.x;
    if (i >= n4) return;
    float4 v = x[i];
    __nv_bfloat16 h0, h1, h2, h3;
    float r0, r1, r2, r3;
    splitf(v.x, h0, r0); splitf(v.y, h1, r1);
    splitf(v.z, h2, r2); splitf(v.w, h3, r3);
    __nv_bfloat162 p0; p0.x = h0; p0.y = h1;
    __nv_bfloat162 p1; p1.x = h2; p1.y = h3;
    hi[2*i] = p0; hi[2*i+1] = p1;
    __nv_bfloat162 q0, q1;
    q0.x = __float2bfloat16_rn(r0); q0.y = __float2bfloat16_rn(r1);
    q1.x = __float2bfloat16_rn(r2); q1.y = __float2bfloat16_rn(r3);
    lo[2*i] = q0; lo[2*i+1] = q1;
}

// ===========================================================================
// vtrans: g_v f32 [b,s,h*64+d] -> vtf fp16 [b,h,d,S] (per-head transpose)
// ===========================================================================
__global__ void vtrans(const float* __restrict__ v, __half* __restrict__ vtf) {
    __shared__ float tile[64][65];
    const int tid = threadIdx.x;
    const int s0  = blockIdx.x * 64;
    const int bh  = blockIdx.y;
    const int b   = bh >> 4, h = bh & 15;
    const float* vb = v + (size_t)b * S_ * D_ + h * HD_;
#pragma unroll
    for (int u = tid; u < 4096; u += 256) {
        int row = u >> 6, col = u & 63;
        tile[col][row] = vb[(size_t)(s0 + row) * D_ + col];
    }
    __syncthreads();
    __half* oh = vtf + (size_t)bh * HD_ * S_ + s0;
#pragma unroll
    for (int u = tid; u < 4096; u += 256) {
        int d = u >> 6, sc = u & 63;
        oh[(size_t)d * S_ + sc] = __float2half_rn(tile[d][sc]);
    }
}

// ===========================================================================
// gemm_bf16x3:  Y = (Ah+Al)[M,K] @ (Bh+Bl)[N,K]^T + bias   (split-3 HMMA)
// Output modes: f32 Y, bf16 hi/lo planes (Yh/Yl), or fp16 plane (Yf).
// [mainloop identical to R8/R9 — validated]
// ===========================================================================
#define GSTAGE 32768
#define GSMEM  (2*GSTAGE)

__global__ void __launch_bounds__(256)
gemm_bf16x3(const __nv_bfloat16* __restrict__ Ah, const __nv_bfloat16* __restrict__ Al,
            const __nv_bfloat16* __restrict__ Bh, const __nv_bfloat16* __restrict__ Bl,
            const float* __restrict__ bias, float* __restrict__ Y,
            __nv_bfloat16* __restrict__ Yh, __nv_bfloat16* __restrict__ Yl,
            __half* __restrict__ Yf) {
    extern __shared__ char sm[];
    const uint32_t sb = smem_u32(sm);
    const int tid  = threadIdx.x;
    const int lane = tid & 31;
    const int wid  = tid >> 5;
    const int wm   = (wid & 1) * 64;
    const int wn   = (wid >> 1) * 32;
    const int bm   = blockIdx.y * 128;
    const int bn   = blockIdx.x * 128;

    float acc[4][4][4];
#pragma unroll
    for (int i = 0; i < 4; i++)
#pragma unroll
        for (int j = 0; j < 4; j++)
#pragma unroll
            for (int q = 0; q < 4; q++) acc[i][j][q] = 0.f;

    auto prefetch = [&](int c, int stg) {
        uint32_t sbase = sb + stg * GSTAGE;
#pragma unroll
        for (int q = 0; q < 2; q++) {
            int u   = tid + q * 256;
            int row = u >> 2;
            int seg = u & 3;
            uint32_t d = row * 64 + ((seg * 16) ^ (((row >> 1) & 3) << 4));
            size_t oA = (size_t)(bm + row) * D_ + c * 32 + seg * 8;
            size_t oB = (size_t)(bn + row) * D_ + c * 32 + seg * 8;
            cpa16(sbase +         d, Ah + oA);
            cpa16(sbase +  8192 + d, Al + oA);
            cpa16(sbase + 16384 + d, Bh + oB);
            cpa16(sbase + 24576 + d, Bl + oB);
        }
        CP_COMMIT();
    };

    prefetch(0, 0);

    for (int c = 0; c < 32; c++) {
        if (c < 31) {
            prefetch(c + 1, (c + 1) & 1);
            asm volatile("cp.async.wait_group 1;" ::: "memory");
        } else {
            asm volatile("cp.async.wait_group 0;" ::: "memory");
        }
        __syncthreads();

        const uint32_t st = sb + (c & 1) * GSTAGE;
        const int r    = lane & 15;
        const int hseg = lane >> 4;

#pragma unroll
        for (int ks = 0; ks < 2; ks++) {
            const uint32_t kb = ks * 32 + hseg * 16;
            uint32_t ah[4][4], al[4][4], bh[4][2], bl[4][2];
#pragma unroll
            for (int i = 0; i < 4; i++) {
                int row = wm + i * 16 + r;
                uint32_t ad = st + row * 64 + (kb ^ (((row >> 1) & 3) << 4));
                LDSM4(ah[i][0], ah[i][1], ah[i][2], ah[i][3], ad);
                LDSM4(al[i][0], al[i][1], al[i][2], al[i][3], ad + 8192);
            }
#pragma unroll
            for (int jp = 0; jp < 2; jp++) {
                int row = wn + jp * 16 + r;
                uint32_t bd = st + 16384 + row * 64 + (kb ^ (((row >> 1) & 3) << 4));
                LDSM4(bh[2*jp][0], bh[2*jp+1][0], bh[2*jp][1], bh[2*jp+1][1], bd);
                LDSM4(bl[2*jp][0], bl[2*jp+1][0], bl[2*jp][1], bl[2*jp+1][1], bd + 8192);
            }
#pragma unroll
            for (int i = 0; i < 4; i++)
#pragma unroll
                for (int j = 0; j < 4; j++) {
                    MMA16816(acc[i][j], ah[i], bh[j][0], bh[j][1]);
                    MMA16816(acc[i][j], ah[i], bl[j][0], bl[j][1]);
                    MMA16816(acc[i][j], al[i], bh[j][0], bh[j][1]);
                }
        }
        __syncthreads();
    }

    const int mrow = lane >> 2;
    const int ncol = (lane & 3) * 2;
#pragma unroll
    for (int i = 0; i < 4; i++) {
#pragma unroll
        for (int j = 0; j < 4; j++) {
            int m = bm + wm + i * 16 + mrow;
            int n = bn + wn + j * 8 + ncol;
            float2 bv = *(const float2*)(bias + n);
            float y0 = acc[i][j][0] + bv.x;
            float y1 = acc[i][j][1] + bv.y;
            float y2 = acc[i][j][2] + bv.x;
            float y3 = acc[i][j][3] + bv.y;
            if (Yf) {
                *(uint32_t*)(Yf + (size_t)m*D_ + n)     = packh(y0, y1);
                *(uint32_t*)(Yf + (size_t)(m+8)*D_ + n) = packh(y2, y3);
            } else if (Yh) {
                __nv_bfloat16 h0,h1,h2,h3; float r0,r1,r2,r3;
                splitf(y0,h0,r0); splitf(y1,h1,r1);
                splitf(y2,h2,r2); splitf(y3,h3,r3);
                __nv_bfloat162 p; p.x=h0; p.y=h1;
                *(__nv_bfloat162*)(Yh + (size_t)m*D_ + n) = p;
                p.x=h2; p.y=h3;
                *(__nv_bfloat162*)(Yh + (size_t)(m+8)*D_ + n) = p;
                *(uint32_t*)(Yl + (size_t)m*D_ + n)     = packbf(r0, r1);
                *(uint32_t*)(Yl + (size_t)(m+8)*D_ + n) = packbf(r2, r3);
            } else {
                float2 o;
                o.x = y0; o.y = y1;
                *(float2*)(Y + (size_t)m * D_ + n) = o;
                o.x = y2; o.y = y3;
                *(float2*)(Y + (size_t)(m + 8) * D_ + n) = o;
            }
        }
    }
}

// ===========================================================================
// attn_mma: FlashAttention-style secure-softmax attention, fp16 single-MMA.
// CTA: 128 q-rows (8 warps x 16), loop 32 key-tiles of 64. HD=64.
//   stage A: S = Q K^T   (1 fp16 MMA per k16 — poly softmax tolerates fp16)
//   softmax poly on fragments -> P packed to fp16 A-fragments
//   stage B: ctx += P V   (1 fp16 MMA), V pre-transposed [d][S]
// Output: ctx bf16 hi/lo planes (feeds the split-3 O GEMM).
// SMEM: Q 16KB + 2 stages x (K 8KB + VT 8KB + mask 256B) = 49664 B.
// Swizzle for 128B rows: seg' = seg ^ (row&7), 16B segs.   [geometry = R9]
// ===========================================================================
#define ASTG  16640
#define AQ    16384
#define ASMEM (AQ + 2*ASTG)   // 49664

__global__ void __launch_bounds__(256)
attn_mma(const __half* __restrict__ qf_, const __half* __restrict__ kf_,
         const __half* __restrict__ vtf_, const float* __restrict__ mask,
         __nv_bfloat16* __restrict__ ch_, __nv_bfloat16* __restrict__ cl_) {
    extern __shared__ char sm[];
    const uint32_t sb = smem_u32(sm);
    const int tid  = threadIdx.x;
    const int lane = tid & 31;
    const int wid  = tid >> 5;
    const int t    = lane & 3;
    const int bh   = blockIdx.y;
    const int b    = bh >> 4, h = bh & 15;
    const int q0   = blockIdx.x * 128;

    const __half* qb = qf_ + ((size_t)b * S_ + q0) * D_ + h * HD_;
    const __half* kb = kf_ + (size_t)b * S_ * D_ + h * HD_;
    const __half* vb = vtf_ + (size_t)bh * HD_ * S_;

    // Load Q tile (128 rows x 64 fp16), swizzled
#pragma unroll
    for (int u = tid; u < 1024; u += 256) {
        int row = u >> 3, seg = u & 7;
        uint32_t d = row * 128 + ((seg ^ (row & 7)) << 4);
        cpa16(sb + d, qb + (size_t)row * D_ + seg * 8);
    }

    auto prefetch = [&](int kt, int stg) {
        uint32_t sbase = sb + AQ + stg * ASTG;
        int kr0 = kt * 64;
#pragma unroll
        for (int q = 0; q < 2; q++) {
            int u = tid + q * 256;            // 0..511
            int row = u >> 3, seg = u & 7;
            uint32_t d = row * 128 + ((seg ^ (row & 7)) << 4);
            cpa16(sbase +        d, kb + (size_t)(kr0 + row) * D_ + seg * 8);
            cpa16(sbase + 8192 + d, vb + (size_t)row * S_ + kr0 + seg * 8);
        }
        if (tid < 16)
            cpa16(sbase + 16384 + tid * 16, mask + (size_t)b * S_ + kr0 + tid * 4);
    };

    prefetch(0, 0);
    CP_COMMIT();     // group: Q + stage0

    float ctx[8][4];
#pragma unroll
    for (int j = 0; j < 8; j++)
#pragma unroll
        for (int q = 0; q < 4; q++) ctx[j][q] = 0.f;
    float dsum0 = 0.f, dsum1 = 0.f;

    const int r    = lane & 15;
    const int hseg = lane >> 4;
    const int rowA = wid * 16 + r;

    for (int kt = 0; kt < 32; kt++) {
        if (kt < 31) {
            prefetch(kt + 1, (kt + 1) & 1);
            CP_COMMIT();
            asm volatile("cp.async.wait_group 1;" ::: "memory");
        } else {
            asm volatile("cp.async.wait_group 0;" ::: "memory");
        }
        __syncthreads();

        const uint32_t st = sb + AQ + (kt & 1) * ASTG;
        const float* Ms = (const float*)(sm + AQ + (kt & 1) * ASTG + 16384);

        // ---- Stage A: S = Q K^T (fp16) ----
        float s[8][4];
#pragma unroll
        for (int j = 0; j < 8; j++)
#pragma unroll
            for (int q = 0; q < 4; q++) s[j][q] = 0.f;

#pragma unroll
        for (int ks = 0; ks < 4; ks++) {
            const int segA = ks * 2 + hseg;
            uint32_t qa = sb + rowA * 128 + ((segA ^ (rowA & 7)) << 4);
            uint32_t qA[4];
            LDSM4(qA[0], qA[1], qA[2], qA[3], qa);
            uint32_t kh[8][2];
#pragma unroll
            for (int jp = 0; jp < 4; jp++) {
                int row = jp * 16 + r;
                uint32_t kd = st + row * 128 + ((segA ^ (row & 7)) << 4);
                LDSM4(kh[2*jp][0], kh[2*jp+1][0], kh[2*jp][1], kh[2*jp+1][1], kd);
            }
#pragma unroll
            for (int j = 0; j < 8; j++)
                MMAH16816(s[j], qA, kh[j][0], kh[j][1]);
        }

        // ---- softmax poly + build fp16 P fragments ----
        uint32_t pa[4][4];
#pragma unroll
        for (int j = 0; j < 8; j++) {
            float2 mv = *(const float2*)(Ms + j * 8 + t * 2);
            float mt0 = (1.0f - mv.x) * -10000.0f;
            float mt1 = (1.0f - mv.y) * -10000.0f;
            float e[4];
#pragma unroll
            for (int q = 0; q < 4; q++) {
                float c = s[j][q] * 0.125f + ((q & 1) ? mt1 : mt0);
                c = fminf(3.0f, fmaxf(-3.0f, c));
                float sg = 0.5f + c * (0.25f - 0.01f * c * c);
                e[q] = fminf(0.99f, fmaxf(0.01f, sg));
            }
            dsum0 += e[0] + e[1];
            dsum1 += e[2] + e[3];
            int kk = j >> 1, half = (j & 1) * 2;
            pa[kk][half + 0] = packh(e[0], e[1]);   // rows (g)
            pa[kk][half + 1] = packh(e[2], e[3]);   // rows (g+8)
        }

        // ---- Stage B: ctx += P V (fp16) ----
#pragma unroll
        for (int kk = 0; kk < 4; kk++) {
            const int segB = kk * 2 + hseg;
            uint32_t vh[8][2];
#pragma unroll
            for (int jp = 0; jp < 4; jp++) {
                int row = jp * 16 + r;
                uint32_t vd = st + 8192 + row * 128 + ((segB ^ (row & 7)) << 4);
                LDSM4(vh[2*jp][0], vh[2*jp+1][0], vh[2*jp][1], vh[2*jp+1][1], vd);
            }
#pragma unroll
            for (int j = 0; j < 8; j++)
                MMAH16816(ctx[j], pa[kk], vh[j][0], vh[j][1]);
        }
        __syncthreads();
    }

    // ---- reduce denominators across lane quads (same row) ----
    dsum0 += __shfl_xor_sync(0xffffffffu, dsum0, 1);
    dsum0 += __shfl_xor_sync(0xffffffffu, dsum0, 2);
    dsum1 += __shfl_xor_sync(0xffffffffu, dsum1, 1);
    dsum1 += __shfl_xor_sync(0xffffffffu, dsum1, 2);
    float inv0 = 1.0f / (dsum0 + 1e-8f);
    float inv1 = 1.0f / (dsum1 + 1e-8f);

    const int g = lane >> 2;
    const int row0 = q0 + wid * 16 + g;
    const int row1 = row0 + 8;
#pragma unroll
    for (int j = 0; j < 8; j++) {
        int col = h * HD_ + j * 8 + t * 2;
        float y0 = ctx[j][0] * inv0, y1 = ctx[j][1] * inv0;
        float y2 = ctx[j][2] * inv1, y3 = ctx[j][3] * inv1;
        __nv_bfloat16 h0,h1,h2,h3; float r0,r1,r2,r3;
        splitf(y0,h0,r0); splitf(y1,h1,r1);
        splitf(y2,h2,r2); splitf(y3,h3,r3);
        size_t i0 = ((size_t)b * S_ + row0) * D_ + col;
        size_t i1 = ((size_t)b * S_ + row1) * D_ + col;
        __nv_bfloat162 p; p.x=h0; p.y=h1;
        *(__nv_bfloat162*)(ch_ + i0) = p;
        p.x=h2; p.y=h3;
        *(__nv_bfloat162*)(ch_ + i1) = p;
        *(uint32_t*)(cl_ + i0) = packbf(r0, r1);
        *(uint32_t*)(cl_ + i1) = packbf(r2, r3);
    }
}

// ---------------------------------------------------------------------------
// Host launcher.
// ---------------------------------------------------------------------------
extern "C" void kernel_launch(void* const* d_in, const int* in_sizes, int n_in,
                              void* d_out, int out_size) {
    const float* hs = (const float*)d_in[0];
    const float* am = (const float*)d_in[1];
    const float* Wq = (const float*)d_in[2];
    const float* bq = (const float*)d_in[3];
    const float* Wk = (const float*)d_in[4];
    const float* bk = (const float*)d_in[5];
    const float* Wv = (const float*)d_in[6];
    const float* bv = (const float*)d_in[7];
    const float* Wo = (const float*)d_in[8];
    const float* bo = (const float*)d_in[9];
    float* out = (float*)d_out;

    __nv_bfloat16 *xh, *xl, *wh, *wl, *ch, *cl;
    __half *qf, *kf, *vtf;
    float* v;
    cudaGetSymbolAddress((void**)&xh,  g_x_hi);
    cudaGetSymbolAddress((void**)&xl,  g_x_lo);
    cudaGetSymbolAddress((void**)&wh,  g_w_hi);
    cudaGetSymbolAddress((void**)&wl,  g_w_lo);
    cudaGetSymbolAddress((void**)&qf,  g_qf);
    cudaGetSymbolAddress((void**)&kf,  g_kf);
    cudaGetSymbolAddress((void**)&v,   g_v);
    cudaGetSymbolAddress((void**)&vtf, g_vtf);
    cudaGetSymbolAddress((void**)&ch,  g_ch);
    cudaGetSymbolAddress((void**)&cl,  g_cl);

    static bool attr_set = false;
    if (!attr_set) {
        cudaFuncSetAttribute(gemm_bf16x3,
                             cudaFuncAttributeMaxDynamicSharedMemorySize, GSMEM);
        cudaFuncSetAttribute(attn_mma,
                             cudaFuncAttributeMaxDynamicSharedMemorySize, ASMEM);
        attr_set = true;
    }

    const int D2 = D_ * D_;
    const int n4_x = M_ * D_ / 4;
    const int n4_w = D2 / 4;

    split_bf16<<<n4_x/256, 256>>>((const float4*)hs,
                                  (__nv_bfloat162*)xh, (__nv_bfloat162*)xl, n4_x);
    split_bf16<<<n4_w/256, 256>>>((const float4*)Wq,
                                  (__nv_bfloat162*)(wh),        (__nv_bfloat162*)(wl),        n4_w);
    split_bf16<<<n4_w/256, 256>>>((const float4*)Wk,
                                  (__nv_bfloat162*)(wh + D2),   (__nv_bfloat162*)(wl + D2),   n4_w);
    split_bf16<<<n4_w/256, 256>>>((const float4*)Wv,
                                  (__nv_bfloat162*)(wh + 2*D2), (__nv_bfloat162*)(wl + 2*D2), n4_w);
    split_bf16<<<n4_w/256, 256>>>((const float4*)Wo,
                                  (__nv_bfloat162*)(wh + 3*D2), (__nv_bfloat162*)(wl + 3*D2), n4_w);

    dim3 ggrid(D_/128, M_/128);   // (8, 32)
    gemm_bf16x3<<<ggrid, 256, GSMEM>>>(xh, xl, wh,        wl,        bq,
                                       nullptr, nullptr, nullptr, qf);
    gemm_bf16x3<<<ggrid, 256, GSMEM>>>(xh, xl, wh + D2,   wl + D2,   bk,
                                       nullptr, nullptr, nullptr, kf);
    gemm_bf16x3<<<ggrid, 256, GSMEM>>>(xh, xl, wh + 2*D2, wl + 2*D2, bv,
                                       v, nullptr, nullptr, nullptr);

    vtrans<<<dim3(S_/64, B_*H_), 256>>>(v, vtf);

    dim3 agrid(S_/128, B_*H_);    // (16, 32)
    attn_mma<<<agrid, 256, ASMEM>>>(qf, kf, vtf, am, ch, cl);

    gemm_bf16x3<<<ggrid, 256, GSMEM>>>(ch, cl, wh + 3*D2, wl + 3*D2, bo,
                                       out, nullptr, nullptr, nullptr);
}

// round 13
// speedup vs baseline: 4.6724x; 1.2789x over previous
#include <cuda_runtime.h>
#include <cuda_bf16.h>
#include <cuda_fp16.h>
#include <cstdint>
#include <cstddef>

// Problem constants
#define B_   2
#define S_   2048
#define D_   1024
#define H_   16
#define HD_  64
#define M_   (B_*S_)

// Scratch (no allocation allowed -> device globals)
__device__ __half g_xf [M_*D_];     // hidden_states fp16
__device__ __half g_wfh[4*D_*D_];   // weight hi planes (fp16)
__device__ __half g_wfl[4*D_*D_];   // weight lo planes (fp16, denormal-range ok)
__device__ __half g_qf [M_*D_];
__device__ __half g_kf [M_*D_];
__device__ float  g_v  [M_*D_];
__device__ __half g_vtf[M_*D_];     // V^T per (b,h): [b,h,hd,S]
__device__ __half g_cf [M_*D_];     // ctx fp16

// ===========================================================================
// Helpers (baseline PTX for compute_103: ldmatrix, mma.sync, cp.async)
// ===========================================================================
__device__ __forceinline__ uint32_t smem_u32(const void* p) {
    uint32_t r;
    asm("{ .reg .u64 t; cvta.to.shared.u64 t, %1; cvt.u32.u64 %0, t; }"
        : "=r"(r) : "l"(p));
    return r;
}

__device__ __forceinline__ void cpa16(uint32_t dst, const void* src) {
    asm volatile("cp.async.cg.shared.global [%0], [%1], 16;"
                 :: "r"(dst), "l"(__cvta_generic_to_global(src)) : "memory");
}

#define CP_COMMIT() asm volatile("cp.async.commit_group;" ::: "memory")

#define LDSM4(d0,d1,d2,d3,a) \
    asm volatile("ldmatrix.sync.aligned.m8n8.x4.shared.b16 {%0,%1,%2,%3}, [%4];" \
        : "=r"(d0),"=r"(d1),"=r"(d2),"=r"(d3) : "r"(a))

#define MMAH16816(c,a,b0,b1) \
    asm volatile("mma.sync.aligned.m16n8k16.row.col.f32.f16.f16.f32 " \
        "{%0,%1,%2,%3},{%4,%5,%6,%7},{%8,%9},{%0,%1,%2,%3};" \
        : "+f"((c)[0]),"+f"((c)[1]),"+f"((c)[2]),"+f"((c)[3]) \
        : "r"((a)[0]),"r"((a)[1]),"r"((a)[2]),"r"((a)[3]),"r"(b0),"r"(b1))

// pack two f32 -> f16x2 reg (first arg in low 16 bits)
__device__ __forceinline__ uint32_t packh(float lo, float hi) {
    uint32_t r;
    asm("cvt.rn.f16x2.f32 %0, %1, %2;" : "=r"(r) : "f"(hi), "f"(lo));
    return r;
}

// ===========================================================================
// conv_f16: f32 -> fp16 plane
// ===========================================================================
__global__ void conv_f16(const float4* __restrict__ x,
                         __half2* __restrict__ y, int n4) {
    int i = blockIdx.x * blockDim.x + threadIdx.x;
    if (i >= n4) return;
    float4 v = x[i];
    y[2*i]   = __floats2half2_rn(v.x, v.y);
    y[2*i+1] = __floats2half2_rn(v.z, v.w);
}

// ===========================================================================
// split_f16: f32 -> (hi, lo) fp16 planes.  lo = f16(x - f32(hi))
// ===========================================================================
__global__ void split_f16(const float4* __restrict__ x,
                          __half2* __restrict__ hi,
                          __half2* __restrict__ lo, int n4) {
    int i = blockIdx.x * blockDim.x + threadIdx.x;
    if (i >= n4) return;
    float4 v = x[i];
    __half h0 = __float2half_rn(v.x);
    __half h1 = __float2half_rn(v.y);
    __half h2 = __float2half_rn(v.z);
    __half h3 = __float2half_rn(v.w);
    __half2 p; p.x = h0; p.y = h1;
    hi[2*i] = p;
    p.x = h2; p.y = h3;
    hi[2*i+1] = p;
    __half2 q;
    q.x = __float2half_rn(v.x - __half2float(h0));
    q.y = __float2half_rn(v.y - __half2float(h1));
    lo[2*i] = q;
    q.x = __float2half_rn(v.z - __half2float(h2));
    q.y = __float2half_rn(v.w - __half2float(h3));
    lo[2*i+1] = q;
}

// ===========================================================================
// vtrans: g_v f32 [b,s,h*64+d] -> vtf fp16 [b,h,d,S] (per-head transpose)
// ===========================================================================
__global__ void vtrans(const float* __restrict__ v, __half* __restrict__ vtf) {
    __shared__ float tile[64][65];
    const int tid = threadIdx.x;
    const int s0  = blockIdx.x * 64;
    const int bh  = blockIdx.y;
    const int b   = bh >> 4, h = bh & 15;
    const float* vb = v + (size_t)b * S_ * D_ + h * HD_;
#pragma unroll
    for (int u = tid; u < 4096; u += 256) {
        int row = u >> 6, col = u & 63;
        tile[col][row] = vb[(size_t)(s0 + row) * D_ + col];
    }
    __syncthreads();
    __half* oh = vtf + (size_t)bh * HD_ * S_ + s0;
#pragma unroll
    for (int u = tid; u < 4096; u += 256) {
        int d = u >> 6, sc = u & 63;
        oh[(size_t)d * S_ + sc] = __float2half_rn(tile[d][sc]);
    }
}

// ===========================================================================
// gemm_f16x2:  Y[M,N] = A_f16[M,K] @ (Wh+Wl)[N,K]^T + bias   (2-MMA split)
// CTA tile 128x128, BK=32, 256 thr = 8 warps (2m x 4n), warp tile 64x32.
// Double-buffered cp.async; XOR-swizzled smem; ldmatrix.x4; fp16 m16n8k16.
// SMEM: 2 stages x 3 planes x 8KB = 48 KB.
// [geometry identical to validated gemm_bf16x3 minus the A-lo plane]
// ===========================================================================
#define GSTAGE 24576
#define GSMEM  (2*GSTAGE)

__global__ void __launch_bounds__(256)
gemm_f16x2(const __half* __restrict__ A,
           const __half* __restrict__ Bh, const __half* __restrict__ Bl,
           const float* __restrict__ bias, float* __restrict__ Y,
           __half* __restrict__ Yf) {
    extern __shared__ char sm[];
    const uint32_t sb = smem_u32(sm);
    const int tid  = threadIdx.x;
    const int lane = tid & 31;
    const int wid  = tid >> 5;
    const int wm   = (wid & 1) * 64;
    const int wn   = (wid >> 1) * 32;
    const int bm   = blockIdx.y * 128;
    const int bn   = blockIdx.x * 128;

    float acc[4][4][4];
#pragma unroll
    for (int i = 0; i < 4; i++)
#pragma unroll
        for (int j = 0; j < 4; j++)
#pragma unroll
            for (int q = 0; q < 4; q++) acc[i][j][q] = 0.f;

    auto prefetch = [&](int c, int stg) {
        uint32_t sbase = sb + stg * GSTAGE;
#pragma unroll
        for (int q = 0; q < 2; q++) {
            int u   = tid + q * 256;          // 0..511
            int row = u >> 2;                 // 0..127
            int seg = u & 3;                  // 16B segment within 64B row
            uint32_t d = row * 64 + ((seg * 16) ^ (((row >> 1) & 3) << 4));
            size_t oA = (size_t)(bm + row) * D_ + c * 32 + seg * 8;
            size_t oB = (size_t)(bn + row) * D_ + c * 32 + seg * 8;
            cpa16(sbase +         d, A  + oA);
            cpa16(sbase +  8192 + d, Bh + oB);
            cpa16(sbase + 16384 + d, Bl + oB);
        }
        CP_COMMIT();
    };

    prefetch(0, 0);

    for (int c = 0; c < 32; c++) {
        if (c < 31) {
            prefetch(c + 1, (c + 1) & 1);
            asm volatile("cp.async.wait_group 1;" ::: "memory");
        } else {
            asm volatile("cp.async.wait_group 0;" ::: "memory");
        }
        __syncthreads();

        const uint32_t st = sb + (c & 1) * GSTAGE;
        const int r    = lane & 15;
        const int hseg = lane >> 4;

#pragma unroll
        for (int ks = 0; ks < 2; ks++) {
            const uint32_t kb = ks * 32 + hseg * 16;
            uint32_t ah[4][4], bh[4][2], bl[4][2];
#pragma unroll
            for (int i = 0; i < 4; i++) {
                int row = wm + i * 16 + r;
                uint32_t ad = st + row * 64 + (kb ^ (((row >> 1) & 3) << 4));
                LDSM4(ah[i][0], ah[i][1], ah[i][2], ah[i][3], ad);
            }
#pragma unroll
            for (int jp = 0; jp < 2; jp++) {
                int row = wn + jp * 16 + r;
                uint32_t bd = st + 8192 + row * 64 + (kb ^ (((row >> 1) & 3) << 4));
                LDSM4(bh[2*jp][0], bh[2*jp+1][0], bh[2*jp][1], bh[2*jp+1][1], bd);
                LDSM4(bl[2*jp][0], bl[2*jp+1][0], bl[2*jp][1], bl[2*jp+1][1], bd + 8192);
            }
#pragma unroll
            for (int i = 0; i < 4; i++)
#pragma unroll
                for (int j = 0; j < 4; j++) {
                    MMAH16816(acc[i][j], ah[i], bh[j][0], bh[j][1]);
                    MMAH16816(acc[i][j], ah[i], bl[j][0], bl[j][1]);
                }
        }
        __syncthreads();
    }

    const int mrow = lane >> 2;
    const int ncol = (lane & 3) * 2;
#pragma unroll
    for (int i = 0; i < 4; i++) {
#pragma unroll
        for (int j = 0; j < 4; j++) {
            int m = bm + wm + i * 16 + mrow;
            int n = bn + wn + j * 8 + ncol;
            float2 bv = *(const float2*)(bias + n);
            float y0 = acc[i][j][0] + bv.x;
            float y1 = acc[i][j][1] + bv.y;
            float y2 = acc[i][j][2] + bv.x;
            float y3 = acc[i][j][3] + bv.y;
            if (Yf) {
                *(uint32_t*)(Yf + (size_t)m*D_ + n)     = packh(y0, y1);
                *(uint32_t*)(Yf + (size_t)(m+8)*D_ + n) = packh(y2, y3);
            } else {
                float2 o;
                o.x = y0; o.y = y1;
                *(float2*)(Y + (size_t)m * D_ + n) = o;
                o.x = y2; o.y = y3;
                *(float2*)(Y + (size_t)(m + 8) * D_ + n) = o;
            }
        }
    }
}

// ===========================================================================
// attn_mma: FlashAttention-style secure-softmax attention, fp16 single-MMA.
// [mainloop identical to validated R11; epilogue now emits one fp16 plane]
// ===========================================================================
#define ASTG  16640
#define AQ    16384
#define ASMEM (AQ + 2*ASTG)   // 49664

__global__ void __launch_bounds__(256)
attn_mma(const __half* __restrict__ qf_, const __half* __restrict__ kf_,
         const __half* __restrict__ vtf_, const float* __restrict__ mask,
         __half* __restrict__ cf_) {
    extern __shared__ char sm[];
    const uint32_t sb = smem_u32(sm);
    const int tid  = threadIdx.x;
    const int lane = tid & 31;
    const int wid  = tid >> 5;
    const int t    = lane & 3;
    const int bh   = blockIdx.y;
    const int b    = bh >> 4, h = bh & 15;
    const int q0   = blockIdx.x * 128;

    const __half* qb = qf_ + ((size_t)b * S_ + q0) * D_ + h * HD_;
    const __half* kb = kf_ + (size_t)b * S_ * D_ + h * HD_;
    const __half* vb = vtf_ + (size_t)bh * HD_ * S_;

    // Load Q tile (128 rows x 64 fp16), swizzled
#pragma unroll
    for (int u = tid; u < 1024; u += 256) {
        int row = u >> 3, seg = u & 7;
        uint32_t d = row * 128 + ((seg ^ (row & 7)) << 4);
        cpa16(sb + d, qb + (size_t)row * D_ + seg * 8);
    }

    auto prefetch = [&](int kt, int stg) {
        uint32_t sbase = sb + AQ + stg * ASTG;
        int kr0 = kt * 64;
#pragma unroll
        for (int q = 0; q < 2; q++) {
            int u = tid + q * 256;
            int row = u >> 3, seg = u & 7;
            uint32_t d = row * 128 + ((seg ^ (row & 7)) << 4);
            cpa16(sbase +        d, kb + (size_t)(kr0 + row) * D_ + seg * 8);
            cpa16(sbase + 8192 + d, vb + (size_t)row * S_ + kr0 + seg * 8);
        }
        if (tid < 16)
            cpa16(sbase + 16384 + tid * 16, mask + (size_t)b * S_ + kr0 + tid * 4);
    };

    prefetch(0, 0);
    CP_COMMIT();     // group: Q + stage0

    float ctx[8][4];
#pragma unroll
    for (int j = 0; j < 8; j++)
#pragma unroll
        for (int q = 0; q < 4; q++) ctx[j][q] = 0.f;
    float dsum0 = 0.f, dsum1 = 0.f;

    const int r    = lane & 15;
    const int hseg = lane >> 4;
    const int rowA = wid * 16 + r;

    for (int kt = 0; kt < 32; kt++) {
        if (kt < 31) {
            prefetch(kt + 1, (kt + 1) & 1);
            CP_COMMIT();
            asm volatile("cp.async.wait_group 1;" ::: "memory");
        } else {
            asm volatile("cp.async.wait_group 0;" ::: "memory");
        }
        __syncthreads();

        const uint32_t st = sb + AQ + (kt & 1) * ASTG;
        const float* Ms = (const float*)(sm + AQ + (kt & 1) * ASTG + 16384);

        // ---- Stage A: S = Q K^T (fp16) ----
        float s[8][4];
#pragma unroll
        for (int j = 0; j < 8; j++)
#pragma unroll
            for (int q = 0; q < 4; q++) s[j][q] = 0.f;

#pragma unroll
        for (int ks = 0; ks < 4; ks++) {
            const int segA = ks * 2 + hseg;
            uint32_t qa = sb + rowA * 128 + ((segA ^ (rowA & 7)) << 4);
            uint32_t qA[4];
            LDSM4(qA[0], qA[1], qA[2], qA[3], qa);
            uint32_t kh[8][2];
#pragma unroll
            for (int jp = 0; jp < 4; jp++) {
                int row = jp * 16 + r;
                uint32_t kd = st + row * 128 + ((segA ^ (row & 7)) << 4);
                LDSM4(kh[2*jp][0], kh[2*jp+1][0], kh[2*jp][1], kh[2*jp+1][1], kd);
            }
#pragma unroll
            for (int j = 0; j < 8; j++)
                MMAH16816(s[j], qA, kh[j][0], kh[j][1]);
        }

        // ---- softmax poly + build fp16 P fragments ----
        uint32_t pa[4][4];
#pragma unroll
        for (int j = 0; j < 8; j++) {
            float2 mv = *(const float2*)(Ms + j * 8 + t * 2);
            float mt0 = (1.0f - mv.x) * -10000.0f;
            float mt1 = (1.0f - mv.y) * -10000.0f;
            float e[4];
#pragma unroll
            for (int q = 0; q < 4; q++) {
                float c = s[j][q] * 0.125f + ((q & 1) ? mt1 : mt0);
                c = fminf(3.0f, fmaxf(-3.0f, c));
                float sg = 0.5f + c * (0.25f - 0.01f * c * c);
                e[q] = fminf(0.99f, fmaxf(0.01f, sg));
            }
            dsum0 += e[0] + e[1];
            dsum1 += e[2] + e[3];
            int kk = j >> 1, half = (j & 1) * 2;
            pa[kk][half + 0] = packh(e[0], e[1]);   // rows (g)
            pa[kk][half + 1] = packh(e[2], e[3]);   // rows (g+8)
        }

        // ---- Stage B: ctx += P V (fp16) ----
#pragma unroll
        for (int kk = 0; kk < 4; kk++) {
            const int segB = kk * 2 + hseg;
            uint32_t vh[8][2];
#pragma unroll
            for (int jp = 0; jp < 4; jp++) {
                int row = jp * 16 + r;
                uint32_t vd = st + 8192 + row * 128 + ((segB ^ (row & 7)) << 4);
                LDSM4(vh[2*jp][0], vh[2*jp+1][0], vh[2*jp][1], vh[2*jp+1][1], vd);
            }
#pragma unroll
            for (int j = 0; j < 8; j++)
                MMAH16816(ctx[j], pa[kk], vh[j][0], vh[j][1]);
        }
        __syncthreads();
    }

    // ---- reduce denominators across lane quads (same row) ----
    dsum0 += __shfl_xor_sync(0xffffffffu, dsum0, 1);
    dsum0 += __shfl_xor_sync(0xffffffffu, dsum0, 2);
    dsum1 += __shfl_xor_sync(0xffffffffu, dsum1, 1);
    dsum1 += __shfl_xor_sync(0xffffffffu, dsum1, 2);
    float inv0 = 1.0f / (dsum0 + 1e-8f);
    float inv1 = 1.0f / (dsum1 + 1e-8f);

    const int g = lane >> 2;
    const int row0 = q0 + wid * 16 + g;
    const int row1 = row0 + 8;
#pragma unroll
    for (int j = 0; j < 8; j++) {
        int col = h * HD_ + j * 8 + t * 2;
        size_t i0 = ((size_t)b * S_ + row0) * D_ + col;
        size_t i1 = ((size_t)b * S_ + row1) * D_ + col;
        *(uint32_t*)(cf_ + i0) = packh(ctx[j][0] * inv0, ctx[j][1] * inv0);
        *(uint32_t*)(cf_ + i1) = packh(ctx[j][2] * inv1, ctx[j][3] * inv1);
    }
}

// ---------------------------------------------------------------------------
// Host launcher. Inputs (metadata order):
//  0 hidden_states [B,S,D] f32    1 attention_mask [B,S] f32
//  2 Wq [D,D]  3 bq [D]  4 Wk  5 bk  6 Wv  7 bv  8 Wo  9 bo
// ---------------------------------------------------------------------------
extern "C" void kernel_launch(void* const* d_in, const int* in_sizes, int n_in,
                              void* d_out, int out_size) {
    const float* hs = (const float*)d_in[0];
    const float* am = (const float*)d_in[1];
    const float* Wq = (const float*)d_in[2];
    const float* bq = (const float*)d_in[3];
    const float* Wk = (const float*)d_in[4];
    const float* bk = (const float*)d_in[5];
    const float* Wv = (const float*)d_in[6];
    const float* bv = (const float*)d_in[7];
    const float* Wo = (const float*)d_in[8];
    const float* bo = (const float*)d_in[9];
    float* out = (float*)d_out;

    __half *xf, *wfh, *wfl, *qf, *kf, *vtf, *cf;
    float* v;
    cudaGetSymbolAddress((void**)&xf,  g_xf);
    cudaGetSymbolAddress((void**)&wfh, g_wfh);
    cudaGetSymbolAddress((void**)&wfl, g_wfl);
    cudaGetSymbolAddress((void**)&qf,  g_qf);
    cudaGetSymbolAddress((void**)&kf,  g_kf);
    cudaGetSymbolAddress((void**)&v,   g_v);
    cudaGetSymbolAddress((void**)&vtf, g_vtf);
    cudaGetSymbolAddress((void**)&cf,  g_cf);

    static bool attr_set = false;
    if (!attr_set) {
        cudaFuncSetAttribute(gemm_f16x2,
                             cudaFuncAttributeMaxDynamicSharedMemorySize, GSMEM);
        cudaFuncSetAttribute(attn_mma,
                             cudaFuncAttributeMaxDynamicSharedMemorySize, ASMEM);
        attr_set = true;
    }

    const int D2 = D_ * D_;
    const int n4_x = M_ * D_ / 4;
    const int n4_w = D2 / 4;

    conv_f16<<<n4_x/256, 256>>>((const float4*)hs, (__half2*)xf, n4_x);
    split_f16<<<n4_w/256, 256>>>((const float4*)Wq,
                                 (__half2*)(wfh),        (__half2*)(wfl),        n4_w);
    split_f16<<<n4_w/256, 256>>>((const float4*)Wk,
                                 (__half2*)(wfh + D2),   (__half2*)(wfl + D2),   n4_w);
    split_f16<<<n4_w/256, 256>>>((const float4*)Wv,
                                 (__half2*)(wfh + 2*D2), (__half2*)(wfl + 2*D2), n4_w);
    split_f16<<<n4_w/256, 256>>>((const float4*)Wo,
                                 (__half2*)(wfh + 3*D2), (__half2*)(wfl + 3*D2), n4_w);

    dim3 ggrid(D_/128, M_/128);   // (8, 32)
    gemm_f16x2<<<ggrid, 256, GSMEM>>>(xf, wfh,        wfl,        bq, nullptr, qf);
    gemm_f16x2<<<ggrid, 256, GSMEM>>>(xf, wfh + D2,   wfl + D2,   bk, nullptr, kf);
    gemm_f16x2<<<ggrid, 256, GSMEM>>>(xf, wfh + 2*D2, wfl + 2*D2, bv, v, nullptr);

    vtrans<<<dim3(S_/64, B_*H_), 256>>>(v, vtf);

    dim3 agrid(S_/128, B_*H_);    // (16, 32)
    attn_mma<<<agrid, 256, ASMEM>>>(qf, kf, vtf, am, cf);

    gemm_f16x2<<<ggrid, 256, GSMEM>>>(cf, wfh + 3*D2, wfl + 3*D2, bo, out, nullptr);
}

// round 14
// speedup vs baseline: 5.4071x; 1.1572x over previous
#include <cuda_runtime.h>
#include <cuda_bf16.h>
#include <cuda_fp16.h>
#include <cstdint>
#include <cstddef>

// Problem constants
#define B_   2
#define S_   2048
#define D_   1024
#define H_   16
#define HD_  64
#define M_   (B_*S_)

// Scratch (no allocation allowed -> device globals)
__device__ __half g_xf [M_*D_];     // hidden_states fp16
__device__ __half g_wfh[4*D_*D_];   // weight hi planes (fp16)
__device__ __half g_wfl[4*D_*D_];   // weight lo planes (only V/O slots used)
__device__ __half g_qf [M_*D_];
__device__ __half g_kf [M_*D_];
__device__ float  g_v  [M_*D_];
__device__ __half g_vtf[M_*D_];     // V^T per (b,h): [b,h,hd,S]
__device__ __half g_cf [M_*D_];     // ctx fp16

// ===========================================================================
// Helpers (baseline PTX for compute_103: ldmatrix, mma.sync, cp.async)
// ===========================================================================
__device__ __forceinline__ uint32_t smem_u32(const void* p) {
    uint32_t r;
    asm("{ .reg .u64 t; cvta.to.shared.u64 t, %1; cvt.u32.u64 %0, t; }"
        : "=r"(r) : "l"(p));
    return r;
}

__device__ __forceinline__ void cpa16(uint32_t dst, const void* src) {
    asm volatile("cp.async.cg.shared.global [%0], [%1], 16;"
                 :: "r"(dst), "l"(__cvta_generic_to_global(src)) : "memory");
}

#define CP_COMMIT() asm volatile("cp.async.commit_group;" ::: "memory")

#define LDSM4(d0,d1,d2,d3,a) \
    asm volatile("ldmatrix.sync.aligned.m8n8.x4.shared.b16 {%0,%1,%2,%3}, [%4];" \
        : "=r"(d0),"=r"(d1),"=r"(d2),"=r"(d3) : "r"(a))

#define MMAH16816(c,a,b0,b1) \
    asm volatile("mma.sync.aligned.m16n8k16.row.col.f32.f16.f16.f32 " \
        "{%0,%1,%2,%3},{%4,%5,%6,%7},{%8,%9},{%0,%1,%2,%3};" \
        : "+f"((c)[0]),"+f"((c)[1]),"+f"((c)[2]),"+f"((c)[3]) \
        : "r"((a)[0]),"r"((a)[1]),"r"((a)[2]),"r"((a)[3]),"r"(b0),"r"(b1))

// pack two f32 -> f16x2 reg (first arg in low 16 bits)
__device__ __forceinline__ uint32_t packh(float lo, float hi) {
    uint32_t r;
    asm("cvt.rn.f16x2.f32 %0, %1, %2;" : "=r"(r) : "f"(hi), "f"(lo));
    return r;
}

// ===========================================================================
// conv_f16: f32 -> fp16 plane (hidden_states)
// ===========================================================================
__global__ void conv_f16(const float4* __restrict__ x,
                         __half2* __restrict__ y, int n4) {
    int i = blockIdx.x * blockDim.x + threadIdx.x;
    if (i >= n4) return;
    float4 v = x[i];
    y[2*i]   = __floats2half2_rn(v.x, v.y);
    y[2*i+1] = __floats2half2_rn(v.z, v.w);
}

// ===========================================================================
// prep_w: all 4 weights in one launch. blockIdx.y = weight id.
// Wq/Wk (id 0,1): hi plane only.  Wv/Wo (id 2,3): hi + lo planes.
// ===========================================================================
__global__ void prep_w(const float4* __restrict__ Wq, const float4* __restrict__ Wk,
                       const float4* __restrict__ Wv, const float4* __restrict__ Wo,
                       __half2* __restrict__ wfh, __half2* __restrict__ wfl, int n4) {
    int i = blockIdx.x * blockDim.x + threadIdx.x;
    if (i >= n4) return;
    int w = blockIdx.y;
    const float4* src = (w == 0) ? Wq : (w == 1) ? Wk : (w == 2) ? Wv : Wo;
    float4 v = src[i];
    size_t off = (size_t)w * (D_ * (size_t)D_ / 2);   // half2 units per weight
    __half h0 = __float2half_rn(v.x);
    __half h1 = __float2half_rn(v.y);
    __half h2 = __float2half_rn(v.z);
    __half h3 = __float2half_rn(v.w);
    __half2 p; p.x = h0; p.y = h1;
    wfh[off + 2*i] = p;
    p.x = h2; p.y = h3;
    wfh[off + 2*i + 1] = p;
    if (w >= 2) {
        __half2 q;
        q.x = __float2half_rn(v.x - __half2float(h0));
        q.y = __float2half_rn(v.y - __half2float(h1));
        wfl[off + 2*i] = q;
        q.x = __float2half_rn(v.z - __half2float(h2));
        q.y = __float2half_rn(v.w - __half2float(h3));
        wfl[off + 2*i + 1] = q;
    }
}

// ===========================================================================
// vtrans: g_v f32 [b,s,h*64+d] -> vtf fp16 [b,h,d,S] (per-head transpose)
// ===========================================================================
__global__ void vtrans(const float* __restrict__ v, __half* __restrict__ vtf) {
    __shared__ float tile[64][65];
    const int tid = threadIdx.x;
    const int s0  = blockIdx.x * 64;
    const int bh  = blockIdx.y;
    const int b   = bh >> 4, h = bh & 15;
    const float* vb = v + (size_t)b * S_ * D_ + h * HD_;
#pragma unroll
    for (int u = tid; u < 4096; u += 256) {
        int row = u >> 6, col = u & 63;
        tile[col][row] = vb[(size_t)(s0 + row) * D_ + col];
    }
    __syncthreads();
    __half* oh = vtf + (size_t)bh * HD_ * S_ + s0;
#pragma unroll
    for (int u = tid; u < 4096; u += 256) {
        int d = u >> 6, sc = u & 63;
        oh[(size_t)d * S_ + sc] = __float2half_rn(tile[d][sc]);
    }
}

// ===========================================================================
// gemm_f16<LO>:  Y[M,N] = A_f16[M,K] @ Wh[N,K]^T (+ A @ Wl^T if LO) + bias
// CTA tile 128x128, BK=32, 256 thr = 8 warps (2m x 4n), warp tile 64x32.
// Double-buffered cp.async; XOR-swizzled smem; ldmatrix.x4; fp16 m16n8k16.
// SMEM/stage: LO ? 3 planes (24KB) : 2 planes (16KB).
// [geometry identical to validated R12 gemm_f16x2]
// ===========================================================================
template<bool LO>
__global__ void __launch_bounds__(256)
gemm_f16(const __half* __restrict__ A,
         const __half* __restrict__ Bh, const __half* __restrict__ Bl,
         const float* __restrict__ bias, float* __restrict__ Y,
         __half* __restrict__ Yf) {
    constexpr uint32_t STG = LO ? 24576 : 16384;
    extern __shared__ char sm[];
    const uint32_t sb = smem_u32(sm);
    const int tid  = threadIdx.x;
    const int lane = tid & 31;
    const int wid  = tid >> 5;
    const int wm   = (wid & 1) * 64;
    const int wn   = (wid >> 1) * 32;
    const int bm   = blockIdx.y * 128;
    const int bn   = blockIdx.x * 128;

    float acc[4][4][4];
#pragma unroll
    for (int i = 0; i < 4; i++)
#pragma unroll
        for (int j = 0; j < 4; j++)
#pragma unroll
            for (int q = 0; q < 4; q++) acc[i][j][q] = 0.f;

    auto prefetch = [&](int c, int stg) {
        uint32_t sbase = sb + stg * STG;
#pragma unroll
        for (int q = 0; q < 2; q++) {
            int u   = tid + q * 256;          // 0..511
            int row = u >> 2;                 // 0..127
            int seg = u & 3;                  // 16B segment within 64B row
            uint32_t d = row * 64 + ((seg * 16) ^ (((row >> 1) & 3) << 4));
            size_t oA = (size_t)(bm + row) * D_ + c * 32 + seg * 8;
            size_t oB = (size_t)(bn + row) * D_ + c * 32 + seg * 8;
            cpa16(sbase +        d, A  + oA);
            cpa16(sbase + 8192 + d, Bh + oB);
            if constexpr (LO)
                cpa16(sbase + 16384 + d, Bl + oB);
        }
        CP_COMMIT();
    };

    prefetch(0, 0);

    for (int c = 0; c < 32; c++) {
        if (c < 31) {
            prefetch(c + 1, (c + 1) & 1);
            asm volatile("cp.async.wait_group 1;" ::: "memory");
        } else {
            asm volatile("cp.async.wait_group 0;" ::: "memory");
        }
        __syncthreads();

        const uint32_t st = sb + (c & 1) * STG;
        const int r    = lane & 15;
        const int hseg = lane >> 4;

#pragma unroll
        for (int ks = 0; ks < 2; ks++) {
            const uint32_t kb = ks * 32 + hseg * 16;
            uint32_t ah[4][4], bh[4][2], bl[4][2];
#pragma unroll
            for (int i = 0; i < 4; i++) {
                int row = wm + i * 16 + r;
                uint32_t ad = st + row * 64 + (kb ^ (((row >> 1) & 3) << 4));
                LDSM4(ah[i][0], ah[i][1], ah[i][2], ah[i][3], ad);
            }
#pragma unroll
            for (int jp = 0; jp < 2; jp++) {
                int row = wn + jp * 16 + r;
                uint32_t bd = st + 8192 + row * 64 + (kb ^ (((row >> 1) & 3) << 4));
                LDSM4(bh[2*jp][0], bh[2*jp+1][0], bh[2*jp][1], bh[2*jp+1][1], bd);
                if constexpr (LO)
                    LDSM4(bl[2*jp][0], bl[2*jp+1][0], bl[2*jp][1], bl[2*jp+1][1], bd + 8192);
            }
#pragma unroll
            for (int i = 0; i < 4; i++)
#pragma unroll
                for (int j = 0; j < 4; j++) {
                    MMAH16816(acc[i][j], ah[i], bh[j][0], bh[j][1]);
                    if constexpr (LO)
                        MMAH16816(acc[i][j], ah[i], bl[j][0], bl[j][1]);
                }
        }
        __syncthreads();
    }

    const int mrow = lane >> 2;
    const int ncol = (lane & 3) * 2;
#pragma unroll
    for (int i = 0; i < 4; i++) {
#pragma unroll
        for (int j = 0; j < 4; j++) {
            int m = bm + wm + i * 16 + mrow;
            int n = bn + wn + j * 8 + ncol;
            float2 bv = *(const float2*)(bias + n);
            float y0 = acc[i][j][0] + bv.x;
            float y1 = acc[i][j][1] + bv.y;
            float y2 = acc[i][j][2] + bv.x;
            float y3 = acc[i][j][3] + bv.y;
            if (Yf) {
                *(uint32_t*)(Yf + (size_t)m*D_ + n)     = packh(y0, y1);
                *(uint32_t*)(Yf + (size_t)(m+8)*D_ + n) = packh(y2, y3);
            } else {
                float2 o;
                o.x = y0; o.y = y1;
                *(float2*)(Y + (size_t)m * D_ + n) = o;
                o.x = y2; o.y = y3;
                *(float2*)(Y + (size_t)(m + 8) * D_ + n) = o;
            }
        }
    }
}

// ===========================================================================
// attn_mma: FlashAttention-style secure-softmax attention, fp16 single-MMA.
// [unchanged from validated R12]
// ===========================================================================
#define ASTG  16640
#define AQ    16384
#define ASMEM (AQ + 2*ASTG)   // 49664

__global__ void __launch_bounds__(256)
attn_mma(const __half* __restrict__ qf_, const __half* __restrict__ kf_,
         const __half* __restrict__ vtf_, const float* __restrict__ mask,
         __half* __restrict__ cf_) {
    extern __shared__ char sm[];
    const uint32_t sb = smem_u32(sm);
    const int tid  = threadIdx.x;
    const int lane = tid & 31;
    const int wid  = tid >> 5;
    const int t    = lane & 3;
    const int bh   = blockIdx.y;
    const int b    = bh >> 4, h = bh & 15;
    const int q0   = blockIdx.x * 128;

    const __half* qb = qf_ + ((size_t)b * S_ + q0) * D_ + h * HD_;
    const __half* kb = kf_ + (size_t)b * S_ * D_ + h * HD_;
    const __half* vb = vtf_ + (size_t)bh * HD_ * S_;

    // Load Q tile (128 rows x 64 fp16), swizzled
#pragma unroll
    for (int u = tid; u < 1024; u += 256) {
        int row = u >> 3, seg = u & 7;
        uint32_t d = row * 128 + ((seg ^ (row & 7)) << 4);
        cpa16(sb + d, qb + (size_t)row * D_ + seg * 8);
    }

    auto prefetch = [&](int kt, int stg) {
        uint32_t sbase = sb + AQ + stg * ASTG;
        int kr0 = kt * 64;
#pragma unroll
        for (int q = 0; q < 2; q++) {
            int u = tid + q * 256;
            int row = u >> 3, seg = u & 7;
            uint32_t d = row * 128 + ((seg ^ (row & 7)) << 4);
            cpa16(sbase +        d, kb + (size_t)(kr0 + row) * D_ + seg * 8);
            cpa16(sbase + 8192 + d, vb + (size_t)row * S_ + kr0 + seg * 8);
        }
        if (tid < 16)
            cpa16(sbase + 16384 + tid * 16, mask + (size_t)b * S_ + kr0 + tid * 4);
    };

    prefetch(0, 0);
    CP_COMMIT();     // group: Q + stage0

    float ctx[8][4];
#pragma unroll
    for (int j = 0; j < 8; j++)
#pragma unroll
        for (int q = 0; q < 4; q++) ctx[j][q] = 0.f;
    float dsum0 = 0.f, dsum1 = 0.f;

    const int r    = lane & 15;
    const int hseg = lane >> 4;
    const int rowA = wid * 16 + r;

    for (int kt = 0; kt < 32; kt++) {
        if (kt < 31) {
            prefetch(kt + 1, (kt + 1) & 1);
            CP_COMMIT();
            asm volatile("cp.async.wait_group 1;" ::: "memory");
        } else {
            asm volatile("cp.async.wait_group 0;" ::: "memory");
        }
        __syncthreads();

        const uint32_t st = sb + AQ + (kt & 1) * ASTG;
        const float* Ms = (const float*)(sm + AQ + (kt & 1) * ASTG + 16384);

        // ---- Stage A: S = Q K^T (fp16) ----
        float s[8][4];
#pragma unroll
        for (int j = 0; j < 8; j++)
#pragma unroll
            for (int q = 0; q < 4; q++) s[j][q] = 0.f;

#pragma unroll
        for (int ks = 0; ks < 4; ks++) {
            const int segA = ks * 2 + hseg;
            uint32_t qa = sb + rowA * 128 + ((segA ^ (rowA & 7)) << 4);
            uint32_t qA[4];
            LDSM4(qA[0], qA[1], qA[2], qA[3], qa);
            uint32_t kh[8][2];
#pragma unroll
            for (int jp = 0; jp < 4; jp++) {
                int row = jp * 16 + r;
                uint32_t kd = st + row * 128 + ((segA ^ (row & 7)) << 4);
                LDSM4(kh[2*jp][0], kh[2*jp+1][0], kh[2*jp][1], kh[2*jp+1][1], kd);
            }
#pragma unroll
            for (int j = 0; j < 8; j++)
                MMAH16816(s[j], qA, kh[j][0], kh[j][1]);
        }

        // ---- softmax poly + build fp16 P fragments ----
        uint32_t pa[4][4];
#pragma unroll
        for (int j = 0; j < 8; j++) {
            float2 mv = *(const float2*)(Ms + j * 8 + t * 2);
            float mt0 = (1.0f - mv.x) * -10000.0f;
            float mt1 = (1.0f - mv.y) * -10000.0f;
            float e[4];
#pragma unroll
            for (int q = 0; q < 4; q++) {
                float c = s[j][q] * 0.125f + ((q & 1) ? mt1 : mt0);
                c = fminf(3.0f, fmaxf(-3.0f, c));
                float sg = 0.5f + c * (0.25f - 0.01f * c * c);
                e[q] = fminf(0.99f, fmaxf(0.01f, sg));
            }
            dsum0 += e[0] + e[1];
            dsum1 += e[2] + e[3];
            int kk = j >> 1, half = (j & 1) * 2;
            pa[kk][half + 0] = packh(e[0], e[1]);   // rows (g)
            pa[kk][half + 1] = packh(e[2], e[3]);   // rows (g+8)
        }

        // ---- Stage B: ctx += P V (fp16) ----
#pragma unroll
        for (int kk = 0; kk < 4; kk++) {
            const int segB = kk * 2 + hseg;
            uint32_t vh[8][2];
#pragma unroll
            for (int jp = 0; jp < 4; jp++) {
                int row = jp * 16 + r;
                uint32_t vd = st + 8192 + row * 128 + ((segB ^ (row & 7)) << 4);
                LDSM4(vh[2*jp][0], vh[2*jp+1][0], vh[2*jp][1], vh[2*jp+1][1], vd);
            }
#pragma unroll
            for (int j = 0; j < 8; j++)
                MMAH16816(ctx[j], pa[kk], vh[j][0], vh[j][1]);
        }
        __syncthreads();
    }

    // ---- reduce denominators across lane quads (same row) ----
    dsum0 += __shfl_xor_sync(0xffffffffu, dsum0, 1);
    dsum0 += __shfl_xor_sync(0xffffffffu, dsum0, 2);
    dsum1 += __shfl_xor_sync(0xffffffffu, dsum1, 1);
    dsum1 += __shfl_xor_sync(0xffffffffu, dsum1, 2);
    float inv0 = 1.0f / (dsum0 + 1e-8f);
    float inv1 = 1.0f / (dsum1 + 1e-8f);

    const int g = lane >> 2;
    const int row0 = q0 + wid * 16 + g;
    const int row1 = row0 + 8;
#pragma unroll
    for (int j = 0; j < 8; j++) {
        int col = h * HD_ + j * 8 + t * 2;
        size_t i0 = ((size_t)b * S_ + row0) * D_ + col;
        size_t i1 = ((size_t)b * S_ + row1) * D_ + col;
        *(uint32_t*)(cf_ + i0) = packh(ctx[j][0] * inv0, ctx[j][1] * inv0);
        *(uint32_t*)(cf_ + i1) = packh(ctx[j][2] * inv1, ctx[j][3] * inv1);
    }
}

// ---------------------------------------------------------------------------
// Host launcher. Inputs (metadata order):
//  0 hidden_states [B,S,D] f32    1 attention_mask [B,S] f32
//  2 Wq [D,D]  3 bq [D]  4 Wk  5 bk  6 Wv  7 bv  8 Wo  9 bo
// ---------------------------------------------------------------------------
extern "C" void kernel_launch(void* const* d_in, const int* in_sizes, int n_in,
                              void* d_out, int out_size) {
    const float* hs = (const float*)d_in[0];
    const float* am = (const float*)d_in[1];
    const float* Wq = (const float*)d_in[2];
    const float* bq = (const float*)d_in[3];
    const float* Wk = (const float*)d_in[4];
    const float* bk = (const float*)d_in[5];
    const float* Wv = (const float*)d_in[6];
    const float* bv = (const float*)d_in[7];
    const float* Wo = (const float*)d_in[8];
    const float* bo = (const float*)d_in[9];
    float* out = (float*)d_out;

    __half *xf, *wfh, *wfl, *qf, *kf, *vtf, *cf;
    float* v;
    cudaGetSymbolAddress((void**)&xf,  g_xf);
    cudaGetSymbolAddress((void**)&wfh, g_wfh);
    cudaGetSymbolAddress((void**)&wfl, g_wfl);
    cudaGetSymbolAddress((void**)&qf,  g_qf);
    cudaGetSymbolAddress((void**)&kf,  g_kf);
    cudaGetSymbolAddress((void**)&v,   g_v);
    cudaGetSymbolAddress((void**)&vtf, g_vtf);
    cudaGetSymbolAddress((void**)&cf,  g_cf);

    static bool attr_set = false;
    if (!attr_set) {
        cudaFuncSetAttribute(gemm_f16<true>,
                             cudaFuncAttributeMaxDynamicSharedMemorySize, 49152);
        cudaFuncSetAttribute(gemm_f16<false>,
                             cudaFuncAttributeMaxDynamicSharedMemorySize, 32768);
        cudaFuncSetAttribute(attn_mma,
                             cudaFuncAttributeMaxDynamicSharedMemorySize, ASMEM);
        attr_set = true;
    }

    const int D2 = D_ * D_;
    const int n4_x = M_ * D_ / 4;    // 1048576
    const int n4_w = D2 / 4;         // 262144

    conv_f16<<<n4_x/256, 256>>>((const float4*)hs, (__half2*)xf, n4_x);
    prep_w<<<dim3(n4_w/256, 4), 256>>>((const float4*)Wq, (const float4*)Wk,
                                       (const float4*)Wv, (const float4*)Wo,
                                       (__half2*)wfh, (__half2*)wfl, n4_w);

    dim3 ggrid(D_/128, M_/128);   // (8, 32)
    gemm_f16<false><<<ggrid, 256, 32768>>>(xf, wfh,        nullptr,    bq, nullptr, qf);
    gemm_f16<false><<<ggrid, 256, 32768>>>(xf, wfh + D2,   nullptr,    bk, nullptr, kf);
    gemm_f16<true ><<<ggrid, 256, 49152>>>(xf, wfh + 2*D2, wfl + 2*D2, bv, v, nullptr);

    vtrans<<<dim3(S_/64, B_*H_), 256>>>(v, vtf);

    dim3 agrid(S_/128, B_*H_);    // (16, 32)
    attn_mma<<<agrid, 256, ASMEM>>>(qf, kf, vtf, am, cf);

    gemm_f16<true><<<ggrid, 256, 49152>>>(cf, wfh + 3*D2, wfl + 3*D2, bo, out, nullptr);
}

// round 15
// speedup vs baseline: 5.4551x; 1.0089x over previous
#include <cuda_runtime.h>
#include <cuda_bf16.h>
#include <cuda_fp16.h>
#include <cstdint>
#include <cstddef>

// Problem constants
#define B_   2
#define S_   2048
#define D_   1024
#define H_   16
#define HD_  64
#define M_   (B_*S_)

// Scratch (no allocation allowed -> device globals)
__device__ __half g_xf [M_*D_];     // hidden_states fp16
__device__ __half g_wfh[4*D_*D_];   // weight hi planes (fp16); Wq,Wk adjacent
__device__ __half g_wfl[4*D_*D_];   // weight lo planes (only V/O slots used)
__device__ __half g_qf [M_*D_];
__device__ __half g_kf [M_*D_];
__device__ float  g_v  [M_*D_];
__device__ __half g_vtf[M_*D_];     // V^T per (b,h): [b,h,hd,S]
__device__ __half g_cf [M_*D_];     // ctx fp16

// ===========================================================================
// Helpers (baseline PTX for compute_103: ldmatrix, mma.sync, cp.async)
// ===========================================================================
__device__ __forceinline__ uint32_t smem_u32(const void* p) {
    uint32_t r;
    asm("{ .reg .u64 t; cvta.to.shared.u64 t, %1; cvt.u32.u64 %0, t; }"
        : "=r"(r) : "l"(p));
    return r;
}

__device__ __forceinline__ void cpa16(uint32_t dst, const void* src) {
    asm volatile("cp.async.cg.shared.global [%0], [%1], 16;"
                 :: "r"(dst), "l"(__cvta_generic_to_global(src)) : "memory");
}

#define CP_COMMIT() asm volatile("cp.async.commit_group;" ::: "memory")
#define CP_WAIT(n)  asm volatile("cp.async.wait_group " #n ";" ::: "memory")

#define LDSM4(d0,d1,d2,d3,a) \
    asm volatile("ldmatrix.sync.aligned.m8n8.x4.shared.b16 {%0,%1,%2,%3}, [%4];" \
        : "=r"(d0),"=r"(d1),"=r"(d2),"=r"(d3) : "r"(a))

#define MMAH16816(c,a,b0,b1) \
    asm volatile("mma.sync.aligned.m16n8k16.row.col.f32.f16.f16.f32 " \
        "{%0,%1,%2,%3},{%4,%5,%6,%7},{%8,%9},{%0,%1,%2,%3};" \
        : "+f"((c)[0]),"+f"((c)[1]),"+f"((c)[2]),"+f"((c)[3]) \
        : "r"((a)[0]),"r"((a)[1]),"r"((a)[2]),"r"((a)[3]),"r"(b0),"r"(b1))

// pack two f32 -> f16x2 reg (first arg in low 16 bits)
__device__ __forceinline__ uint32_t packh(float lo, float hi) {
    uint32_t r;
    asm("cvt.rn.f16x2.f32 %0, %1, %2;" : "=r"(r) : "f"(hi), "f"(lo));
    return r;
}

// ===========================================================================
// conv_f16: f32 -> fp16 plane (hidden_states)
// ===========================================================================
__global__ void conv_f16(const float4* __restrict__ x,
                         __half2* __restrict__ y, int n4) {
    int i = blockIdx.x * blockDim.x + threadIdx.x;
    if (i >= n4) return;
    float4 v = x[i];
    y[2*i]   = __floats2half2_rn(v.x, v.y);
    y[2*i+1] = __floats2half2_rn(v.z, v.w);
}

// ===========================================================================
// prep_w: all 4 weights in one launch. blockIdx.y = weight id.
// Wq/Wk (id 0,1): hi plane only.  Wv/Wo (id 2,3): hi + lo planes.
// ===========================================================================
__global__ void prep_w(const float4* __restrict__ Wq, const float4* __restrict__ Wk,
                       const float4* __restrict__ Wv, const float4* __restrict__ Wo,
                       __half2* __restrict__ wfh, __half2* __restrict__ wfl, int n4) {
    int i = blockIdx.x * blockDim.x + threadIdx.x;
    if (i >= n4) return;
    int w = blockIdx.y;
    const float4* src = (w == 0) ? Wq : (w == 1) ? Wk : (w == 2) ? Wv : Wo;
    float4 v = src[i];
    size_t off = (size_t)w * (D_ * (size_t)D_ / 2);   // half2 units per weight
    __half h0 = __float2half_rn(v.x);
    __half h1 = __float2half_rn(v.y);
    __half h2 = __float2half_rn(v.z);
    __half h3 = __float2half_rn(v.w);
    __half2 p; p.x = h0; p.y = h1;
    wfh[off + 2*i] = p;
    p.x = h2; p.y = h3;
    wfh[off + 2*i + 1] = p;
    if (w >= 2) {
        __half2 q;
        q.x = __float2half_rn(v.x - __half2float(h0));
        q.y = __float2half_rn(v.y - __half2float(h1));
        wfl[off + 2*i] = q;
        q.x = __float2half_rn(v.z - __half2float(h2));
        q.y = __float2half_rn(v.w - __half2float(h3));
        wfl[off + 2*i + 1] = q;
    }
}

// ===========================================================================
// vtrans: g_v f32 [b,s,h*64+d] -> vtf fp16 [b,h,d,S] (per-head transpose)
// ===========================================================================
__global__ void vtrans(const float* __restrict__ v, __half* __restrict__ vtf) {
    __shared__ float tile[64][65];
    const int tid = threadIdx.x;
    const int s0  = blockIdx.x * 64;
    const int bh  = blockIdx.y;
    const int b   = bh >> 4, h = bh & 15;
    const float* vb = v + (size_t)b * S_ * D_ + h * HD_;
#pragma unroll
    for (int u = tid; u < 4096; u += 256) {
        int row = u >> 6, col = u & 63;
        tile[col][row] = vb[(size_t)(s0 + row) * D_ + col];
    }
    __syncthreads();
    __half* oh = vtf + (size_t)bh * HD_ * S_ + s0;
#pragma unroll
    for (int u = tid; u < 4096; u += 256) {
        int d = u >> 6, sc = u & 63;
        oh[(size_t)d * S_ + sc] = __float2half_rn(tile[d][sc]);
    }
}

// ===========================================================================
// gemm_qk: fused Q+K projection. Wh = [Wq;Wk] as one [2048,1024] fp16 matrix.
// Single-MMA per k16 (validated numerics). 4-stage cp.async pipeline.
// grid = (2048/128, 4096/128) = (16, 32) = 512 CTAs.
// SMEM: 4 stages x 2 planes x 8KB = 64 KB.
// ===========================================================================
#define QK_STG  16384
#define QK_SMEM (4*QK_STG)   // 65536

__global__ void __launch_bounds__(256)
gemm_qk(const __half* __restrict__ A, const __half* __restrict__ Wh,
        const float* __restrict__ bq, const float* __restrict__ bk,
        __half* __restrict__ qf, __half* __restrict__ kf) {
    extern __shared__ char sm[];
    const uint32_t sb = smem_u32(sm);
    const int tid  = threadIdx.x;
    const int lane = tid & 31;
    const int wid  = tid >> 5;
    const int wm   = (wid & 1) * 64;
    const int wn   = (wid >> 1) * 32;
    const int bm   = blockIdx.y * 128;
    const int bn   = blockIdx.x * 128;   // 0..2047 across [Wq;Wk]

    float acc[4][4][4];
#pragma unroll
    for (int i = 0; i < 4; i++)
#pragma unroll
        for (int j = 0; j < 4; j++)
#pragma unroll
            for (int q = 0; q < 4; q++) acc[i][j][q] = 0.f;

    auto prefetch = [&](int c, int stg) {
        uint32_t sbase = sb + stg * QK_STG;
#pragma unroll
        for (int q = 0; q < 2; q++) {
            int u   = tid + q * 256;
            int row = u >> 2;
            int seg = u & 3;
            uint32_t d = row * 64 + ((seg * 16) ^ (((row >> 1) & 3) << 4));
            cpa16(sbase +        d, A  + (size_t)(bm + row) * D_ + c * 32 + seg * 8);
            cpa16(sbase + 8192 + d, Wh + (size_t)(bn + row) * D_ + c * 32 + seg * 8);
        }
        CP_COMMIT();
    };

    prefetch(0, 0); prefetch(1, 1); prefetch(2, 2);

    for (int c = 0; c < 32; c++) {
        if (c + 3 < 32) { prefetch(c + 3, (c + 3) & 3); CP_WAIT(3); }
        else            { CP_WAIT(0); }
        __syncthreads();

        const uint32_t st = sb + (c & 3) * QK_STG;
        const int r    = lane & 15;
        const int hseg = lane >> 4;

#pragma unroll
        for (int ks = 0; ks < 2; ks++) {
            const uint32_t kb = ks * 32 + hseg * 16;
            uint32_t ah[4][4], bh[4][2];
#pragma unroll
            for (int i = 0; i < 4; i++) {
                int row = wm + i * 16 + r;
                uint32_t ad = st + row * 64 + (kb ^ (((row >> 1) & 3) << 4));
                LDSM4(ah[i][0], ah[i][1], ah[i][2], ah[i][3], ad);
            }
#pragma unroll
            for (int jp = 0; jp < 2; jp++) {
                int row = wn + jp * 16 + r;
                uint32_t bd = st + 8192 + row * 64 + (kb ^ (((row >> 1) & 3) << 4));
                LDSM4(bh[2*jp][0], bh[2*jp+1][0], bh[2*jp][1], bh[2*jp+1][1], bd);
            }
#pragma unroll
            for (int i = 0; i < 4; i++)
#pragma unroll
                for (int j = 0; j < 4; j++)
                    MMAH16816(acc[i][j], ah[i], bh[j][0], bh[j][1]);
        }
        __syncthreads();
    }

    const bool  isK  = bn >= D_;
    const float* bias = isK ? bk : bq;
    __half*      Yf   = isK ? kf : qf;
    const int    nb   = bn - (isK ? D_ : 0);

    const int mrow = lane >> 2;
    const int ncol = (lane & 3) * 2;
#pragma unroll
    for (int i = 0; i < 4; i++) {
#pragma unroll
        for (int j = 0; j < 4; j++) {
            int m = bm + wm + i * 16 + mrow;
            int n = nb + wn + j * 8 + ncol;
            float2 bv = *(const float2*)(bias + n);
            *(uint32_t*)(Yf + (size_t)m*D_ + n)     = packh(acc[i][j][0] + bv.x,
                                                           acc[i][j][1] + bv.y);
            *(uint32_t*)(Yf + (size_t)(m+8)*D_ + n) = packh(acc[i][j][2] + bv.x,
                                                           acc[i][j][3] + bv.y);
        }
    }
}

// ===========================================================================
// gemm_lo:  Y[M,N] = A_f16[M,K] @ (Wh+Wl)[N,K]^T + bias   (split-2, V/O)
// 3-stage cp.async pipeline; SMEM: 3 stages x 3 planes x 8KB = 72 KB.
// [numerics identical to validated R12/R13 LO path]
// ===========================================================================
#define LO_STG  24576
#define LO_SMEM (3*LO_STG)   // 73728

__global__ void __launch_bounds__(256)
gemm_lo(const __half* __restrict__ A,
        const __half* __restrict__ Bh, const __half* __restrict__ Bl,
        const float* __restrict__ bias, float* __restrict__ Y,
        __half* __restrict__ Yf) {
    extern __shared__ char sm[];
    const uint32_t sb = smem_u32(sm);
    const int tid  = threadIdx.x;
    const int lane = tid & 31;
    const int wid  = tid >> 5;
    const int wm   = (wid & 1) * 64;
    const int wn   = (wid >> 1) * 32;
    const int bm   = blockIdx.y * 128;
    const int bn   = blockIdx.x * 128;

    float acc[4][4][4];
#pragma unroll
    for (int i = 0; i < 4; i++)
#pragma unroll
        for (int j = 0; j < 4; j++)
#pragma unroll
            for (int q = 0; q < 4; q++) acc[i][j][q] = 0.f;

    auto prefetch = [&](int c, int stg) {
        uint32_t sbase = sb + stg * LO_STG;
#pragma unroll
        for (int q = 0; q < 2; q++) {
            int u   = tid + q * 256;
            int row = u >> 2;
            int seg = u & 3;
            uint32_t d = row * 64 + ((seg * 16) ^ (((row >> 1) & 3) << 4));
            size_t oA = (size_t)(bm + row) * D_ + c * 32 + seg * 8;
            size_t oB = (size_t)(bn + row) * D_ + c * 32 + seg * 8;
            cpa16(sbase +         d, A  + oA);
            cpa16(sbase +  8192 + d, Bh + oB);
            cpa16(sbase + 16384 + d, Bl + oB);
        }
        CP_COMMIT();
    };

    prefetch(0, 0); prefetch(1, 1);

    for (int c = 0; c < 32; c++) {
        if (c + 2 < 32) { prefetch(c + 2, (c + 2) % 3); CP_WAIT(2); }
        else            { CP_WAIT(0); }
        __syncthreads();

        const uint32_t st = sb + (c % 3) * LO_STG;
        const int r    = lane & 15;
        const int hseg = lane >> 4;

#pragma unroll
        for (int ks = 0; ks < 2; ks++) {
            const uint32_t kb = ks * 32 + hseg * 16;
            uint32_t ah[4][4], bh[4][2], bl[4][2];
#pragma unroll
            for (int i = 0; i < 4; i++) {
                int row = wm + i * 16 + r;
                uint32_t ad = st + row * 64 + (kb ^ (((row >> 1) & 3) << 4));
                LDSM4(ah[i][0], ah[i][1], ah[i][2], ah[i][3], ad);
            }
#pragma unroll
            for (int jp = 0; jp < 2; jp++) {
                int row = wn + jp * 16 + r;
                uint32_t bd = st + 8192 + row * 64 + (kb ^ (((row >> 1) & 3) << 4));
                LDSM4(bh[2*jp][0], bh[2*jp+1][0], bh[2*jp][1], bh[2*jp+1][1], bd);
                LDSM4(bl[2*jp][0], bl[2*jp+1][0], bl[2*jp][1], bl[2*jp+1][1], bd + 8192);
            }
#pragma unroll
            for (int i = 0; i < 4; i++)
#pragma unroll
                for (int j = 0; j < 4; j++) {
                    MMAH16816(acc[i][j], ah[i], bh[j][0], bh[j][1]);
                    MMAH16816(acc[i][j], ah[i], bl[j][0], bl[j][1]);
                }
        }
        __syncthreads();
    }

    const int mrow = lane >> 2;
    const int ncol = (lane & 3) * 2;
#pragma unroll
    for (int i = 0; i < 4; i++) {
#pragma unroll
        for (int j = 0; j < 4; j++) {
            int m = bm + wm + i * 16 + mrow;
            int n = bn + wn + j * 8 + ncol;
            float2 bv = *(const float2*)(bias + n);
            float y0 = acc[i][j][0] + bv.x;
            float y1 = acc[i][j][1] + bv.y;
            float y2 = acc[i][j][2] + bv.x;
            float y3 = acc[i][j][3] + bv.y;
            if (Yf) {
                *(uint32_t*)(Yf + (size_t)m*D_ + n)     = packh(y0, y1);
                *(uint32_t*)(Yf + (size_t)(m+8)*D_ + n) = packh(y2, y3);
            } else {
                float2 o;
                o.x = y0; o.y = y1;
                *(float2*)(Y + (size_t)m * D_ + n) = o;
                o.x = y2; o.y = y3;
                *(float2*)(Y + (size_t)(m + 8) * D_ + n) = o;
            }
        }
    }
}

// ===========================================================================
// attn_mma: FlashAttention-style secure-softmax attention, fp16 single-MMA.
// 3-stage cp.async pipeline (was 2). Numerics unchanged from validated R12.
// SMEM: Q 16KB + 3 stages x (K 8KB + VT 8KB + mask 256B) = 66304 B.
// ===========================================================================
#define ASTG  16640
#define AQ    16384
#define ASMEM (AQ + 3*ASTG)   // 66304

__global__ void __launch_bounds__(256)
attn_mma(const __half* __restrict__ qf_, const __half* __restrict__ kf_,
         const __half* __restrict__ vtf_, const float* __restrict__ mask,
         __half* __restrict__ cf_) {
    extern __shared__ char sm[];
    const uint32_t sb = smem_u32(sm);
    const int tid  = threadIdx.x;
    const int lane = tid & 31;
    const int wid  = tid >> 5;
    const int t    = lane & 3;
    const int bh   = blockIdx.y;
    const int b    = bh >> 4, h = bh & 15;
    const int q0   = blockIdx.x * 128;

    const __half* qb = qf_ + ((size_t)b * S_ + q0) * D_ + h * HD_;
    const __half* kb = kf_ + (size_t)b * S_ * D_ + h * HD_;
    const __half* vb = vtf_ + (size_t)bh * HD_ * S_;

    auto prefetch = [&](int kt, int stg) {
        uint32_t sbase = sb + AQ + stg * ASTG;
        int kr0 = kt * 64;
#pragma unroll
        for (int q = 0; q < 2; q++) {
            int u = tid + q * 256;
            int row = u >> 3, seg = u & 7;
            uint32_t d = row * 128 + ((seg ^ (row & 7)) << 4);
            cpa16(sbase +        d, kb + (size_t)(kr0 + row) * D_ + seg * 8);
            cpa16(sbase + 8192 + d, vb + (size_t)row * S_ + kr0 + seg * 8);
        }
        if (tid < 16)
            cpa16(sbase + 16384 + tid * 16, mask + (size_t)b * S_ + kr0 + tid * 4);
    };

    // Q load shares the first commit group with stage 0
#pragma unroll
    for (int u = tid; u < 1024; u += 256) {
        int row = u >> 3, seg = u & 7;
        uint32_t d = row * 128 + ((seg ^ (row & 7)) << 4);
        cpa16(sb + d, qb + (size_t)row * D_ + seg * 8);
    }
    prefetch(0, 0);
    CP_COMMIT();
    prefetch(1, 1);
    CP_COMMIT();

    float ctx[8][4];
#pragma unroll
    for (int j = 0; j < 8; j++)
#pragma unroll
        for (int q = 0; q < 4; q++) ctx[j][q] = 0.f;
    float dsum0 = 0.f, dsum1 = 0.f;

    const int r    = lane & 15;
    const int hseg = lane >> 4;
    const int rowA = wid * 16 + r;

    for (int kt = 0; kt < 32; kt++) {
        if (kt + 2 < 32) { prefetch(kt + 2, (kt + 2) % 3); CP_COMMIT(); CP_WAIT(2); }
        else             { CP_WAIT(0); }
        __syncthreads();

        const uint32_t st = sb + AQ + (kt % 3) * ASTG;
        const float* Ms = (const float*)(sm + AQ + (kt % 3) * ASTG + 16384);

        // ---- Stage A: S = Q K^T (fp16) ----
        float s[8][4];
#pragma unroll
        for (int j = 0; j < 8; j++)
#pragma unroll
            for (int q = 0; q < 4; q++) s[j][q] = 0.f;

#pragma unroll
        for (int ks = 0; ks < 4; ks++) {
            const int segA = ks * 2 + hseg;
            uint32_t qa = sb + rowA * 128 + ((segA ^ (rowA & 7)) << 4);
            uint32_t qA[4];
            LDSM4(qA[0], qA[1], qA[2], qA[3], qa);
            uint32_t kh[8][2];
#pragma unroll
            for (int jp = 0; jp < 4; jp++) {
                int row = jp * 16 + r;
                uint32_t kd = st + row * 128 + ((segA ^ (row & 7)) << 4);
                LDSM4(kh[2*jp][0], kh[2*jp+1][0], kh[2*jp][1], kh[2*jp+1][1], kd);
            }
#pragma unroll
            for (int j = 0; j < 8; j++)
                MMAH16816(s[j], qA, kh[j][0], kh[j][1]);
        }

        // ---- softmax poly + build fp16 P fragments ----
        uint32_t pa[4][4];
#pragma unroll
        for (int j = 0; j < 8; j++) {
            float2 mv = *(const float2*)(Ms + j * 8 + t * 2);
            float mt0 = (1.0f - mv.x) * -10000.0f;
            float mt1 = (1.0f - mv.y) * -10000.0f;
            float e[4];
#pragma unroll
            for (int q = 0; q < 4; q++) {
                float c = s[j][q] * 0.125f + ((q & 1) ? mt1 : mt0);
                c = fminf(3.0f, fmaxf(-3.0f, c));
                float sg = 0.5f + c * (0.25f - 0.01f * c * c);
                e[q] = fminf(0.99f, fmaxf(0.01f, sg));
            }
            dsum0 += e[0] + e[1];
            dsum1 += e[2] + e[3];
            int kk = j >> 1, half = (j & 1) * 2;
            pa[kk][half + 0] = packh(e[0], e[1]);   // rows (g)
            pa[kk][half + 1] = packh(e[2], e[3]);   // rows (g+8)
        }

        // ---- Stage B: ctx += P V (fp16) ----
#pragma unroll
        for (int kk = 0; kk < 4; kk++) {
            const int segB = kk * 2 + hseg;
            uint32_t vh[8][2];
#pragma unroll
            for (int jp = 0; jp < 4; jp++) {
                int row = jp * 16 + r;
                uint32_t vd = st + 8192 + row * 128 + ((segB ^ (row & 7)) << 4);
                LDSM4(vh[2*jp][0], vh[2*jp+1][0], vh[2*jp][1], vh[2*jp+1][1], vd);
            }
#pragma unroll
            for (int j = 0; j < 8; j++)
                MMAH16816(ctx[j], pa[kk], vh[j][0], vh[j][1]);
        }
        __syncthreads();
    }

    // ---- reduce denominators across lane quads (same row) ----
    dsum0 += __shfl_xor_sync(0xffffffffu, dsum0, 1);
    dsum0 += __shfl_xor_sync(0xffffffffu, dsum0, 2);
    dsum1 += __shfl_xor_sync(0xffffffffu, dsum1, 1);
    dsum1 += __shfl_xor_sync(0xffffffffu, dsum1, 2);
    float inv0 = 1.0f / (dsum0 + 1e-8f);
    float inv1 = 1.0f / (dsum1 + 1e-8f);

    const int g = lane >> 2;
    const int row0 = q0 + wid * 16 + g;
    const int row1 = row0 + 8;
#pragma unroll
    for (int j = 0; j < 8; j++) {
        int col = h * HD_ + j * 8 + t * 2;
        size_t i0 = ((size_t)b * S_ + row0) * D_ + col;
        size_t i1 = ((size_t)b * S_ + row1) * D_ + col;
        *(uint32_t*)(cf_ + i0) = packh(ctx[j][0] * inv0, ctx[j][1] * inv0);
        *(uint32_t*)(cf_ + i1) = packh(ctx[j][2] * inv1, ctx[j][3] * inv1);
    }
}

// ---------------------------------------------------------------------------
// Host launcher. Inputs (metadata order):
//  0 hidden_states [B,S,D] f32    1 attention_mask [B,S] f32
//  2 Wq [D,D]  3 bq [D]  4 Wk  5 bk  6 Wv  7 bv  8 Wo  9 bo
// ---------------------------------------------------------------------------
extern "C" void kernel_launch(void* const* d_in, const int* in_sizes, int n_in,
                              void* d_out, int out_size) {
    const float* hs = (const float*)d_in[0];
    const float* am = (const float*)d_in[1];
    const float* Wq = (const float*)d_in[2];
    const float* bq = (const float*)d_in[3];
    const float* Wk = (const float*)d_in[4];
    const float* bk = (const float*)d_in[5];
    const float* Wv = (const float*)d_in[6];
    const float* bv = (const float*)d_in[7];
    const float* Wo = (const float*)d_in[8];
    const float* bo = (const float*)d_in[9];
    float* out = (float*)d_out;

    __half *xf, *wfh, *wfl, *qf, *kf, *vtf, *cf;
    float* v;
    cudaGetSymbolAddress((void**)&xf,  g_xf);
    cudaGetSymbolAddress((void**)&wfh, g_wfh);
    cudaGetSymbolAddress((void**)&wfl, g_wfl);
    cudaGetSymbolAddress((void**)&qf,  g_qf);
    cudaGetSymbolAddress((void**)&kf,  g_kf);
    cudaGetSymbolAddress((void**)&v,   g_v);
    cudaGetSymbolAddress((void**)&vtf, g_vtf);
    cudaGetSymbolAddress((void**)&cf,  g_cf);

    static bool attr_set = false;
    if (!attr_set) {
        cudaFuncSetAttribute(gemm_qk,
                             cudaFuncAttributeMaxDynamicSharedMemorySize, QK_SMEM);
        cudaFuncSetAttribute(gemm_lo,
                             cudaFuncAttributeMaxDynamicSharedMemorySize, LO_SMEM);
        cudaFuncSetAttribute(attn_mma,
                             cudaFuncAttributeMaxDynamicSharedMemorySize, ASMEM);
        attr_set = true;
    }

    const int D2 = D_ * D_;
    const int n4_x = M_ * D_ / 4;    // 1048576
    const int n4_w = D2 / 4;         // 262144

    conv_f16<<<n4_x/256, 256>>>((const float4*)hs, (__half2*)xf, n4_x);
    prep_w<<<dim3(n4_w/256, 4), 256>>>((const float4*)Wq, (const float4*)Wk,
                                       (const float4*)Wv, (const float4*)Wo,
                                       (__half2*)wfh, (__half2*)wfl, n4_w);

    // Fused Q+K projection: Wh = [Wq;Wk] contiguous in g_wfh
    gemm_qk<<<dim3(2*D_/128, M_/128), 256, QK_SMEM>>>(xf, wfh, bq, bk, qf, kf);

    dim3 ggrid(D_/128, M_/128);   // (8, 32)
    gemm_lo<<<ggrid, 256, LO_SMEM>>>(xf, wfh + 2*D2, wfl + 2*D2, bv, v, nullptr);

    vtrans<<<dim3(S_/64, B_*H_), 256>>>(v, vtf);

    dim3 agrid(S_/128, B_*H_);    // (16, 32)
    attn_mma<<<agrid, 256, ASMEM>>>(qf, kf, vtf, am, cf);

    gemm_lo<<<ggrid, 256, LO_SMEM>>>(cf, wfh + 3*D2, wfl + 3*D2, bo, out, nullptr);
}

// round 16
// speedup vs baseline: 5.5469x; 1.0168x over previous
#include <cuda_runtime.h>
#include <cuda_bf16.h>
#include <cuda_fp16.h>
#include <cstdint>
#include <cstddef>

// Problem constants
#define B_   2
#define S_   2048
#define D_   1024
#define H_   16
#define HD_  64
#define M_   (B_*S_)

// Scratch (no allocation allowed -> device globals)
__device__ __half g_xf [M_*D_];     // hidden_states fp16
__device__ __half g_wfh[4*D_*D_];   // weight hi planes (fp16); Wq,Wk adjacent
__device__ __half g_wfl[4*D_*D_];   // weight lo planes (only V/O slots used)
__device__ __half g_qf [M_*D_];
__device__ __half g_kf [M_*D_];
__device__ float  g_v  [M_*D_];
__device__ __half g_vtf[M_*D_];     // V^T per (b,h): [b,h,hd,S]
__device__ __half g_cf [M_*D_];     // ctx fp16

// ===========================================================================
// Helpers (baseline PTX for compute_103: ldmatrix, mma.sync, cp.async)
// ===========================================================================
__device__ __forceinline__ uint32_t smem_u32(const void* p) {
    uint32_t r;
    asm("{ .reg .u64 t; cvta.to.shared.u64 t, %1; cvt.u32.u64 %0, t; }"
        : "=r"(r) : "l"(p));
    return r;
}

__device__ __forceinline__ void cpa16(uint32_t dst, const void* src) {
    asm volatile("cp.async.cg.shared.global [%0], [%1], 16;"
                 :: "r"(dst), "l"(__cvta_generic_to_global(src)) : "memory");
}

#define CP_COMMIT() asm volatile("cp.async.commit_group;" ::: "memory")
#define CP_WAIT(n)  asm volatile("cp.async.wait_group " #n ";" ::: "memory")

#define LDSM4(d0,d1,d2,d3,a) \
    asm volatile("ldmatrix.sync.aligned.m8n8.x4.shared.b16 {%0,%1,%2,%3}, [%4];" \
        : "=r"(d0),"=r"(d1),"=r"(d2),"=r"(d3) : "r"(a))

#define MMAH16816(c,a,b0,b1) \
    asm volatile("mma.sync.aligned.m16n8k16.row.col.f32.f16.f16.f32 " \
        "{%0,%1,%2,%3},{%4,%5,%6,%7},{%8,%9},{%0,%1,%2,%3};" \
        : "+f"((c)[0]),"+f"((c)[1]),"+f"((c)[2]),"+f"((c)[3]) \
        : "r"((a)[0]),"r"((a)[1]),"r"((a)[2]),"r"((a)[3]),"r"(b0),"r"(b1))

// pack two f32 -> f16x2 reg (first arg in low 16 bits)
__device__ __forceinline__ uint32_t packh(float lo, float hi) {
    uint32_t r;
    asm("cvt.rn.f16x2.f32 %0, %1, %2;" : "=r"(r) : "f"(hi), "f"(lo));
    return r;
}

// ===========================================================================
// conv_f16: f32 -> fp16 plane (hidden_states)
// ===========================================================================
__global__ void conv_f16(const float4* __restrict__ x,
                         __half2* __restrict__ y, int n4) {
    int i = blockIdx.x * blockDim.x + threadIdx.x;
    if (i >= n4) return;
    float4 v = x[i];
    y[2*i]   = __floats2half2_rn(v.x, v.y);
    y[2*i+1] = __floats2half2_rn(v.z, v.w);
}

// ===========================================================================
// prep_w: all 4 weights in one launch. blockIdx.y = weight id.
// Wq/Wk (id 0,1): hi plane only.  Wv/Wo (id 2,3): hi + lo planes.
// ===========================================================================
__global__ void prep_w(const float4* __restrict__ Wq, const float4* __restrict__ Wk,
                       const float4* __restrict__ Wv, const float4* __restrict__ Wo,
                       __half2* __restrict__ wfh, __half2* __restrict__ wfl, int n4) {
    int i = blockIdx.x * blockDim.x + threadIdx.x;
    if (i >= n4) return;
    int w = blockIdx.y;
    const float4* src = (w == 0) ? Wq : (w == 1) ? Wk : (w == 2) ? Wv : Wo;
    float4 v = src[i];
    size_t off = (size_t)w * (D_ * (size_t)D_ / 2);   // half2 units per weight
    __half h0 = __float2half_rn(v.x);
    __half h1 = __float2half_rn(v.y);
    __half h2 = __float2half_rn(v.z);
    __half h3 = __float2half_rn(v.w);
    __half2 p; p.x = h0; p.y = h1;
    wfh[off + 2*i] = p;
    p.x = h2; p.y = h3;
    wfh[off + 2*i + 1] = p;
    if (w >= 2) {
        __half2 q;
        q.x = __float2half_rn(v.x - __half2float(h0));
        q.y = __float2half_rn(v.y - __half2float(h1));
        wfl[off + 2*i] = q;
        q.x = __float2half_rn(v.z - __half2float(h2));
        q.y = __float2half_rn(v.w - __half2float(h3));
        wfl[off + 2*i + 1] = q;
    }
}

// ===========================================================================
// vtrans: g_v f32 [b,s,h*64+d] -> vtf fp16 [b,h,d,S] (per-head transpose)
// ===========================================================================
__global__ void vtrans(const float* __restrict__ v, __half* __restrict__ vtf) {
    __shared__ float tile[64][65];
    const int tid = threadIdx.x;
    const int s0  = blockIdx.x * 64;
    const int bh  = blockIdx.y;
    const int b   = bh >> 4, h = bh & 15;
    const float* vb = v + (size_t)b * S_ * D_ + h * HD_;
#pragma unroll
    for (int u = tid; u < 4096; u += 256) {
        int row = u >> 6, col = u & 63;
        tile[col][row] = vb[(size_t)(s0 + row) * D_ + col];
    }
    __syncthreads();
    __half* oh = vtf + (size_t)bh * HD_ * S_ + s0;
#pragma unroll
    for (int u = tid; u < 4096; u += 256) {
        int d = u >> 6, sc = u & 63;
        oh[(size_t)d * S_ + sc] = __float2half_rn(tile[d][sc]);
    }
}

// ===========================================================================
// gemm_qk: fused Q+K projection, CTA tile 128x64 (occupancy-optimized).
// Wh = [Wq;Wk] as one [2048,1024] fp16 matrix; single-MMA numerics (R13).
// grid = (2048/64, 4096/128) = (32, 32) = 1024 CTAs.
// 8 warps as 4m x 2n, warp tile 32x32, acc[2][4][4] = 32 regs.
// SMEM: 4 stages x (A 8KB + B 4KB) = 48 KB -> 3 CTAs/SM.
// ===========================================================================
#define QK_STG  12288
#define QK_SMEM (4*QK_STG)   // 49152

__global__ void __launch_bounds__(256, 3)
gemm_qk(const __half* __restrict__ A, const __half* __restrict__ Wh,
        const float* __restrict__ bq, const float* __restrict__ bk,
        __half* __restrict__ qf, __half* __restrict__ kf) {
    extern __shared__ char sm[];
    const uint32_t sb = smem_u32(sm);
    const int tid  = threadIdx.x;
    const int lane = tid & 31;
    const int wid  = tid >> 5;
    const int wm   = (wid & 3) * 32;
    const int wn   = (wid >> 2) * 32;
    const int bm   = blockIdx.y * 128;
    const int bn   = blockIdx.x * 64;    // 0..2047 across [Wq;Wk]

    float acc[2][4][4];
#pragma unroll
    for (int i = 0; i < 2; i++)
#pragma unroll
        for (int j = 0; j < 4; j++)
#pragma unroll
            for (int q = 0; q < 4; q++) acc[i][j][q] = 0.f;

    auto prefetch = [&](int c, int stg) {
        uint32_t sbase = sb + stg * QK_STG;
#pragma unroll
        for (int q = 0; q < 2; q++) {            // A: 128 rows
            int u   = tid + q * 256;
            int row = u >> 2, seg = u & 3;
            uint32_t d = row * 64 + ((seg * 16) ^ (((row >> 1) & 3) << 4));
            cpa16(sbase + d, A + (size_t)(bm + row) * D_ + c * 32 + seg * 8);
        }
        {                                         // B: 64 rows
            int row = tid >> 2, seg = tid & 3;
            uint32_t d = row * 64 + ((seg * 16) ^ (((row >> 1) & 3) << 4));
            cpa16(sbase + 8192 + d, Wh + (size_t)(bn + row) * D_ + c * 32 + seg * 8);
        }
        CP_COMMIT();
    };

    prefetch(0, 0); prefetch(1, 1); prefetch(2, 2);

    for (int c = 0; c < 32; c++) {
        if (c + 3 < 32) { prefetch(c + 3, (c + 3) & 3); CP_WAIT(3); }
        else            { CP_WAIT(0); }
        __syncthreads();

        const uint32_t st = sb + (c & 3) * QK_STG;
        const int r    = lane & 15;
        const int hseg = lane >> 4;

#pragma unroll
        for (int ks = 0; ks < 2; ks++) {
            const uint32_t kb = ks * 32 + hseg * 16;
            uint32_t ah[2][4], bh[4][2];
#pragma unroll
            for (int i = 0; i < 2; i++) {
                int row = wm + i * 16 + r;
                uint32_t ad = st + row * 64 + (kb ^ (((row >> 1) & 3) << 4));
                LDSM4(ah[i][0], ah[i][1], ah[i][2], ah[i][3], ad);
            }
#pragma unroll
            for (int jp = 0; jp < 2; jp++) {
                int row = wn + jp * 16 + r;
                uint32_t bd = st + 8192 + row * 64 + (kb ^ (((row >> 1) & 3) << 4));
                LDSM4(bh[2*jp][0], bh[2*jp+1][0], bh[2*jp][1], bh[2*jp+1][1], bd);
            }
#pragma unroll
            for (int i = 0; i < 2; i++)
#pragma unroll
                for (int j = 0; j < 4; j++)
                    MMAH16816(acc[i][j], ah[i], bh[j][0], bh[j][1]);
        }
        __syncthreads();
    }

    const bool   isK  = bn >= D_;
    const float* bias = isK ? bk : bq;
    __half*      Yf   = isK ? kf : qf;
    const int    nb   = bn - (isK ? D_ : 0);

    const int mrow = lane >> 2;
    const int ncol = (lane & 3) * 2;
#pragma unroll
    for (int i = 0; i < 2; i++) {
#pragma unroll
        for (int j = 0; j < 4; j++) {
            int m = bm + wm + i * 16 + mrow;
            int n = nb + wn + j * 8 + ncol;
            float2 bv = *(const float2*)(bias + n);
            *(uint32_t*)(Yf + (size_t)m*D_ + n)     = packh(acc[i][j][0] + bv.x,
                                                           acc[i][j][1] + bv.y);
            *(uint32_t*)(Yf + (size_t)(m+8)*D_ + n) = packh(acc[i][j][2] + bv.x,
                                                           acc[i][j][3] + bv.y);
        }
    }
}

// ===========================================================================
// gemm_lo: split-2 V/O GEMM, CTA tile 128x64 (occupancy-optimized).
// grid = (1024/64, 4096/128) = (16, 32) = 512 CTAs.
// 8 warps as 4m x 2n, warp tile 32x32; 16 MMA per k16 (hi+lo).
// SMEM: 4 stages x (A 8KB + Bh 4KB + Bl 4KB) = 64 KB -> 3 CTAs/SM.
// [numerics identical to validated R12/R13 LO path]
// ===========================================================================
#define LO_STG  16384
#define LO_SMEM (4*LO_STG)   // 65536

__global__ void __launch_bounds__(256, 3)
gemm_lo(const __half* __restrict__ A,
        const __half* __restrict__ Bh, const __half* __restrict__ Bl,
        const float* __restrict__ bias, float* __restrict__ Y,
        __half* __restrict__ Yf) {
    extern __shared__ char sm[];
    const uint32_t sb = smem_u32(sm);
    const int tid  = threadIdx.x;
    const int lane = tid & 31;
    const int wid  = tid >> 5;
    const int wm   = (wid & 3) * 32;
    const int wn   = (wid >> 2) * 32;
    const int bm   = blockIdx.y * 128;
    const int bn   = blockIdx.x * 64;

    float acc[2][4][4];
#pragma unroll
    for (int i = 0; i < 2; i++)
#pragma unroll
        for (int j = 0; j < 4; j++)
#pragma unroll
            for (int q = 0; q < 4; q++) acc[i][j][q] = 0.f;

    auto prefetch = [&](int c, int stg) {
        uint32_t sbase = sb + stg * LO_STG;
#pragma unroll
        for (int q = 0; q < 2; q++) {            // A: 128 rows
            int u   = tid + q * 256;
            int row = u >> 2, seg = u & 3;
            uint32_t d = row * 64 + ((seg * 16) ^ (((row >> 1) & 3) << 4));
            cpa16(sbase + d, A + (size_t)(bm + row) * D_ + c * 32 + seg * 8);
        }
        {                                         // Bh + Bl: 64 rows each
            int row = tid >> 2, seg = tid & 3;
            uint32_t d = row * 64 + ((seg * 16) ^ (((row >> 1) & 3) << 4));
            size_t oB = (size_t)(bn + row) * D_ + c * 32 + seg * 8;
            cpa16(sbase +  8192 + d, Bh + oB);
            cpa16(sbase + 12288 + d, Bl + oB);
        }
        CP_COMMIT();
    };

    prefetch(0, 0); prefetch(1, 1); prefetch(2, 2);

    for (int c = 0; c < 32; c++) {
        if (c + 3 < 32) { prefetch(c + 3, (c + 3) & 3); CP_WAIT(3); }
        else            { CP_WAIT(0); }
        __syncthreads();

        const uint32_t st = sb + (c & 3) * LO_STG;
        const int r    = lane & 15;
        const int hseg = lane >> 4;

#pragma unroll
        for (int ks = 0; ks < 2; ks++) {
            const uint32_t kb = ks * 32 + hseg * 16;
            uint32_t ah[2][4], bh[4][2], bl[4][2];
#pragma unroll
            for (int i = 0; i < 2; i++) {
                int row = wm + i * 16 + r;
                uint32_t ad = st + row * 64 + (kb ^ (((row >> 1) & 3) << 4));
                LDSM4(ah[i][0], ah[i][1], ah[i][2], ah[i][3], ad);
            }
#pragma unroll
            for (int jp = 0; jp < 2; jp++) {
                int row = wn + jp * 16 + r;
                uint32_t bd = st + 8192 + row * 64 + (kb ^ (((row >> 1) & 3) << 4));
                LDSM4(bh[2*jp][0], bh[2*jp+1][0], bh[2*jp][1], bh[2*jp+1][1], bd);
                LDSM4(bl[2*jp][0], bl[2*jp+1][0], bl[2*jp][1], bl[2*jp+1][1], bd + 4096);
            }
#pragma unroll
            for (int i = 0; i < 2; i++)
#pragma unroll
                for (int j = 0; j < 4; j++) {
                    MMAH16816(acc[i][j], ah[i], bh[j][0], bh[j][1]);
                    MMAH16816(acc[i][j], ah[i], bl[j][0], bl[j][1]);
                }
        }
        __syncthreads();
    }

    const int mrow = lane >> 2;
    const int ncol = (lane & 3) * 2;
#pragma unroll
    for (int i = 0; i < 2; i++) {
#pragma unroll
        for (int j = 0; j < 4; j++) {
            int m = bm + wm + i * 16 + mrow;
            int n = bn + wn + j * 8 + ncol;
            float2 bv = *(const float2*)(bias + n);
            float y0 = acc[i][j][0] + bv.x;
            float y1 = acc[i][j][1] + bv.y;
            float y2 = acc[i][j][2] + bv.x;
            float y3 = acc[i][j][3] + bv.y;
            if (Yf) {
                *(uint32_t*)(Yf + (size_t)m*D_ + n)     = packh(y0, y1);
                *(uint32_t*)(Yf + (size_t)(m+8)*D_ + n) = packh(y2, y3);
            } else {
                float2 o;
                o.x = y0; o.y = y1;
                *(float2*)(Y + (size_t)m * D_ + n) = o;
                o.x = y2; o.y = y3;
                *(float2*)(Y + (size_t)(m + 8) * D_ + n) = o;
            }
        }
    }
}

// ===========================================================================
// attn_mma: FlashAttention-style secure-softmax attention, fp16 single-MMA.
// [UNCHANGED from R14 — experiment control]
// ===========================================================================
#define ASTG  16640
#define AQ    16384
#define ASMEM (AQ + 3*ASTG)   // 66304

__global__ void __launch_bounds__(256)
attn_mma(const __half* __restrict__ qf_, const __half* __restrict__ kf_,
         const __half* __restrict__ vtf_, const float* __restrict__ mask,
         __half* __restrict__ cf_) {
    extern __shared__ char sm[];
    const uint32_t sb = smem_u32(sm);
    const int tid  = threadIdx.x;
    const int lane = tid & 31;
    const int wid  = tid >> 5;
    const int t    = lane & 3;
    const int bh   = blockIdx.y;
    const int b    = bh >> 4, h = bh & 15;
    const int q0   = blockIdx.x * 128;

    const __half* qb = qf_ + ((size_t)b * S_ + q0) * D_ + h * HD_;
    const __half* kb = kf_ + (size_t)b * S_ * D_ + h * HD_;
    const __half* vb = vtf_ + (size_t)bh * HD_ * S_;

    auto prefetch = [&](int kt, int stg) {
        uint32_t sbase = sb + AQ + stg * ASTG;
        int kr0 = kt * 64;
#pragma unroll
        for (int q = 0; q < 2; q++) {
            int u = tid + q * 256;
            int row = u >> 3, seg = u & 7;
            uint32_t d = row * 128 + ((seg ^ (row & 7)) << 4);
            cpa16(sbase +        d, kb + (size_t)(kr0 + row) * D_ + seg * 8);
            cpa16(sbase + 8192 + d, vb + (size_t)row * S_ + kr0 + seg * 8);
        }
        if (tid < 16)
            cpa16(sbase + 16384 + tid * 16, mask + (size_t)b * S_ + kr0 + tid * 4);
    };

    // Q load shares the first commit group with stage 0
#pragma unroll
    for (int u = tid; u < 1024; u += 256) {
        int row = u >> 3, seg = u & 7;
        uint32_t d = row * 128 + ((seg ^ (row & 7)) << 4);
        cpa16(sb + d, qb + (size_t)row * D_ + seg * 8);
    }
    prefetch(0, 0);
    CP_COMMIT();
    prefetch(1, 1);
    CP_COMMIT();

    float ctx[8][4];
#pragma unroll
    for (int j = 0; j < 8; j++)
#pragma unroll
        for (int q = 0; q < 4; q++) ctx[j][q] = 0.f;
    float dsum0 = 0.f, dsum1 = 0.f;

    const int r    = lane & 15;
    const int hseg = lane >> 4;
    const int rowA = wid * 16 + r;

    for (int kt = 0; kt < 32; kt++) {
        if (kt + 2 < 32) { prefetch(kt + 2, (kt + 2) % 3); CP_COMMIT(); CP_WAIT(2); }
        else             { CP_WAIT(0); }
        __syncthreads();

        const uint32_t st = sb + AQ + (kt % 3) * ASTG;
        const float* Ms = (const float*)(sm + AQ + (kt % 3) * ASTG + 16384);

        // ---- Stage A: S = Q K^T (fp16) ----
        float s[8][4];
#pragma unroll
        for (int j = 0; j < 8; j++)
#pragma unroll
            for (int q = 0; q < 4; q++) s[j][q] = 0.f;

#pragma unroll
        for (int ks = 0; ks < 4; ks++) {
            const int segA = ks * 2 + hseg;
            uint32_t qa = sb + rowA * 128 + ((segA ^ (rowA & 7)) << 4);
            uint32_t qA[4];
            LDSM4(qA[0], qA[1], qA[2], qA[3], qa);
            uint32_t kh[8][2];
#pragma unroll
            for (int jp = 0; jp < 4; jp++) {
                int row = jp * 16 + r;
                uint32_t kd = st + row * 128 + ((segA ^ (row & 7)) << 4);
                LDSM4(kh[2*jp][0], kh[2*jp+1][0], kh[2*jp][1], kh[2*jp+1][1], kd);
            }
#pragma unroll
            for (int j = 0; j < 8; j++)
                MMAH16816(s[j], qA, kh[j][0], kh[j][1]);
        }

        // ---- softmax poly + build fp16 P fragments ----
        uint32_t pa[4][4];
#pragma unroll
        for (int j = 0; j < 8; j++) {
            float2 mv = *(const float2*)(Ms + j * 8 + t * 2);
            float mt0 = (1.0f - mv.x) * -10000.0f;
            float mt1 = (1.0f - mv.y) * -10000.0f;
            float e[4];
#pragma unroll
            for (int q = 0; q < 4; q++) {
                float c = s[j][q] * 0.125f + ((q & 1) ? mt1 : mt0);
                c = fminf(3.0f, fmaxf(-3.0f, c));
                float sg = 0.5f + c * (0.25f - 0.01f * c * c);
                e[q] = fminf(0.99f, fmaxf(0.01f, sg));
            }
            dsum0 += e[0] + e[1];
            dsum1 += e[2] + e[3];
            int kk = j >> 1, half = (j & 1) * 2;
            pa[kk][half + 0] = packh(e[0], e[1]);   // rows (g)
            pa[kk][half + 1] = packh(e[2], e[3]);   // rows (g+8)
        }

        // ---- Stage B: ctx += P V (fp16) ----
#pragma unroll
        for (int kk = 0; kk < 4; kk++) {
            const int segB = kk * 2 + hseg;
            uint32_t vh[8][2];
#pragma unroll
            for (int jp = 0; jp < 4; jp++) {
                int row = jp * 16 + r;
                uint32_t vd = st + 8192 + row * 128 + ((segB ^ (row & 7)) << 4);
                LDSM4(vh[2*jp][0], vh[2*jp+1][0], vh[2*jp][1], vh[2*jp+1][1], vd);
            }
#pragma unroll
            for (int j = 0; j < 8; j++)
                MMAH16816(ctx[j], pa[kk], vh[j][0], vh[j][1]);
        }
        __syncthreads();
    }

    // ---- reduce denominators across lane quads (same row) ----
    dsum0 += __shfl_xor_sync(0xffffffffu, dsum0, 1);
    dsum0 += __shfl_xor_sync(0xffffffffu, dsum0, 2);
    dsum1 += __shfl_xor_sync(0xffffffffu, dsum1, 1);
    dsum1 += __shfl_xor_sync(0xffffffffu, dsum1, 2);
    float inv0 = 1.0f / (dsum0 + 1e-8f);
    float inv1 = 1.0f / (dsum1 + 1e-8f);

    const int g = lane >> 2;
    const int row0 = q0 + wid * 16 + g;
    const int row1 = row0 + 8;
#pragma unroll
    for (int j = 0; j < 8; j++) {
        int col = h * HD_ + j * 8 + t * 2;
        size_t i0 = ((size_t)b * S_ + row0) * D_ + col;
        size_t i1 = ((size_t)b * S_ + row1) * D_ + col;
        *(uint32_t*)(cf_ + i0) = packh(ctx[j][0] * inv0, ctx[j][1] * inv0);
        *(uint32_t*)(cf_ + i1) = packh(ctx[j][2] * inv1, ctx[j][3] * inv1);
    }
}

// ---------------------------------------------------------------------------
// Host launcher. Inputs (metadata order):
//  0 hidden_states [B,S,D] f32    1 attention_mask [B,S] f32
//  2 Wq [D,D]  3 bq [D]  4 Wk  5 bk  6 Wv  7 bv  8 Wo  9 bo
// ---------------------------------------------------------------------------
extern "C" void kernel_launch(void* const* d_in, const int* in_sizes, int n_in,
                              void* d_out, int out_size) {
    const float* hs = (const float*)d_in[0];
    const float* am = (const float*)d_in[1];
    const float* Wq = (const float*)d_in[2];
    const float* bq = (const float*)d_in[3];
    const float* Wk = (const float*)d_in[4];
    const float* bk = (const float*)d_in[5];
    const float* Wv = (const float*)d_in[6];
    const float* bv = (const float*)d_in[7];
    const float* Wo = (const float*)d_in[8];
    const float* bo = (const float*)d_in[9];
    float* out = (float*)d_out;

    __half *xf, *wfh, *wfl, *qf, *kf, *vtf, *cf;
    float* v;
    cudaGetSymbolAddress((void**)&xf,  g_xf);
    cudaGetSymbolAddress((void**)&wfh, g_wfh);
    cudaGetSymbolAddress((void**)&wfl, g_wfl);
    cudaGetSymbolAddress((void**)&qf,  g_qf);
    cudaGetSymbolAddress((void**)&kf,  g_kf);
    cudaGetSymbolAddress((void**)&v,   g_v);
    cudaGetSymbolAddress((void**)&vtf, g_vtf);
    cudaGetSymbolAddress((void**)&cf,  g_cf);

    static bool attr_set = false;
    if (!attr_set) {
        cudaFuncSetAttribute(gemm_qk,
                             cudaFuncAttributeMaxDynamicSharedMemorySize, QK_SMEM);
        cudaFuncSetAttribute(gemm_lo,
                             cudaFuncAttributeMaxDynamicSharedMemorySize, LO_SMEM);
        cudaFuncSetAttribute(attn_mma,
                             cudaFuncAttributeMaxDynamicSharedMemorySize, ASMEM);
        attr_set = true;
    }

    const int D2 = D_ * D_;
    const int n4_x = M_ * D_ / 4;    // 1048576
    const int n4_w = D2 / 4;         // 262144

    conv_f16<<<n4_x/256, 256>>>((const float4*)hs, (__half2*)xf, n4_x);
    prep_w<<<dim3(n4_w/256, 4), 256>>>((const float4*)Wq, (const float4*)Wk,
                                       (const float4*)Wv, (const float4*)Wo,
                                       (__half2*)wfh, (__half2*)wfl, n4_w);

    // Fused Q+K projection: Wh = [Wq;Wk] contiguous in g_wfh
    gemm_qk<<<dim3(2*D_/64, M_/128), 256, QK_SMEM>>>(xf, wfh, bq, bk, qf, kf);

    dim3 ggrid(D_/64, M_/128);    // (16, 32) = 512
    gemm_lo<<<ggrid, 256, LO_SMEM>>>(xf, wfh + 2*D2, wfl + 2*D2, bv, v, nullptr);

    vtrans<<<dim3(S_/64, B_*H_), 256>>>(v, vtf);

    dim3 agrid(S_/128, B_*H_);    // (16, 32)
    attn_mma<<<agrid, 256, ASMEM>>>(qf, kf, vtf, am, cf);

    gemm_lo<<<ggrid, 256, LO_SMEM>>>(cf, wfh + 3*D2, wfl + 3*D2, bo, out, nullptr);
}

// round 17
// speedup vs baseline: 6.5273x; 1.1768x over previous
#include <cuda_runtime.h>
#include <cuda_bf16.h>
#include <cuda_fp16.h>
#include <cstdint>
#include <cstddef>

// Problem constants
#define B_   2
#define S_   2048
#define D_   1024
#define H_   16
#define HD_  64
#define M_   (B_*S_)

// Scratch (no allocation allowed -> device globals)
__device__ __half g_xf [M_*D_];     // hidden_states fp16
__device__ __half g_wfh[4*D_*D_];   // weight hi planes: [Wq;Wk;Wv;Wo] contiguous
__device__ __half g_qf [M_*D_];
__device__ __half g_kf [M_*D_];
__device__ __half g_vf [M_*D_];
__device__ __half g_vtf[M_*D_];     // V^T per (b,h): [b,h,hd,S]
__device__ __half g_cf [M_*D_];     // ctx fp16

// ===========================================================================
// Helpers (baseline PTX for compute_103: ldmatrix, mma.sync, cp.async)
// ===========================================================================
__device__ __forceinline__ uint32_t smem_u32(const void* p) {
    uint32_t r;
    asm("{ .reg .u64 t; cvta.to.shared.u64 t, %1; cvt.u32.u64 %0, t; }"
        : "=r"(r) : "l"(p));
    return r;
}

__device__ __forceinline__ void cpa16(uint32_t dst, const void* src) {
    asm volatile("cp.async.cg.shared.global [%0], [%1], 16;"
                 :: "r"(dst), "l"(__cvta_generic_to_global(src)) : "memory");
}

#define CP_COMMIT() asm volatile("cp.async.commit_group;" ::: "memory")
#define CP_WAIT(n)  asm volatile("cp.async.wait_group " #n ";" ::: "memory")

#define LDSM4(d0,d1,d2,d3,a) \
    asm volatile("ldmatrix.sync.aligned.m8n8.x4.shared.b16 {%0,%1,%2,%3}, [%4];" \
        : "=r"(d0),"=r"(d1),"=r"(d2),"=r"(d3) : "r"(a))

#define MMAH16816(c,a,b0,b1) \
    asm volatile("mma.sync.aligned.m16n8k16.row.col.f32.f16.f16.f32 " \
        "{%0,%1,%2,%3},{%4,%5,%6,%7},{%8,%9},{%0,%1,%2,%3};" \
        : "+f"((c)[0]),"+f"((c)[1]),"+f"((c)[2]),"+f"((c)[3]) \
        : "r"((a)[0]),"r"((a)[1]),"r"((a)[2]),"r"((a)[3]),"r"(b0),"r"(b1))

// pack two f32 -> f16x2 reg (first arg in low 16 bits)
__device__ __forceinline__ uint32_t packh(float lo, float hi) {
    uint32_t r;
    asm("cvt.rn.f16x2.f32 %0, %1, %2;" : "=r"(r) : "f"(hi), "f"(lo));
    return r;
}

// ===========================================================================
// conv_f16: f32 -> fp16 plane (hidden_states)
// ===========================================================================
__global__ void conv_f16(const float4* __restrict__ x,
                         __half2* __restrict__ y, int n4) {
    int i = blockIdx.x * blockDim.x + threadIdx.x;
    if (i >= n4) return;
    float4 v = x[i];
    y[2*i]   = __floats2half2_rn(v.x, v.y);
    y[2*i+1] = __floats2half2_rn(v.z, v.w);
}

// ===========================================================================
// prep_w: all 4 weights -> fp16 hi planes, one launch. blockIdx.y = weight.
// ===========================================================================
__global__ void prep_w(const float4* __restrict__ Wq, const float4* __restrict__ Wk,
                       const float4* __restrict__ Wv, const float4* __restrict__ Wo,
                       __half2* __restrict__ wfh, int n4) {
    int i = blockIdx.x * blockDim.x + threadIdx.x;
    if (i >= n4) return;
    int w = blockIdx.y;
    const float4* src = (w == 0) ? Wq : (w == 1) ? Wk : (w == 2) ? Wv : Wo;
    float4 v = src[i];
    size_t off = (size_t)w * (D_ * (size_t)D_ / 2);
    wfh[off + 2*i]     = __floats2half2_rn(v.x, v.y);
    wfh[off + 2*i + 1] = __floats2half2_rn(v.z, v.w);
}

// ===========================================================================
// vtrans: vf fp16 [b,s,h*64+d] -> vtf fp16 [b,h,d,S] (per-head transpose)
// ===========================================================================
__global__ void vtrans(const __half* __restrict__ vf, __half* __restrict__ vtf) {
    __shared__ __half tile[64][65];
    const int tid = threadIdx.x;
    const int s0  = blockIdx.x * 64;
    const int bh  = blockIdx.y;
    const int b   = bh >> 4, h = bh & 15;
    const __half* vb = vf + (size_t)b * S_ * D_ + h * HD_;
#pragma unroll
    for (int u = tid; u < 4096; u += 256) {
        int row = u >> 6, col = u & 63;
        tile[col][row] = vb[(size_t)(s0 + row) * D_ + col];
    }
    __syncthreads();
    __half* oh = vtf + (size_t)bh * HD_ * S_ + s0;
#pragma unroll
    for (int u = tid; u < 4096; u += 256) {
        int d = u >> 6, sc = u & 63;
        oh[(size_t)d * S_ + sc] = tile[d][sc];
    }
}

// ===========================================================================
// gemm_qkv: fused Q+K+V projection, CTA tile 128x64, single fp16 MMA.
// Wh = [Wq;Wk;Wv] as one [3072,1024] fp16 matrix (contiguous in g_wfh).
// grid = (3072/64, 4096/128) = (48, 32) = 1536 CTAs.
// 8 warps as 4m x 2n, warp tile 32x32; 4-stage cp.async.
// SMEM: 4 stages x (A 8KB + B 4KB) = 48 KB -> 3 CTAs/SM.
// [structure identical to validated R15 gemm_qk; 3-way epilogue select]
// ===========================================================================
#define QK_STG  12288
#define QK_SMEM (4*QK_STG)   // 49152

__global__ void __launch_bounds__(256, 3)
gemm_qkv(const __half* __restrict__ A, const __half* __restrict__ Wh,
         const float* __restrict__ bq, const float* __restrict__ bk,
         const float* __restrict__ bv,
         __half* __restrict__ qf, __half* __restrict__ kf,
         __half* __restrict__ vf) {
    extern __shared__ char sm[];
    const uint32_t sb = smem_u32(sm);
    const int tid  = threadIdx.x;
    const int lane = tid & 31;
    const int wid  = tid >> 5;
    const int wm   = (wid & 3) * 32;
    const int wn   = (wid >> 2) * 32;
    const int bm   = blockIdx.y * 128;
    const int bn   = blockIdx.x * 64;    // 0..3071 across [Wq;Wk;Wv]

    float acc[2][4][4];
#pragma unroll
    for (int i = 0; i < 2; i++)
#pragma unroll
        for (int j = 0; j < 4; j++)
#pragma unroll
            for (int q = 0; q < 4; q++) acc[i][j][q] = 0.f;

    auto prefetch = [&](int c, int stg) {
        uint32_t sbase = sb + stg * QK_STG;
#pragma unroll
        for (int q = 0; q < 2; q++) {            // A: 128 rows
            int u   = tid + q * 256;
            int row = u >> 2, seg = u & 3;
            uint32_t d = row * 64 + ((seg * 16) ^ (((row >> 1) & 3) << 4));
            cpa16(sbase + d, A + (size_t)(bm + row) * D_ + c * 32 + seg * 8);
        }
        {                                         // B: 64 rows
            int row = tid >> 2, seg = tid & 3;
            uint32_t d = row * 64 + ((seg * 16) ^ (((row >> 1) & 3) << 4));
            cpa16(sbase + 8192 + d, Wh + (size_t)(bn + row) * D_ + c * 32 + seg * 8);
        }
        CP_COMMIT();
    };

    prefetch(0, 0); prefetch(1, 1); prefetch(2, 2);

    for (int c = 0; c < 32; c++) {
        if (c + 3 < 32) { prefetch(c + 3, (c + 3) & 3); CP_WAIT(3); }
        else            { CP_WAIT(0); }
        __syncthreads();

        const uint32_t st = sb + (c & 3) * QK_STG;
        const int r    = lane & 15;
        const int hseg = lane >> 4;

#pragma unroll
        for (int ks = 0; ks < 2; ks++) {
            const uint32_t kb = ks * 32 + hseg * 16;
            uint32_t ah[2][4], bh[4][2];
#pragma unroll
            for (int i = 0; i < 2; i++) {
                int row = wm + i * 16 + r;
                uint32_t ad = st + row * 64 + (kb ^ (((row >> 1) & 3) << 4));
                LDSM4(ah[i][0], ah[i][1], ah[i][2], ah[i][3], ad);
            }
#pragma unroll
            for (int jp = 0; jp < 2; jp++) {
                int row = wn + jp * 16 + r;
                uint32_t bd = st + 8192 + row * 64 + (kb ^ (((row >> 1) & 3) << 4));
                LDSM4(bh[2*jp][0], bh[2*jp+1][0], bh[2*jp][1], bh[2*jp+1][1], bd);
            }
#pragma unroll
            for (int i = 0; i < 2; i++)
#pragma unroll
                for (int j = 0; j < 4; j++)
                    MMAH16816(acc[i][j], ah[i], bh[j][0], bh[j][1]);
        }
        __syncthreads();
    }

    const int    w    = bn >> 10;                 // 0=Q, 1=K, 2=V
    const float* bias = (w == 0) ? bq : (w == 1) ? bk : bv;
    __half*      Yf   = (w == 0) ? qf : (w == 1) ? kf : vf;
    const int    nb   = bn & 1023;

    const int mrow = lane >> 2;
    const int ncol = (lane & 3) * 2;
#pragma unroll
    for (int i = 0; i < 2; i++) {
#pragma unroll
        for (int j = 0; j < 4; j++) {
            int m = bm + wm + i * 16 + mrow;
            int n = nb + wn + j * 8 + ncol;
            float2 bv2 = *(const float2*)(bias + n);
            *(uint32_t*)(Yf + (size_t)m*D_ + n)     = packh(acc[i][j][0] + bv2.x,
                                                           acc[i][j][1] + bv2.y);
            *(uint32_t*)(Yf + (size_t)(m+8)*D_ + n) = packh(acc[i][j][2] + bv2.x,
                                                           acc[i][j][3] + bv2.y);
        }
    }
}

// ===========================================================================
// gemm_o: output projection, CTA tile 128x64, single fp16 MMA, f32 output.
// grid = (1024/64, 4096/128) = (16, 32) = 512 CTAs.
// [same mainloop as gemm_qkv]
// ===========================================================================
__global__ void __launch_bounds__(256, 3)
gemm_o(const __half* __restrict__ A, const __half* __restrict__ Wh,
       const float* __restrict__ bias, float* __restrict__ Y) {
    extern __shared__ char sm[];
    const uint32_t sb = smem_u32(sm);
    const int tid  = threadIdx.x;
    const int lane = tid & 31;
    const int wid  = tid >> 5;
    const int wm   = (wid & 3) * 32;
    const int wn   = (wid >> 2) * 32;
    const int bm   = blockIdx.y * 128;
    const int bn   = blockIdx.x * 64;

    float acc[2][4][4];
#pragma unroll
    for (int i = 0; i < 2; i++)
#pragma unroll
        for (int j = 0; j < 4; j++)
#pragma unroll
            for (int q = 0; q < 4; q++) acc[i][j][q] = 0.f;

    auto prefetch = [&](int c, int stg) {
        uint32_t sbase = sb + stg * QK_STG;
#pragma unroll
        for (int q = 0; q < 2; q++) {
            int u   = tid + q * 256;
            int row = u >> 2, seg = u & 3;
            uint32_t d = row * 64 + ((seg * 16) ^ (((row >> 1) & 3) << 4));
            cpa16(sbase + d, A + (size_t)(bm + row) * D_ + c * 32 + seg * 8);
        }
        {
            int row = tid >> 2, seg = tid & 3;
            uint32_t d = row * 64 + ((seg * 16) ^ (((row >> 1) & 3) << 4));
            cpa16(sbase + 8192 + d, Wh + (size_t)(bn + row) * D_ + c * 32 + seg * 8);
        }
        CP_COMMIT();
    };

    prefetch(0, 0); prefetch(1, 1); prefetch(2, 2);

    for (int c = 0; c < 32; c++) {
        if (c + 3 < 32) { prefetch(c + 3, (c + 3) & 3); CP_WAIT(3); }
        else            { CP_WAIT(0); }
        __syncthreads();

        const uint32_t st = sb + (c & 3) * QK_STG;
        const int r    = lane & 15;
        const int hseg = lane >> 4;

#pragma unroll
        for (int ks = 0; ks < 2; ks++) {
            const uint32_t kb = ks * 32 + hseg * 16;
            uint32_t ah[2][4], bh[4][2];
#pragma unroll
            for (int i = 0; i < 2; i++) {
                int row = wm + i * 16 + r;
                uint32_t ad = st + row * 64 + (kb ^ (((row >> 1) & 3) << 4));
                LDSM4(ah[i][0], ah[i][1], ah[i][2], ah[i][3], ad);
            }
#pragma unroll
            for (int jp = 0; jp < 2; jp++) {
                int row = wn + jp * 16 + r;
                uint32_t bd = st + 8192 + row * 64 + (kb ^ (((row >> 1) & 3) << 4));
                LDSM4(bh[2*jp][0], bh[2*jp+1][0], bh[2*jp][1], bh[2*jp+1][1], bd);
            }
#pragma unroll
            for (int i = 0; i < 2; i++)
#pragma unroll
                for (int j = 0; j < 4; j++)
                    MMAH16816(acc[i][j], ah[i], bh[j][0], bh[j][1]);
        }
        __syncthreads();
    }

    const int mrow = lane >> 2;
    const int ncol = (lane & 3) * 2;
#pragma unroll
    for (int i = 0; i < 2; i++) {
#pragma unroll
        for (int j = 0; j < 4; j++) {
            int m = bm + wm + i * 16 + mrow;
            int n = bn + wn + j * 8 + ncol;
            float2 bv = *(const float2*)(bias + n);
            float2 o;
            o.x = acc[i][j][0] + bv.x;
            o.y = acc[i][j][1] + bv.y;
            *(float2*)(Y + (size_t)m * D_ + n) = o;
            o.x = acc[i][j][2] + bv.x;
            o.y = acc[i][j][3] + bv.y;
            *(float2*)(Y + (size_t)(m + 8) * D_ + n) = o;
        }
    }
}

// ===========================================================================
// attn_mma: FlashAttention-style secure-softmax attention, fp16 single-MMA.
// [UNCHANGED from validated R14/R15]
// ===========================================================================
#define ASTG  16640
#define AQ    16384
#define ASMEM (AQ + 3*ASTG)   // 66304

__global__ void __launch_bounds__(256)
attn_mma(const __half* __restrict__ qf_, const __half* __restrict__ kf_,
         const __half* __restrict__ vtf_, const float* __restrict__ mask,
         __half* __restrict__ cf_) {
    extern __shared__ char sm[];
    const uint32_t sb = smem_u32(sm);
    const int tid  = threadIdx.x;
    const int lane = tid & 31;
    const int wid  = tid >> 5;
    const int t    = lane & 3;
    const int bh   = blockIdx.y;
    const int b    = bh >> 4, h = bh & 15;
    const int q0   = blockIdx.x * 128;

    const __half* qb = qf_ + ((size_t)b * S_ + q0) * D_ + h * HD_;
    const __half* kb = kf_ + (size_t)b * S_ * D_ + h * HD_;
    const __half* vb = vtf_ + (size_t)bh * HD_ * S_;

    auto prefetch = [&](int kt, int stg) {
        uint32_t sbase = sb + AQ + stg * ASTG;
        int kr0 = kt * 64;
#pragma unroll
        for (int q = 0; q < 2; q++) {
            int u = tid + q * 256;
            int row = u >> 3, seg = u & 7;
            uint32_t d = row * 128 + ((seg ^ (row & 7)) << 4);
            cpa16(sbase +        d, kb + (size_t)(kr0 + row) * D_ + seg * 8);
            cpa16(sbase + 8192 + d, vb + (size_t)row * S_ + kr0 + seg * 8);
        }
        if (tid < 16)
            cpa16(sbase + 16384 + tid * 16, mask + (size_t)b * S_ + kr0 + tid * 4);
    };

    // Q load shares the first commit group with stage 0
#pragma unroll
    for (int u = tid; u < 1024; u += 256) {
        int row = u >> 3, seg = u & 7;
        uint32_t d = row * 128 + ((seg ^ (row & 7)) << 4);
        cpa16(sb + d, qb + (size_t)row * D_ + seg * 8);
    }
    prefetch(0, 0);
    CP_COMMIT();
    prefetch(1, 1);
    CP_COMMIT();

    float ctx[8][4];
#pragma unroll
    for (int j = 0; j < 8; j++)
#pragma unroll
        for (int q = 0; q < 4; q++) ctx[j][q] = 0.f;
    float dsum0 = 0.f, dsum1 = 0.f;

    const int r    = lane & 15;
    const int hseg = lane >> 4;
    const int rowA = wid * 16 + r;

    for (int kt = 0; kt < 32; kt++) {
        if (kt + 2 < 32) { prefetch(kt + 2, (kt + 2) % 3); CP_COMMIT(); CP_WAIT(2); }
        else             { CP_WAIT(0); }
        __syncthreads();

        const uint32_t st = sb + AQ + (kt % 3) * ASTG;
        const float* Ms = (const float*)(sm + AQ + (kt % 3) * ASTG + 16384);

        // ---- Stage A: S = Q K^T (fp16) ----
        float s[8][4];
#pragma unroll
        for (int j = 0; j < 8; j++)
#pragma unroll
            for (int q = 0; q < 4; q++) s[j][q] = 0.f;

#pragma unroll
        for (int ks = 0; ks < 4; ks++) {
            const int segA = ks * 2 + hseg;
            uint32_t qa = sb + rowA * 128 + ((segA ^ (rowA & 7)) << 4);
            uint32_t qA[4];
            LDSM4(qA[0], qA[1], qA[2], qA[3], qa);
            uint32_t kh[8][2];
#pragma unroll
            for (int jp = 0; jp < 4; jp++) {
                int row = jp * 16 + r;
                uint32_t kd = st + row * 128 + ((segA ^ (row & 7)) << 4);
                LDSM4(kh[2*jp][0], kh[2*jp+1][0], kh[2*jp][1], kh[2*jp+1][1], kd);
            }
#pragma unroll
            for (int j = 0; j < 8; j++)
                MMAH16816(s[j], qA, kh[j][0], kh[j][1]);
        }

        // ---- softmax poly + build fp16 P fragments ----
        uint32_t pa[4][4];
#pragma unroll
        for (int j = 0; j < 8; j++) {
            float2 mv = *(const float2*)(Ms + j * 8 + t * 2);
            float mt0 = (1.0f - mv.x) * -10000.0f;
            float mt1 = (1.0f - mv.y) * -10000.0f;
            float e[4];
#pragma unroll
            for (int q = 0; q < 4; q++) {
                float c = s[j][q] * 0.125f + ((q & 1) ? mt1 : mt0);
                c = fminf(3.0f, fmaxf(-3.0f, c));
                float sg = 0.5f + c * (0.25f - 0.01f * c * c);
                e[q] = fminf(0.99f, fmaxf(0.01f, sg));
            }
            dsum0 += e[0] + e[1];
            dsum1 += e[2] + e[3];
            int kk = j >> 1, half = (j & 1) * 2;
            pa[kk][half + 0] = packh(e[0], e[1]);   // rows (g)
            pa[kk][half + 1] = packh(e[2], e[3]);   // rows (g+8)
        }

        // ---- Stage B: ctx += P V (fp16) ----
#pragma unroll
        for (int kk = 0; kk < 4; kk++) {
            const int segB = kk * 2 + hseg;
            uint32_t vh[8][2];
#pragma unroll
            for (int jp = 0; jp < 4; jp++) {
                int row = jp * 16 + r;
                uint32_t vd = st + 8192 + row * 128 + ((segB ^ (row & 7)) << 4);
                LDSM4(vh[2*jp][0], vh[2*jp+1][0], vh[2*jp][1], vh[2*jp+1][1], vd);
            }
#pragma unroll
            for (int j = 0; j < 8; j++)
                MMAH16816(ctx[j], pa[kk], vh[j][0], vh[j][1]);
        }
        __syncthreads();
    }

    // ---- reduce denominators across lane quads (same row) ----
    dsum0 += __shfl_xor_sync(0xffffffffu, dsum0, 1);
    dsum0 += __shfl_xor_sync(0xffffffffu, dsum0, 2);
    dsum1 += __shfl_xor_sync(0xffffffffu, dsum1, 1);
    dsum1 += __shfl_xor_sync(0xffffffffu, dsum1, 2);
    float inv0 = 1.0f / (dsum0 + 1e-8f);
    float inv1 = 1.0f / (dsum1 + 1e-8f);

    const int g = lane >> 2;
    const int row0 = q0 + wid * 16 + g;
    const int row1 = row0 + 8;
#pragma unroll
    for (int j = 0; j < 8; j++) {
        int col = h * HD_ + j * 8 + t * 2;
        size_t i0 = ((size_t)b * S_ + row0) * D_ + col;
        size_t i1 = ((size_t)b * S_ + row1) * D_ + col;
        *(uint32_t*)(cf_ + i0) = packh(ctx[j][0] * inv0, ctx[j][1] * inv0);
        *(uint32_t*)(cf_ + i1) = packh(ctx[j][2] * inv1, ctx[j][3] * inv1);
    }
}

// ---------------------------------------------------------------------------
// Host launcher. Inputs (metadata order):
//  0 hidden_states [B,S,D] f32    1 attention_mask [B,S] f32
//  2 Wq [D,D]  3 bq [D]  4 Wk  5 bk  6 Wv  7 bv  8 Wo  9 bo
// ---------------------------------------------------------------------------
extern "C" void kernel_launch(void* const* d_in, const int* in_sizes, int n_in,
                              void* d_out, int out_size) {
    const float* hs = (const float*)d_in[0];
    const float* am = (const float*)d_in[1];
    const float* Wq = (const float*)d_in[2];
    const float* bq = (const float*)d_in[3];
    const float* Wk = (const float*)d_in[4];
    const float* bk = (const float*)d_in[5];
    const float* Wv = (const float*)d_in[6];
    const float* bv = (const float*)d_in[7];
    const float* Wo = (const float*)d_in[8];
    const float* bo = (const float*)d_in[9];
    float* out = (float*)d_out;

    __half *xf, *wfh, *qf, *kf, *vf, *vtf, *cf;
    cudaGetSymbolAddress((void**)&xf,  g_xf);
    cudaGetSymbolAddress((void**)&wfh, g_wfh);
    cudaGetSymbolAddress((void**)&qf,  g_qf);
    cudaGetSymbolAddress((void**)&kf,  g_kf);
    cudaGetSymbolAddress((void**)&vf,  g_vf);
    cudaGetSymbolAddress((void**)&vtf, g_vtf);
    cudaGetSymbolAddress((void**)&cf,  g_cf);

    static bool attr_set = false;
    if (!attr_set) {
        cudaFuncSetAttribute(gemm_qkv,
                             cudaFuncAttributeMaxDynamicSharedMemorySize, QK_SMEM);
        cudaFuncSetAttribute(gemm_o,
                             cudaFuncAttributeMaxDynamicSharedMemorySize, QK_SMEM);
        cudaFuncSetAttribute(attn_mma,
                             cudaFuncAttributeMaxDynamicSharedMemorySize, ASMEM);
        attr_set = true;
    }

    const int D2 = D_ * D_;
    const int n4_x = M_ * D_ / 4;    // 1048576
    const int n4_w = D2 / 4;         // 262144

    conv_f16<<<n4_x/256, 256>>>((const float4*)hs, (__half2*)xf, n4_x);
    prep_w<<<dim3(n4_w/256, 4), 256>>>((const float4*)Wq, (const float4*)Wk,
                                       (const float4*)Wv, (const float4*)Wo,
                                       (__half2*)wfh, n4_w);

    // Fused Q+K+V projection: Wh = [Wq;Wk;Wv] contiguous in g_wfh
    gemm_qkv<<<dim3(3*D_/64, M_/128), 256, QK_SMEM>>>(xf, wfh, bq, bk, bv,
                                                      qf, kf, vf);

    vtrans<<<dim3(S_/64, B_*H_), 256>>>(vf, vtf);

    dim3 agrid(S_/128, B_*H_);    // (16, 32)
    attn_mma<<<agrid, 256, ASMEM>>>(qf, kf, vtf, am, cf);

    gemm_o<<<dim3(D_/64, M_/128), 256, QK_SMEM>>>(cf, wfh + 3*D2, bo, out);
}